// round 1
// baseline (speedup 1.0000x reference)
#include <cuda_runtime.h>
#include <cuda_bf16.h>
#include <math.h>

// Problem constants
#define BB 128   // batch
#define LL 128   // enc length
#define HE 1024  // enc hidden
#define HD 1024  // dec hidden
#define EE 512   // embed
#define AP 512   // attn proj
#define TT 64    // timesteps
#define G4 (4*HD)

// ---------------- device scratch (no allocation allowed) ----------------
__device__ float g_enc_proj[BB * LL * AP];   // 33.5 MB
__device__ float g_q[BB * AP];
__device__ float g_e[BB * LL];
__device__ float g_alpha[BB * LL];
__device__ float g_at[BB * HE];
__device__ float g_gates[BB * G4];
__device__ float g_h1[BB * HD];
__device__ float g_c1[BB * HD];
__device__ float g_h2[BB * HD];
__device__ float g_c2[BB * HD];
__device__ float g_hprev[BB * HD];

__device__ __forceinline__ float sigm(float x) { return 1.0f / (1.0f + expf(-x)); }

// ---------------- init ----------------
__global__ void init_state(const float* __restrict__ h1_0, const float* __restrict__ c1_0,
                           const float* __restrict__ h2_0, const float* __restrict__ c2_0) {
    int i = blockIdx.x * blockDim.x + threadIdx.x;
    if (i < BB * HD) {
        g_h1[i] = h1_0[i];
        g_c1[i] = c1_0[i];
        g_h2[i] = h2_0[i];
        g_c2[i] = c2_0[i];
        g_hprev[i] = 1.0f / (float)HE;
    }
}

// ---------------- tiled SGEMM: C[M,N] (= or +=) bias + A[M,K] @ B[K,N], optional tanh ----------------
// BM=64, BN=64, BK=16, 256 threads, 4x4 per thread. All dims divisible by tiles here.
#define BM 64
#define BN 64
#define BK 16

__global__ void sgemm(const float* __restrict__ A, int lda,
                      const float* __restrict__ Bm, int ldb,
                      float* __restrict__ C, int ldc,
                      int M, int N, int K,
                      const float* __restrict__ bias,
                      int accumulate, int act_tanh) {
    __shared__ float As[BK][BM + 1];
    __shared__ float Bs[BK][BN];

    const int bm = blockIdx.y * BM;
    const int bn = blockIdx.x * BN;
    const int tid = threadIdx.x;
    const int tx = tid & 15;        // 0..15 -> cols
    const int ty = tid >> 4;        // 0..15 -> rows

    float acc[4][4] = {};

    for (int k0 = 0; k0 < K; k0 += BK) {
        #pragma unroll
        for (int i = 0; i < 4; i++) {
            int e = tid + i * 256;          // 0..1023
            int m = e >> 4;                 // /BK
            int kk = e & 15;                // %BK
            As[kk][m] = A[(size_t)(bm + m) * lda + (k0 + kk)];
        }
        #pragma unroll
        for (int i = 0; i < 4; i++) {
            int e = tid + i * 256;
            int kk = e >> 6;                // /BN
            int n = e & 63;                 // %BN
            Bs[kk][n] = Bm[(size_t)(k0 + kk) * ldb + (bn + n)];
        }
        __syncthreads();

        #pragma unroll
        for (int kk = 0; kk < BK; kk++) {
            float ra[4], rb[4];
            #pragma unroll
            for (int i = 0; i < 4; i++) ra[i] = As[kk][ty * 4 + i];
            #pragma unroll
            for (int j = 0; j < 4; j++) rb[j] = Bs[kk][tx * 4 + j];
            #pragma unroll
            for (int i = 0; i < 4; i++)
                #pragma unroll
                for (int j = 0; j < 4; j++)
                    acc[i][j] = fmaf(ra[i], rb[j], acc[i][j]);
        }
        __syncthreads();
    }

    #pragma unroll
    for (int i = 0; i < 4; i++) {
        int m = bm + ty * 4 + i;
        #pragma unroll
        for (int j = 0; j < 4; j++) {
            int n = bn + tx * 4 + j;
            float v = acc[i][j];
            if (bias) v += bias[n];
            if (accumulate) v += C[(size_t)m * ldc + n];
            if (act_tanh) v = tanhf(v);
            C[(size_t)m * ldc + n] = v;
        }
    }
}

// ---------------- attention scores: e[b,l] = sum_ap tanh(enc_proj+q)*corr_w + corr_b (masked) ----------------
__global__ void attn_scores(const float* __restrict__ corr_w,
                            const float* __restrict__ corr_b,
                            const int* __restrict__ mask) {
    int warp = blockIdx.x * 8 + (threadIdx.x >> 5);
    int lane = threadIdx.x & 31;
    if (warp >= BB * LL) return;
    int b = warp / LL;
    int l = warp % LL;

    const float* ep = g_enc_proj + (size_t)warp * AP;
    const float* qb = g_q + (size_t)b * AP;
    float sum = 0.0f;
    #pragma unroll 4
    for (int ap = lane; ap < AP; ap += 32)
        sum += tanhf(ep[ap] + qb[ap]) * corr_w[ap];
    #pragma unroll
    for (int off = 16; off; off >>= 1)
        sum += __shfl_down_sync(0xffffffffu, sum, off);
    if (lane == 0) {
        float v = sum + corr_b[0];
        if (mask[warp] != 0) v = -INFINITY;
        g_e[warp] = v;
    }
}

// ---------------- softmax over L per row b ----------------
__global__ void softmax_rows() {
    int b = blockIdx.x;
    int l = threadIdx.x;
    __shared__ float s[LL];
    float v = g_e[b * LL + l];
    s[l] = v;
    __syncthreads();
    for (int off = 64; off; off >>= 1) {
        if (l < off) s[l] = fmaxf(s[l], s[l + off]);
        __syncthreads();
    }
    float m = s[0];
    __syncthreads();
    float ex = expf(v - m);
    s[l] = ex;
    __syncthreads();
    for (int off = 64; off; off >>= 1) {
        if (l < off) s[l] += s[l + off];
        __syncthreads();
    }
    g_alpha[b * LL + l] = ex / s[0];
}

// ---------------- attention context: a_t[b,h] = sum_l alpha[b,l]*enc[b,l,h] ----------------
__global__ void attn_context(const float* __restrict__ enc) {
    int b = blockIdx.y;
    int h = blockIdx.x * 256 + threadIdx.x;
    __shared__ float al[LL];
    if (threadIdx.x < LL) al[threadIdx.x] = g_alpha[b * LL + threadIdx.x];
    __syncthreads();
    const float* eb = enc + (size_t)b * LL * HE + h;
    float acc = 0.0f;
    #pragma unroll 8
    for (int l = 0; l < LL; l++)
        acc = fmaf(al[l], eb[(size_t)l * HE], acc);
    g_at[b * HE + h] = acc;
}

// ---------------- LSTM cell elementwise (gates order i,f,g,o) ----------------
__global__ void lstm_cell_k(const float* __restrict__ gates,
                            float* __restrict__ h, float* __restrict__ c,
                            float* __restrict__ hprev_copy) {
    int idx = blockIdx.x * 256 + threadIdx.x;
    if (idx >= BB * HD) return;
    int b = idx / HD, j = idx % HD;
    const float* gb = gates + (size_t)b * G4;
    float ig = gb[j];
    float fg = gb[HD + j];
    float gg = gb[2 * HD + j];
    float og = gb[3 * HD + j];
    float cn = sigm(fg) * c[idx] + sigm(ig) * tanhf(gg);
    float hn = sigm(og) * tanhf(cn);
    c[idx] = cn;
    h[idx] = hn;
    if (hprev_copy) hprev_copy[idx] = hn;
}

// ---------------- launch ----------------
extern "C" void kernel_launch(void* const* d_in, const int* in_sizes, int n_in,
                              void* d_out, int out_size) {
    const float* enc      = (const float*)d_in[0];
    const int*   mask     = (const int*)  d_in[1];
    const float* h1_0     = (const float*)d_in[2];
    const float* c1_0     = (const float*)d_in[3];
    const float* h2_0     = (const float*)d_in[4];
    const float* c2_0     = (const float*)d_in[5];
    const float* captions = (const float*)d_in[6];
    const float* att_W    = (const float*)d_in[7];
    const float* att_b    = (const float*)d_in[8];
    const float* dhp_W    = (const float*)d_in[9];
    const float* dhp_b    = (const float*)d_in[10];
    const float* corr_w   = (const float*)d_in[11];
    const float* corr_b   = (const float*)d_in[12];
    const float* lt_W     = (const float*)d_in[13];
    const float* lt_b     = (const float*)d_in[14];
    const float* W_ih1    = (const float*)d_in[15];
    const float* W_hh1    = (const float*)d_in[16];
    const float* b_ih1    = (const float*)d_in[17];
    const float* b_hh1    = (const float*)d_in[18];
    const float* W_ih2    = (const float*)d_in[19];
    const float* W_hh2    = (const float*)d_in[20];
    const float* b_ih2    = (const float*)d_in[21];
    const float* b_hh2    = (const float*)d_in[22];
    float* out = (float*)d_out;

    float *p_encproj, *p_q, *p_gates, *p_h1, *p_c1, *p_h2, *p_c2, *p_hprev, *p_at;
    cudaGetSymbolAddress((void**)&p_encproj, g_enc_proj);
    cudaGetSymbolAddress((void**)&p_q,       g_q);
    cudaGetSymbolAddress((void**)&p_gates,   g_gates);
    cudaGetSymbolAddress((void**)&p_h1,      g_h1);
    cudaGetSymbolAddress((void**)&p_c1,      g_c1);
    cudaGetSymbolAddress((void**)&p_h2,      g_h2);
    cudaGetSymbolAddress((void**)&p_c2,      g_c2);
    cudaGetSymbolAddress((void**)&p_hprev,   g_hprev);
    cudaGetSymbolAddress((void**)&p_at,      g_at);

    // init states
    init_state<<<(BB * HD + 255) / 256, 256>>>(h1_0, c1_0, h2_0, c2_0);

    // enc_proj = enc_hiddens @ att_W + att_b   [(B*L) x AP]
    sgemm<<<dim3(AP / BN, (BB * LL) / BM), 256>>>(enc, HE, att_W, AP, p_encproj, AP,
                                                  BB * LL, AP, HE, att_b, 0, 0);

    for (int t = 0; t < TT; t++) {
        // q = h_prev @ dhp_W + dhp_b  [B x AP]
        sgemm<<<dim3(AP / BN, BB / BM), 256>>>(p_hprev, HD, dhp_W, AP, p_q, AP,
                                               BB, AP, HD, dhp_b, 0, 0);
        // scores + softmax + context
        attn_scores<<<(BB * LL) / 8, 256>>>(corr_w, corr_b, mask);
        softmax_rows<<<BB, LL>>>();
        attn_context<<<dim3(HE / 256, BB), 256>>>(enc);

        // gates1 = [x_t, a_t] @ W_ih1 + b_ih1 + h1 @ W_hh1 + b_hh1
        sgemm<<<dim3(G4 / BN, BB / BM), 256>>>(captions + (size_t)t * BB * EE, EE,
                                               W_ih1, G4, p_gates, G4,
                                               BB, G4, EE, b_ih1, 0, 0);
        sgemm<<<dim3(G4 / BN, BB / BM), 256>>>(p_at, HE,
                                               W_ih1 + (size_t)EE * G4, G4, p_gates, G4,
                                               BB, G4, HE, b_hh1, 1, 0);
        sgemm<<<dim3(G4 / BN, BB / BM), 256>>>(p_h1, HD,
                                               W_hh1, G4, p_gates, G4,
                                               BB, G4, HD, (const float*)nullptr, 1, 0);
        lstm_cell_k<<<(BB * HD) / 256, 256>>>(p_gates, p_h1, p_c1, (float*)nullptr);

        // out_t = tanh(h1n @ lt_W + lt_b)
        sgemm<<<dim3(HD / BN, BB / BM), 256>>>(p_h1, HD, lt_W, HD,
                                               out + (size_t)t * BB * HD, HD,
                                               BB, HD, HD, lt_b, 0, 1);

        // gates2 = h1n @ W_ih2 + b_ih2 + h2 @ W_hh2 + b_hh2
        sgemm<<<dim3(G4 / BN, BB / BM), 256>>>(p_h1, HD, W_ih2, G4, p_gates, G4,
                                               BB, G4, HD, b_ih2, 0, 0);
        sgemm<<<dim3(G4 / BN, BB / BM), 256>>>(p_h2, HD, W_hh2, G4, p_gates, G4,
                                               BB, G4, HD, b_hh2, 1, 0);
        lstm_cell_k<<<(BB * HD) / 256, 256>>>(p_gates, p_h2, p_c2, p_hprev);
    }

    (void)in_sizes; (void)n_in; (void)out_size;
}

// round 2
// speedup vs baseline: 2.1666x; 2.1666x over previous
#include <cuda_runtime.h>
#include <cuda_bf16.h>
#include <math.h>
#include <stdint.h>

// Problem constants
#define BB 128   // batch
#define LL 128   // enc length
#define HE 1024  // enc hidden
#define HD 1024  // dec hidden
#define EE 512   // embed
#define AP 512   // attn proj
#define TT 64    // timesteps
#define G4 (4*HD)

// ---------------- device scratch ----------------
__device__ float g_enc_proj[BB * LL * AP];   // 33.5 MB
__device__ float g_q[BB * AP];
__device__ float g_e[BB * LL];
__device__ float g_alpha[BB * LL];
__device__ float g_at[BB * HE];
__device__ float g_gates[BB * G4];
__device__ float g_h1[BB * HD];
__device__ float g_c1[BB * HD];
__device__ float g_h2[BB * HD];
__device__ float g_c2[BB * HD];
__device__ float g_hprev[BB * HD];

// bf16 hi/lo weight pool: attW + dhpW + ltW + Wih1 + Whh1 + Wih2 + Whh2
// 524288 + 524288 + 1048576 + 6291456 + 4194304*3 = 20971520 elements
#define WPOOL 20971520
__device__ __nv_bfloat16 g_whi[WPOOL];
__device__ __nv_bfloat16 g_wlo[WPOOL];

__device__ __forceinline__ float sigm(float x) { return 1.0f / (1.0f + expf(-x)); }

// ---------------- init ----------------
__global__ void init_state(const float* __restrict__ h1_0, const float* __restrict__ c1_0,
                           const float* __restrict__ h2_0, const float* __restrict__ c2_0) {
    int i = blockIdx.x * blockDim.x + threadIdx.x;
    if (i < BB * HD) {
        g_h1[i] = h1_0[i];
        g_c1[i] = c1_0[i];
        g_h2[i] = h2_0[i];
        g_c2[i] = c2_0[i];
        g_hprev[i] = 1.0f / (float)HE;
    }
}

// ---------------- fp32 -> (bf16 hi, bf16 lo) split ----------------
__global__ void f32_split(const float* __restrict__ src,
                          __nv_bfloat16* __restrict__ hi,
                          __nv_bfloat16* __restrict__ lo, int n) {
    int i = blockIdx.x * 256 + threadIdx.x;
    if (i < n) {
        float x = src[i];
        __nv_bfloat16 h = __float2bfloat16_rn(x);
        hi[i] = h;
        lo[i] = __float2bfloat16_rn(x - __bfloat162float(h));
    }
}

// ---------------- split-bf16 tensor-core GEMM ----------------
// D[M,N] = sum_seg A_seg[M,Kseg] @ B_seg[Kseg,N]  (+bias1+bias2, opt tanh)
// A fp32 (split to hi/lo on the fly), B pre-split bf16 hi/lo.
// 3 passes per smem tile: Ahi*Bhi + Alo*Bhi + Ahi*Blo (fp32 accum).
// CTA tile 64x64, BK=32, 4 warps, warp tile 32x32 (2x4 m16n8k16 mmas).

struct Seg {
    const float* A; int lda;
    const __nv_bfloat16* Bhi; const __nv_bfloat16* Blo; int ldb;
    int K;
};
struct GemmArgs {
    Seg seg[3];
    int nseg;
    float* D; int ldd;
    const float* bias1; const float* bias2;
    int act_tanh;
};

#define PADA 40   // A smem row stride (halves): 80B -> conflict-free ldmatrix
#define PADB 72   // B smem row stride (halves): 144B -> conflict-free ldmatrix

__device__ __forceinline__ uint32_t smem_u32(const void* p) {
    return (uint32_t)__cvta_generic_to_shared(p);
}
__device__ __forceinline__ void ldsm_x4(uint32_t addr, uint32_t& r0, uint32_t& r1,
                                        uint32_t& r2, uint32_t& r3) {
    asm volatile("ldmatrix.sync.aligned.m8n8.x4.shared.b16 {%0,%1,%2,%3}, [%4];"
                 : "=r"(r0), "=r"(r1), "=r"(r2), "=r"(r3) : "r"(addr));
}
__device__ __forceinline__ void ldsm_x4_t(uint32_t addr, uint32_t& r0, uint32_t& r1,
                                          uint32_t& r2, uint32_t& r3) {
    asm volatile("ldmatrix.sync.aligned.m8n8.x4.trans.shared.b16 {%0,%1,%2,%3}, [%4];"
                 : "=r"(r0), "=r"(r1), "=r"(r2), "=r"(r3) : "r"(addr));
}
__device__ __forceinline__ void mma16816(float* c, const uint32_t* a, const uint32_t* b) {
    asm volatile(
        "mma.sync.aligned.m16n8k16.row.col.f32.bf16.bf16.f32 "
        "{%0,%1,%2,%3}, {%4,%5,%6,%7}, {%8,%9}, {%0,%1,%2,%3};"
        : "+f"(c[0]), "+f"(c[1]), "+f"(c[2]), "+f"(c[3])
        : "r"(a[0]), "r"(a[1]), "r"(a[2]), "r"(a[3]), "r"(b[0]), "r"(b[1]));
}

__global__ void __launch_bounds__(128)
gemm_bf16x3(GemmArgs args, int M, int N) {
    __shared__ __align__(16) __nv_bfloat16 As[2][64 * PADA];
    __shared__ __align__(16) __nv_bfloat16 Bs[2][32 * PADB];

    const int tid = threadIdx.x;
    const int lane = tid & 31;
    const int wid = tid >> 5;
    const int wm = wid & 1;          // warp row (0,1)
    const int wn = wid >> 1;         // warp col (0,1)
    const int bm = blockIdx.y * 64;
    const int bn = blockIdx.x * 64;

    float acc[2][4][4];
    #pragma unroll
    for (int i = 0; i < 2; i++)
        #pragma unroll
        for (int j = 0; j < 4; j++)
            #pragma unroll
            for (int k = 0; k < 4; k++) acc[i][j][k] = 0.0f;

    // ldmatrix addresses (fixed per thread)
    // A frag (16x16, non-trans): row = mbase + (lane&15), col = k16 + (lane>>4)*8
    const int a_r = lane & 15;
    const int a_c = (lane >> 4) << 3;
    // B frag (16x16 at [k][n], trans): row(k)= (lane&7)+((lane>>3)&1)*8, col(n)= (lane>>4)*8
    const int b_r = (lane & 7) + ((lane >> 3) & 1) * 8;
    const int b_c = (lane >> 4) << 3;

    for (int s = 0; s < args.nseg; s++) {
        const Seg sg = args.seg[s];
        for (int k0 = 0; k0 < sg.K; k0 += 32) {
            // ---- stage A (fp32 -> hi/lo bf16), 64x32 tile ----
            #pragma unroll
            for (int i = 0; i < 4; i++) {
                int idx = tid + i * 128;       // 0..511
                int row = idx >> 3;            // 64 rows
                int c4 = idx & 7;              // 8 float4 per row
                float4 v = *reinterpret_cast<const float4*>(
                    sg.A + (size_t)(bm + row) * sg.lda + k0 + c4 * 4);
                __nv_bfloat16 h0 = __float2bfloat16_rn(v.x);
                __nv_bfloat16 h1 = __float2bfloat16_rn(v.y);
                __nv_bfloat16 h2 = __float2bfloat16_rn(v.z);
                __nv_bfloat16 h3 = __float2bfloat16_rn(v.w);
                __nv_bfloat16 l0 = __float2bfloat16_rn(v.x - __bfloat162float(h0));
                __nv_bfloat16 l1 = __float2bfloat16_rn(v.y - __bfloat162float(h1));
                __nv_bfloat16 l2 = __float2bfloat16_rn(v.z - __bfloat162float(h2));
                __nv_bfloat16 l3 = __float2bfloat16_rn(v.w - __bfloat162float(h3));
                __nv_bfloat162* ph = reinterpret_cast<__nv_bfloat162*>(&As[0][row * PADA + c4 * 4]);
                ph[0] = __halves2bfloat162(h0, h1);
                ph[1] = __halves2bfloat162(h2, h3);
                __nv_bfloat162* pl = reinterpret_cast<__nv_bfloat162*>(&As[1][row * PADA + c4 * 4]);
                pl[0] = __halves2bfloat162(l0, l1);
                pl[1] = __halves2bfloat162(l2, l3);
            }
            // ---- stage B hi/lo, 32x64 tiles ----
            #pragma unroll
            for (int i = 0; i < 2; i++) {
                int idx = tid + i * 128;       // 0..255
                int row = idx >> 3;            // 32 rows (k)
                int c8 = idx & 7;              // 8 uint4 per row (64 bf16)
                size_t goff = (size_t)(k0 + row) * sg.ldb + bn + c8 * 8;
                *reinterpret_cast<uint4*>(&Bs[0][row * PADB + c8 * 8]) =
                    *reinterpret_cast<const uint4*>(sg.Bhi + goff);
                *reinterpret_cast<uint4*>(&Bs[1][row * PADB + c8 * 8]) =
                    *reinterpret_cast<const uint4*>(sg.Blo + goff);
            }
            __syncthreads();

            // ---- compute: 3 passes x 2 k16 x (2x4 mma) ----
            #pragma unroll
            for (int pass = 0; pass < 3; pass++) {
                const __nv_bfloat16* Asel = As[pass == 1 ? 1 : 0];
                const __nv_bfloat16* Bsel = Bs[pass == 2 ? 1 : 0];
                #pragma unroll
                for (int kk = 0; kk < 32; kk += 16) {
                    uint32_t afr[2][4];
                    #pragma unroll
                    for (int mt = 0; mt < 2; mt++) {
                        uint32_t addr = smem_u32(&Asel[(wm * 32 + mt * 16 + a_r) * PADA + kk + a_c]);
                        ldsm_x4(addr, afr[mt][0], afr[mt][1], afr[mt][2], afr[mt][3]);
                    }
                    uint32_t bfr[4][2];
                    #pragma unroll
                    for (int g = 0; g < 2; g++) {
                        uint32_t r0, r1, r2, r3;
                        uint32_t addr = smem_u32(&Bsel[(kk + b_r) * PADB + wn * 32 + g * 16 + b_c]);
                        ldsm_x4_t(addr, r0, r1, r2, r3);
                        bfr[g * 2 + 0][0] = r0; bfr[g * 2 + 0][1] = r1;
                        bfr[g * 2 + 1][0] = r2; bfr[g * 2 + 1][1] = r3;
                    }
                    #pragma unroll
                    for (int mt = 0; mt < 2; mt++)
                        #pragma unroll
                        for (int nt = 0; nt < 4; nt++)
                            mma16816(acc[mt][nt], afr[mt], bfr[nt]);
                }
            }
            __syncthreads();
        }
    }

    // ---- epilogue ----
    #pragma unroll
    for (int mt = 0; mt < 2; mt++) {
        int r0 = bm + wm * 32 + mt * 16 + (lane >> 2);
        #pragma unroll
        for (int nt = 0; nt < 4; nt++) {
            int c0 = bn + wn * 32 + nt * 8 + (lane & 3) * 2;
            float bia0 = 0.0f, bia1 = 0.0f;
            if (args.bias1) { bia0 += args.bias1[c0]; bia1 += args.bias1[c0 + 1]; }
            if (args.bias2) { bia0 += args.bias2[c0]; bia1 += args.bias2[c0 + 1]; }
            float v00 = acc[mt][nt][0] + bia0;
            float v01 = acc[mt][nt][1] + bia1;
            float v10 = acc[mt][nt][2] + bia0;
            float v11 = acc[mt][nt][3] + bia1;
            if (args.act_tanh) {
                v00 = tanhf(v00); v01 = tanhf(v01);
                v10 = tanhf(v10); v11 = tanhf(v11);
            }
            args.D[(size_t)r0 * args.ldd + c0] = v00;
            args.D[(size_t)r0 * args.ldd + c0 + 1] = v01;
            args.D[(size_t)(r0 + 8) * args.ldd + c0] = v10;
            args.D[(size_t)(r0 + 8) * args.ldd + c0 + 1] = v11;
        }
    }
}

// ---------------- attention scores ----------------
__global__ void attn_scores(const float* __restrict__ corr_w,
                            const float* __restrict__ corr_b,
                            const int* __restrict__ mask) {
    int warp = blockIdx.x * 8 + (threadIdx.x >> 5);
    int lane = threadIdx.x & 31;
    if (warp >= BB * LL) return;
    int b = warp / LL;

    const float* ep = g_enc_proj + (size_t)warp * AP;
    const float* qb = g_q + (size_t)b * AP;
    float sum = 0.0f;
    #pragma unroll 4
    for (int ap = lane; ap < AP; ap += 32)
        sum += tanhf(ep[ap] + qb[ap]) * corr_w[ap];
    #pragma unroll
    for (int off = 16; off; off >>= 1)
        sum += __shfl_down_sync(0xffffffffu, sum, off);
    if (lane == 0) {
        float v = sum + corr_b[0];
        if (mask[warp] != 0) v = -INFINITY;
        g_e[warp] = v;
    }
}

// ---------------- softmax over L per row b ----------------
__global__ void softmax_rows() {
    int b = blockIdx.x;
    int l = threadIdx.x;
    __shared__ float s[LL];
    float v = g_e[b * LL + l];
    s[l] = v;
    __syncthreads();
    for (int off = 64; off; off >>= 1) {
        if (l < off) s[l] = fmaxf(s[l], s[l + off]);
        __syncthreads();
    }
    float m = s[0];
    __syncthreads();
    float ex = expf(v - m);
    s[l] = ex;
    __syncthreads();
    for (int off = 64; off; off >>= 1) {
        if (l < off) s[l] += s[l + off];
        __syncthreads();
    }
    g_alpha[b * LL + l] = ex / s[0];
}

// ---------------- attention context ----------------
__global__ void attn_context(const float* __restrict__ enc) {
    int b = blockIdx.y;
    int h = blockIdx.x * 256 + threadIdx.x;
    __shared__ float al[LL];
    if (threadIdx.x < LL) al[threadIdx.x] = g_alpha[b * LL + threadIdx.x];
    __syncthreads();
    const float* eb = enc + (size_t)b * LL * HE + h;
    float acc = 0.0f;
    #pragma unroll 8
    for (int l = 0; l < LL; l++)
        acc = fmaf(al[l], eb[(size_t)l * HE], acc);
    g_at[b * HE + h] = acc;
}

// ---------------- LSTM cell elementwise ----------------
__global__ void lstm_cell_k(const float* __restrict__ gates,
                            float* __restrict__ h, float* __restrict__ c,
                            float* __restrict__ hprev_copy) {
    int idx = blockIdx.x * 256 + threadIdx.x;
    if (idx >= BB * HD) return;
    int b = idx / HD, j = idx % HD;
    const float* gb = gates + (size_t)b * G4;
    float ig = gb[j];
    float fg = gb[HD + j];
    float gg = gb[2 * HD + j];
    float og = gb[3 * HD + j];
    float cn = sigm(fg) * c[idx] + sigm(ig) * tanhf(gg);
    float hn = sigm(og) * tanhf(cn);
    c[idx] = cn;
    h[idx] = hn;
    if (hprev_copy) hprev_copy[idx] = hn;
}

// ---------------- launch ----------------
extern "C" void kernel_launch(void* const* d_in, const int* in_sizes, int n_in,
                              void* d_out, int out_size) {
    const float* enc      = (const float*)d_in[0];
    const int*   mask     = (const int*)  d_in[1];
    const float* h1_0     = (const float*)d_in[2];
    const float* c1_0     = (const float*)d_in[3];
    const float* h2_0     = (const float*)d_in[4];
    const float* c2_0     = (const float*)d_in[5];
    const float* captions = (const float*)d_in[6];
    const float* att_W    = (const float*)d_in[7];
    const float* att_b    = (const float*)d_in[8];
    const float* dhp_W    = (const float*)d_in[9];
    const float* dhp_b    = (const float*)d_in[10];
    const float* corr_w   = (const float*)d_in[11];
    const float* corr_b   = (const float*)d_in[12];
    const float* lt_W     = (const float*)d_in[13];
    const float* lt_b     = (const float*)d_in[14];
    const float* W_ih1    = (const float*)d_in[15];
    const float* W_hh1    = (const float*)d_in[16];
    const float* b_ih1    = (const float*)d_in[17];
    const float* b_hh1    = (const float*)d_in[18];
    const float* W_ih2    = (const float*)d_in[19];
    const float* W_hh2    = (const float*)d_in[20];
    const float* b_ih2    = (const float*)d_in[21];
    const float* b_hh2    = (const float*)d_in[22];
    float* out = (float*)d_out;

    float *p_encproj, *p_q, *p_gates, *p_h1, *p_c1, *p_h2, *p_c2, *p_hprev, *p_at;
    __nv_bfloat16 *p_whi, *p_wlo;
    cudaGetSymbolAddress((void**)&p_encproj, g_enc_proj);
    cudaGetSymbolAddress((void**)&p_q,       g_q);
    cudaGetSymbolAddress((void**)&p_gates,   g_gates);
    cudaGetSymbolAddress((void**)&p_h1,      g_h1);
    cudaGetSymbolAddress((void**)&p_c1,      g_c1);
    cudaGetSymbolAddress((void**)&p_h2,      g_h2);
    cudaGetSymbolAddress((void**)&p_c2,      g_c2);
    cudaGetSymbolAddress((void**)&p_hprev,   g_hprev);
    cudaGetSymbolAddress((void**)&p_at,      g_at);
    cudaGetSymbolAddress((void**)&p_whi,     g_whi);
    cudaGetSymbolAddress((void**)&p_wlo,     g_wlo);

    // weight pool offsets
    const size_t o_attW = 0;
    const size_t o_dhpW = o_attW + (size_t)HE * AP;
    const size_t o_ltW  = o_dhpW + (size_t)HD * AP;
    const size_t o_ih1  = o_ltW  + (size_t)HD * HD;
    const size_t o_hh1  = o_ih1  + (size_t)(EE + HE) * G4;
    const size_t o_ih2  = o_hh1  + (size_t)HD * G4;
    const size_t o_hh2  = o_ih2  + (size_t)HD * G4;

    // split weights to bf16 hi/lo
    {
        struct { const float* s; size_t o; size_t n; } cv[7] = {
            {att_W, o_attW, (size_t)HE * AP}, {dhp_W, o_dhpW, (size_t)HD * AP},
            {lt_W,  o_ltW,  (size_t)HD * HD}, {W_ih1, o_ih1,  (size_t)(EE + HE) * G4},
            {W_hh1, o_hh1,  (size_t)HD * G4}, {W_ih2, o_ih2,  (size_t)HD * G4},
            {W_hh2, o_hh2,  (size_t)HD * G4}};
        for (int i = 0; i < 7; i++)
            f32_split<<<(int)((cv[i].n + 255) / 256), 256>>>(cv[i].s, p_whi + cv[i].o,
                                                             p_wlo + cv[i].o, (int)cv[i].n);
    }

    init_state<<<(BB * HD + 255) / 256, 256>>>(h1_0, c1_0, h2_0, c2_0);

    // enc_proj = enc @ att_W + att_b  [(B*L) x AP]
    {
        GemmArgs a = {};
        a.seg[0] = {enc, HE, p_whi + o_attW, p_wlo + o_attW, AP, HE};
        a.nseg = 1; a.D = p_encproj; a.ldd = AP; a.bias1 = att_b; a.bias2 = nullptr; a.act_tanh = 0;
        gemm_bf16x3<<<dim3(AP / 64, (BB * LL) / 64), 128>>>(a, BB * LL, AP);
    }

    for (int t = 0; t < TT; t++) {
        // q = h_prev @ dhp_W + dhp_b
        {
            GemmArgs a = {};
            a.seg[0] = {p_hprev, HD, p_whi + o_dhpW, p_wlo + o_dhpW, AP, HD};
            a.nseg = 1; a.D = p_q; a.ldd = AP; a.bias1 = dhp_b; a.bias2 = nullptr; a.act_tanh = 0;
            gemm_bf16x3<<<dim3(AP / 64, BB / 64), 128>>>(a, BB, AP);
        }
        attn_scores<<<(BB * LL) / 8, 256>>>(corr_w, corr_b, mask);
        softmax_rows<<<BB, LL>>>();
        attn_context<<<dim3(HE / 256, BB), 256>>>(enc);

        // gates1 = x_t@Wih1[:E] + a_t@Wih1[E:] + h1@Whh1 + b_ih1 + b_hh1
        {
            GemmArgs a = {};
            a.seg[0] = {captions + (size_t)t * BB * EE, EE,
                        p_whi + o_ih1, p_wlo + o_ih1, G4, EE};
            a.seg[1] = {p_at, HE,
                        p_whi + o_ih1 + (size_t)EE * G4, p_wlo + o_ih1 + (size_t)EE * G4, G4, HE};
            a.seg[2] = {p_h1, HD, p_whi + o_hh1, p_wlo + o_hh1, G4, HD};
            a.nseg = 3; a.D = p_gates; a.ldd = G4; a.bias1 = b_ih1; a.bias2 = b_hh1; a.act_tanh = 0;
            gemm_bf16x3<<<dim3(G4 / 64, BB / 64), 128>>>(a, BB, G4);
        }
        lstm_cell_k<<<(BB * HD) / 256, 256>>>(p_gates, p_h1, p_c1, (float*)nullptr);

        // out_t = tanh(h1n @ lt_W + lt_b)
        {
            GemmArgs a = {};
            a.seg[0] = {p_h1, HD, p_whi + o_ltW, p_wlo + o_ltW, HD, HD};
            a.nseg = 1; a.D = out + (size_t)t * BB * HD; a.ldd = HD;
            a.bias1 = lt_b; a.bias2 = nullptr; a.act_tanh = 1;
            gemm_bf16x3<<<dim3(HD / 64, BB / 64), 128>>>(a, BB, HD);
        }

        // gates2 = h1n@Wih2 + h2@Whh2 + b_ih2 + b_hh2
        {
            GemmArgs a = {};
            a.seg[0] = {p_h1, HD, p_whi + o_ih2, p_wlo + o_ih2, G4, HD};
            a.seg[1] = {p_h2, HD, p_whi + o_hh2, p_wlo + o_hh2, G4, HD};
            a.nseg = 2; a.D = p_gates; a.ldd = G4; a.bias1 = b_ih2; a.bias2 = b_hh2; a.act_tanh = 0;
            gemm_bf16x3<<<dim3(G4 / 64, BB / 64), 128>>>(a, BB, G4);
        }
        lstm_cell_k<<<(BB * HD) / 256, 256>>>(p_gates, p_h2, p_c2, p_hprev);
    }

    (void)in_sizes; (void)n_in; (void)out_size;
}

// round 3
// speedup vs baseline: 2.7616x; 1.2746x over previous
#include <cuda_runtime.h>
#include <cuda_bf16.h>
#include <math.h>
#include <stdint.h>

// Problem constants
#define BB 128   // batch
#define LL 128   // enc length
#define HE 1024  // enc hidden
#define HD 1024  // dec hidden
#define EE 512   // embed
#define AP 512   // attn proj
#define TT 64    // timesteps
#define G4 (4*HD)

// ---------------- device scratch ----------------
__device__ float g_enc_proj[BB * LL * AP];   // 33.5 MB fp32
__device__ float g_q[BB * AP];
__device__ float g_gates[BB * G4];
__device__ float g_c1[BB * HD];
__device__ float g_c2[BB * HD];

// bf16 hi/lo activation buffers
__device__ __nv_bfloat16 g_h1hi[BB * HD], g_h1lo[BB * HD];
__device__ __nv_bfloat16 g_h2hi[BB * HD], g_h2lo[BB * HD];
__device__ __nv_bfloat16 g_hp0hi[BB * HD], g_hp0lo[BB * HD];   // initial h_prev
__device__ __nv_bfloat16 g_athi[BB * HE], g_atlo[BB * HE];
__device__ __nv_bfloat16 g_caphi[TT * BB * EE], g_caplo[TT * BB * EE];
__device__ __nv_bfloat16 g_enchi[BB * LL * HE], g_enclo[BB * LL * HE];

// bf16 hi/lo weight pool
#define WPOOL 20971520
__device__ __nv_bfloat16 g_whi[WPOOL];
__device__ __nv_bfloat16 g_wlo[WPOOL];

__device__ __forceinline__ float sigm(float x) { return 1.0f / (1.0f + expf(-x)); }

// ---------------- init ----------------
__global__ void init_state(const float* __restrict__ h1_0, const float* __restrict__ c1_0,
                           const float* __restrict__ h2_0, const float* __restrict__ c2_0) {
    int i = blockIdx.x * blockDim.x + threadIdx.x;
    if (i < BB * HD) {
        float h1 = h1_0[i], h2 = h2_0[i];
        __nv_bfloat16 a = __float2bfloat16_rn(h1);
        g_h1hi[i] = a; g_h1lo[i] = __float2bfloat16_rn(h1 - __bfloat162float(a));
        __nv_bfloat16 b = __float2bfloat16_rn(h2);
        g_h2hi[i] = b; g_h2lo[i] = __float2bfloat16_rn(h2 - __bfloat162float(b));
        g_c1[i] = c1_0[i];
        g_c2[i] = c2_0[i];
        g_hp0hi[i] = __float2bfloat16_rn(1.0f / (float)HE);  // 2^-10 exact
        g_hp0lo[i] = __float2bfloat16_rn(0.0f);
    }
}

// ---------------- fp32 -> (bf16 hi, bf16 lo) split ----------------
__global__ void f32_split(const float* __restrict__ src,
                          __nv_bfloat16* __restrict__ hi,
                          __nv_bfloat16* __restrict__ lo, int n) {
    int i = blockIdx.x * 256 + threadIdx.x;
    if (i < n) {
        float x = src[i];
        __nv_bfloat16 h = __float2bfloat16_rn(x);
        hi[i] = h;
        lo[i] = __float2bfloat16_rn(x - __bfloat162float(h));
    }
}

// ---------------- split-bf16 tensor-core GEMM (pre-split A, double-buffered) ----------------
// D[M,N] = sum_seg A_seg[M,K] @ B_seg[K,N] (+bias1+bias2, opt tanh)
// A,B both bf16 hi/lo; 3 passes: Ah*Bh + Al*Bh + Ah*Bl, fp32 accum.
// CTA 64x64, BK=32, 4 warps (warp tile 32x32), cp.async 2-stage pipeline.

struct Seg2 {
    const __nv_bfloat16* Ahi; const __nv_bfloat16* Alo; int lda;
    const __nv_bfloat16* Bhi; const __nv_bfloat16* Blo; int ldb;
    int K;
};
struct GemmArgs2 {
    Seg2 seg[3];
    int nseg;
    float* D; int ldd;
    const float* bias1; const float* bias2;
    int act_tanh;
};

#define PADA 40   // A smem row stride (halves) = 80B, 16B-aligned, conflict-free ldsm
#define PADB 72   // B smem row stride (halves) = 144B

__device__ __forceinline__ uint32_t smem_u32(const void* p) {
    return (uint32_t)__cvta_generic_to_shared(p);
}
__device__ __forceinline__ void cp16(void* dst, const void* src) {
    asm volatile("cp.async.ca.shared.global [%0], [%1], 16;"
                 :: "r"(smem_u32(dst)), "l"(src));
}
__device__ __forceinline__ void ldsm_x4(uint32_t addr, uint32_t* r) {
    asm volatile("ldmatrix.sync.aligned.m8n8.x4.shared.b16 {%0,%1,%2,%3}, [%4];"
                 : "=r"(r[0]), "=r"(r[1]), "=r"(r[2]), "=r"(r[3]) : "r"(addr));
}
__device__ __forceinline__ void ldsm_x4_t(uint32_t addr, uint32_t& r0, uint32_t& r1,
                                          uint32_t& r2, uint32_t& r3) {
    asm volatile("ldmatrix.sync.aligned.m8n8.x4.trans.shared.b16 {%0,%1,%2,%3}, [%4];"
                 : "=r"(r0), "=r"(r1), "=r"(r2), "=r"(r3) : "r"(addr));
}
__device__ __forceinline__ void mma16816(float* c, const uint32_t* a, const uint32_t* b) {
    asm volatile(
        "mma.sync.aligned.m16n8k16.row.col.f32.bf16.bf16.f32 "
        "{%0,%1,%2,%3}, {%4,%5,%6,%7}, {%8,%9}, {%0,%1,%2,%3};"
        : "+f"(c[0]), "+f"(c[1]), "+f"(c[2]), "+f"(c[3])
        : "r"(a[0]), "r"(a[1]), "r"(a[2]), "r"(a[3]), "r"(b[0]), "r"(b[1]));
}

__device__ __forceinline__ void stage_tile(const GemmArgs2& a, int g, int bm, int bn, int tid,
                                           __nv_bfloat16* AsH, __nv_bfloat16* AsL,
                                           __nv_bfloat16* BsH, __nv_bfloat16* BsL) {
    int s = 0, rem = g;
    #pragma unroll
    for (int i = 0; i < 2; i++)
        if (s < a.nseg - 1 && rem >= (a.seg[s].K >> 5)) { rem -= a.seg[s].K >> 5; s++; }
    const Seg2 sg = a.seg[s];
    const int k0 = rem << 5;
    // A tile 64x32 (hi+lo)
    #pragma unroll
    for (int i = 0; i < 2; i++) {
        int ch = tid + i * 128;            // 0..255
        int row = ch >> 2, c = (ch & 3) * 8;
        size_t off = (size_t)(bm + row) * sg.lda + k0 + c;
        cp16(AsH + row * PADA + c, sg.Ahi + off);
        cp16(AsL + row * PADA + c, sg.Alo + off);
    }
    // B tile 32x64 (hi+lo)
    #pragma unroll
    for (int i = 0; i < 2; i++) {
        int ch = tid + i * 128;
        int row = ch >> 3, c = (ch & 7) * 8;
        size_t off = (size_t)(k0 + row) * sg.ldb + bn + c;
        cp16(BsH + row * PADB + c, sg.Bhi + off);
        cp16(BsL + row * PADB + c, sg.Blo + off);
    }
}

__global__ void __launch_bounds__(128)
gemm_bf16s(GemmArgs2 args) {
    __shared__ __align__(16) __nv_bfloat16 AsH[2][64 * PADA];
    __shared__ __align__(16) __nv_bfloat16 AsL[2][64 * PADA];
    __shared__ __align__(16) __nv_bfloat16 BsH[2][32 * PADB];
    __shared__ __align__(16) __nv_bfloat16 BsL[2][32 * PADB];

    const int tid = threadIdx.x;
    const int lane = tid & 31;
    const int wid = tid >> 5;
    const int wm = wid & 1;
    const int wn = wid >> 1;
    const int bm = blockIdx.y * 64;
    const int bn = blockIdx.x * 64;

    int ntile = 0;
    #pragma unroll
    for (int s = 0; s < 3; s++) if (s < args.nseg) ntile += args.seg[s].K >> 5;

    float acc[2][4][4];
    #pragma unroll
    for (int i = 0; i < 2; i++)
        #pragma unroll
        for (int j = 0; j < 4; j++)
            #pragma unroll
            for (int k = 0; k < 4; k++) acc[i][j][k] = 0.0f;

    const int a_r = lane & 15;
    const int a_c = (lane >> 4) << 3;
    const int b_r = (lane & 7) + ((lane >> 3) & 1) * 8;
    const int b_c = (lane >> 4) << 3;

    stage_tile(args, 0, bm, bn, tid, AsH[0], AsL[0], BsH[0], BsL[0]);
    asm volatile("cp.async.commit_group;");

    for (int g = 0; g < ntile; g++) {
        const int buf = g & 1;
        if (g + 1 < ntile) {
            stage_tile(args, g + 1, bm, bn, tid, AsH[buf ^ 1], AsL[buf ^ 1],
                       BsH[buf ^ 1], BsL[buf ^ 1]);
            asm volatile("cp.async.commit_group;");
            asm volatile("cp.async.wait_group 1;");
        } else {
            asm volatile("cp.async.wait_group 0;");
        }
        __syncthreads();

        #pragma unroll
        for (int kk = 0; kk < 32; kk += 16) {
            uint32_t ah[2][4], al[2][4];
            #pragma unroll
            for (int mt = 0; mt < 2; mt++) {
                int rowoff = (wm * 32 + mt * 16 + a_r) * PADA + kk + a_c;
                ldsm_x4(smem_u32(&AsH[buf][rowoff]), ah[mt]);
                ldsm_x4(smem_u32(&AsL[buf][rowoff]), al[mt]);
            }
            uint32_t bh[4][2], bl[4][2];
            #pragma unroll
            for (int gi = 0; gi < 2; gi++) {
                int boff = (kk + b_r) * PADB + wn * 32 + gi * 16 + b_c;
                ldsm_x4_t(smem_u32(&BsH[buf][boff]),
                          bh[gi * 2][0], bh[gi * 2][1], bh[gi * 2 + 1][0], bh[gi * 2 + 1][1]);
                ldsm_x4_t(smem_u32(&BsL[buf][boff]),
                          bl[gi * 2][0], bl[gi * 2][1], bl[gi * 2 + 1][0], bl[gi * 2 + 1][1]);
            }
            #pragma unroll
            for (int mt = 0; mt < 2; mt++)
                #pragma unroll
                for (int nt = 0; nt < 4; nt++) {
                    mma16816(acc[mt][nt], ah[mt], bh[nt]);
                    mma16816(acc[mt][nt], al[mt], bh[nt]);
                    mma16816(acc[mt][nt], ah[mt], bl[nt]);
                }
        }
        __syncthreads();
    }

    // epilogue
    #pragma unroll
    for (int mt = 0; mt < 2; mt++) {
        int r0 = bm + wm * 32 + mt * 16 + (lane >> 2);
        #pragma unroll
        for (int nt = 0; nt < 4; nt++) {
            int c0 = bn + wn * 32 + nt * 8 + (lane & 3) * 2;
            float bia0 = 0.0f, bia1 = 0.0f;
            if (args.bias1) { bia0 += args.bias1[c0]; bia1 += args.bias1[c0 + 1]; }
            if (args.bias2) { bia0 += args.bias2[c0]; bia1 += args.bias2[c0 + 1]; }
            float v00 = acc[mt][nt][0] + bia0;
            float v01 = acc[mt][nt][1] + bia1;
            float v10 = acc[mt][nt][2] + bia0;
            float v11 = acc[mt][nt][3] + bia1;
            if (args.act_tanh) {
                v00 = tanhf(v00); v01 = tanhf(v01);
                v10 = tanhf(v10); v11 = tanhf(v11);
            }
            args.D[(size_t)r0 * args.ldd + c0] = v00;
            args.D[(size_t)r0 * args.ldd + c0 + 1] = v01;
            args.D[(size_t)(r0 + 8) * args.ldd + c0] = v10;
            args.D[(size_t)(r0 + 8) * args.ldd + c0 + 1] = v11;
        }
    }
}

// ---------------- fused attention: scores + softmax + context ----------------
// One CTA (512 threads) per batch row b.
__global__ void __launch_bounds__(512)
attn_fused(const float* __restrict__ enc,
           const float* __restrict__ corr_w,
           const float* __restrict__ corr_b,
           const int* __restrict__ mask) {
    const int b = blockIdx.x;
    const int tid = threadIdx.x;
    const int lane = tid & 31;
    const int warp = tid >> 5;      // 16 warps

    __shared__ float sm_e[LL];
    __shared__ float sm_a[LL];

    const float* qb = g_q + (size_t)b * AP;
    // scores: warp w handles l = w, w+16, ...
    for (int l = warp; l < LL; l += 16) {
        const float* ep = g_enc_proj + ((size_t)b * LL + l) * AP;
        float s = 0.0f;
        #pragma unroll 4
        for (int ap = lane; ap < AP; ap += 32)
            s += tanhf(ep[ap] + qb[ap]) * corr_w[ap];
        #pragma unroll
        for (int o = 16; o; o >>= 1) s += __shfl_down_sync(0xffffffffu, s, o);
        if (lane == 0) {
            float v = s + corr_b[0];
            if (mask[b * LL + l] != 0) v = -INFINITY;
            sm_e[l] = v;
        }
    }
    __syncthreads();

    // softmax (warp 0)
    if (warp == 0) {
        float m = -INFINITY;
        #pragma unroll
        for (int i = lane; i < LL; i += 32) m = fmaxf(m, sm_e[i]);
        #pragma unroll
        for (int o = 16; o; o >>= 1) m = fmaxf(m, __shfl_xor_sync(0xffffffffu, m, o));
        float sum = 0.0f;
        #pragma unroll
        for (int i = lane; i < LL; i += 32) sum += expf(sm_e[i] - m);
        #pragma unroll
        for (int o = 16; o; o >>= 1) sum += __shfl_xor_sync(0xffffffffu, sum, o);
        float inv = 1.0f / sum;
        #pragma unroll
        for (int i = lane; i < LL; i += 32) sm_a[i] = expf(sm_e[i] - m) * inv;
    }
    __syncthreads();

    // context: a_t[b,h] = sum_l alpha[l] * enc[b,l,h]; write bf16 hi/lo
    #pragma unroll
    for (int rep = 0; rep < 2; rep++) {
        int h = tid + rep * 512;
        const float* eb = enc + (size_t)b * LL * HE + h;
        float acc = 0.0f;
        #pragma unroll 8
        for (int l = 0; l < LL; l++)
            acc = fmaf(sm_a[l], eb[(size_t)l * HE], acc);
        __nv_bfloat16 hi = __float2bfloat16_rn(acc);
        g_athi[b * HE + h] = hi;
        g_atlo[b * HE + h] = __float2bfloat16_rn(acc - __bfloat162float(hi));
    }
}

// ---------------- LSTM cell elementwise ----------------
__global__ void lstm_cell_k(const float* __restrict__ gates,
                            __nv_bfloat16* __restrict__ hhi,
                            __nv_bfloat16* __restrict__ hlo,
                            float* __restrict__ c) {
    int idx = blockIdx.x * 256 + threadIdx.x;
    if (idx >= BB * HD) return;
    int b = idx / HD, j = idx % HD;
    const float* gb = gates + (size_t)b * G4;
    float ig = gb[j];
    float fg = gb[HD + j];
    float gg = gb[2 * HD + j];
    float og = gb[3 * HD + j];
    float cn = sigm(fg) * c[idx] + sigm(ig) * tanhf(gg);
    float hn = sigm(og) * tanhf(cn);
    c[idx] = cn;
    __nv_bfloat16 h = __float2bfloat16_rn(hn);
    hhi[idx] = h;
    hlo[idx] = __float2bfloat16_rn(hn - __bfloat162float(h));
}

// ---------------- launch ----------------
extern "C" void kernel_launch(void* const* d_in, const int* in_sizes, int n_in,
                              void* d_out, int out_size) {
    const float* enc      = (const float*)d_in[0];
    const int*   mask     = (const int*)  d_in[1];
    const float* h1_0     = (const float*)d_in[2];
    const float* c1_0     = (const float*)d_in[3];
    const float* h2_0     = (const float*)d_in[4];
    const float* c2_0     = (const float*)d_in[5];
    const float* captions = (const float*)d_in[6];
    const float* att_W    = (const float*)d_in[7];
    const float* att_b    = (const float*)d_in[8];
    const float* dhp_W    = (const float*)d_in[9];
    const float* dhp_b    = (const float*)d_in[10];
    const float* corr_w   = (const float*)d_in[11];
    const float* corr_b   = (const float*)d_in[12];
    const float* lt_W     = (const float*)d_in[13];
    const float* lt_b     = (const float*)d_in[14];
    const float* W_ih1    = (const float*)d_in[15];
    const float* W_hh1    = (const float*)d_in[16];
    const float* b_ih1    = (const float*)d_in[17];
    const float* b_hh1    = (const float*)d_in[18];
    const float* W_ih2    = (const float*)d_in[19];
    const float* W_hh2    = (const float*)d_in[20];
    const float* b_ih2    = (const float*)d_in[21];
    const float* b_hh2    = (const float*)d_in[22];
    float* out = (float*)d_out;

    float *p_encproj, *p_q, *p_gates, *p_c1, *p_c2;
    __nv_bfloat16 *p_whi, *p_wlo, *p_h1hi, *p_h1lo, *p_h2hi, *p_h2lo;
    __nv_bfloat16 *p_hp0hi, *p_hp0lo, *p_athi, *p_atlo, *p_caphi, *p_caplo, *p_enchi, *p_enclo;
    cudaGetSymbolAddress((void**)&p_encproj, g_enc_proj);
    cudaGetSymbolAddress((void**)&p_q,     g_q);
    cudaGetSymbolAddress((void**)&p_gates, g_gates);
    cudaGetSymbolAddress((void**)&p_c1,    g_c1);
    cudaGetSymbolAddress((void**)&p_c2,    g_c2);
    cudaGetSymbolAddress((void**)&p_whi,   g_whi);
    cudaGetSymbolAddress((void**)&p_wlo,   g_wlo);
    cudaGetSymbolAddress((void**)&p_h1hi,  g_h1hi);
    cudaGetSymbolAddress((void**)&p_h1lo,  g_h1lo);
    cudaGetSymbolAddress((void**)&p_h2hi,  g_h2hi);
    cudaGetSymbolAddress((void**)&p_h2lo,  g_h2lo);
    cudaGetSymbolAddress((void**)&p_hp0hi, g_hp0hi);
    cudaGetSymbolAddress((void**)&p_hp0lo, g_hp0lo);
    cudaGetSymbolAddress((void**)&p_athi,  g_athi);
    cudaGetSymbolAddress((void**)&p_atlo,  g_atlo);
    cudaGetSymbolAddress((void**)&p_caphi, g_caphi);
    cudaGetSymbolAddress((void**)&p_caplo, g_caplo);
    cudaGetSymbolAddress((void**)&p_enchi, g_enchi);
    cudaGetSymbolAddress((void**)&p_enclo, g_enclo);

    // weight pool offsets
    const size_t o_attW = 0;
    const size_t o_dhpW = o_attW + (size_t)HE * AP;
    const size_t o_ltW  = o_dhpW + (size_t)HD * AP;
    const size_t o_ih1  = o_ltW  + (size_t)HD * HD;
    const size_t o_hh1  = o_ih1  + (size_t)(EE + HE) * G4;
    const size_t o_ih2  = o_hh1  + (size_t)HD * G4;
    const size_t o_hh2  = o_ih2  + (size_t)HD * G4;

    // split weights + captions + enc to bf16 hi/lo
    {
        struct { const float* s; __nv_bfloat16* hi; __nv_bfloat16* lo; size_t n; } cv[9] = {
            {att_W, p_whi + o_attW, p_wlo + o_attW, (size_t)HE * AP},
            {dhp_W, p_whi + o_dhpW, p_wlo + o_dhpW, (size_t)HD * AP},
            {lt_W,  p_whi + o_ltW,  p_wlo + o_ltW,  (size_t)HD * HD},
            {W_ih1, p_whi + o_ih1,  p_wlo + o_ih1,  (size_t)(EE + HE) * G4},
            {W_hh1, p_whi + o_hh1,  p_wlo + o_hh1,  (size_t)HD * G4},
            {W_ih2, p_whi + o_ih2,  p_wlo + o_ih2,  (size_t)HD * G4},
            {W_hh2, p_whi + o_hh2,  p_wlo + o_hh2,  (size_t)HD * G4},
            {captions, p_caphi, p_caplo, (size_t)TT * BB * EE},
            {enc,      p_enchi, p_enclo, (size_t)BB * LL * HE}};
        for (int i = 0; i < 9; i++)
            f32_split<<<(int)((cv[i].n + 255) / 256), 256>>>(cv[i].s, cv[i].hi, cv[i].lo,
                                                             (int)cv[i].n);
    }

    init_state<<<(BB * HD + 255) / 256, 256>>>(h1_0, c1_0, h2_0, c2_0);

    // enc_proj = enc @ att_W + att_b  [(B*L) x AP]
    {
        GemmArgs2 a = {};
        a.seg[0] = {p_enchi, p_enclo, HE, p_whi + o_attW, p_wlo + o_attW, AP, HE};
        a.nseg = 1; a.D = p_encproj; a.ldd = AP; a.bias1 = att_b; a.bias2 = nullptr; a.act_tanh = 0;
        gemm_bf16s<<<dim3(AP / 64, (BB * LL) / 64), 128>>>(a);
    }

    for (int t = 0; t < TT; t++) {
        const __nv_bfloat16* hp_hi = (t == 0) ? p_hp0hi : p_h2hi;
        const __nv_bfloat16* hp_lo = (t == 0) ? p_hp0lo : p_h2lo;

        // q = h_prev @ dhp_W + dhp_b
        {
            GemmArgs2 a = {};
            a.seg[0] = {hp_hi, hp_lo, HD, p_whi + o_dhpW, p_wlo + o_dhpW, AP, HD};
            a.nseg = 1; a.D = p_q; a.ldd = AP; a.bias1 = dhp_b; a.bias2 = nullptr; a.act_tanh = 0;
            gemm_bf16s<<<dim3(AP / 64, BB / 64), 128>>>(a);
        }

        attn_fused<<<BB, 512>>>(enc, corr_w, corr_b, mask);

        // gates1 = x_t@Wih1[:E] + a_t@Wih1[E:] + h1@Whh1 + b_ih1 + b_hh1
        {
            GemmArgs2 a = {};
            a.seg[0] = {p_caphi + (size_t)t * BB * EE, p_caplo + (size_t)t * BB * EE, EE,
                        p_whi + o_ih1, p_wlo + o_ih1, G4, EE};
            a.seg[1] = {p_athi, p_atlo, HE,
                        p_whi + o_ih1 + (size_t)EE * G4, p_wlo + o_ih1 + (size_t)EE * G4, G4, HE};
            a.seg[2] = {p_h1hi, p_h1lo, HD, p_whi + o_hh1, p_wlo + o_hh1, G4, HD};
            a.nseg = 3; a.D = p_gates; a.ldd = G4; a.bias1 = b_ih1; a.bias2 = b_hh1; a.act_tanh = 0;
            gemm_bf16s<<<dim3(G4 / 64, BB / 64), 128>>>(a);
        }
        lstm_cell_k<<<(BB * HD) / 256, 256>>>(p_gates, p_h1hi, p_h1lo, p_c1);

        // out_t = tanh(h1n @ lt_W + lt_b)
        {
            GemmArgs2 a = {};
            a.seg[0] = {p_h1hi, p_h1lo, HD, p_whi + o_ltW, p_wlo + o_ltW, HD, HD};
            a.nseg = 1; a.D = out + (size_t)t * BB * HD; a.ldd = HD;
            a.bias1 = lt_b; a.bias2 = nullptr; a.act_tanh = 1;
            gemm_bf16s<<<dim3(HD / 64, BB / 64), 128>>>(a);
        }

        // gates2 = h1n@Wih2 + h2@Whh2 + b_ih2 + b_hh2
        {
            GemmArgs2 a = {};
            a.seg[0] = {p_h1hi, p_h1lo, HD, p_whi + o_ih2, p_wlo + o_ih2, G4, HD};
            a.seg[1] = {p_h2hi, p_h2lo, HD, p_whi + o_hh2, p_wlo + o_hh2, G4, HD};
            a.nseg = 2; a.D = p_gates; a.ldd = G4; a.bias1 = b_ih2; a.bias2 = b_hh2; a.act_tanh = 0;
            gemm_bf16s<<<dim3(G4 / 64, BB / 64), 128>>>(a);
        }
        lstm_cell_k<<<(BB * HD) / 256, 256>>>(p_gates, p_h2hi, p_h2lo, p_c2);
    }

    (void)in_sizes; (void)n_in; (void)out_size;
}

// round 4
// speedup vs baseline: 3.5196x; 1.2745x over previous
#include <cuda_runtime.h>
#include <cuda_bf16.h>
#include <math.h>
#include <stdint.h>

// Problem constants
#define BB 128   // batch
#define LL 128   // enc length
#define HE 1024  // enc hidden
#define HD 1024  // dec hidden
#define EE 512   // embed
#define AP 512   // attn proj
#define TT 64    // timesteps
#define G4 (4*HD)

// ---------------- device scratch ----------------
__device__ float g_enc_proj[BB * LL * AP];   // 33.5 MB fp32
__device__ float g_q[BB * AP];
__device__ float g_gates[BB * G4];
__device__ float g_c1[BB * HD];
__device__ float g_c2[BB * HD];

// bf16 hi/lo activation buffers
__device__ __nv_bfloat16 g_h1hi[BB * HD], g_h1lo[BB * HD];
__device__ __nv_bfloat16 g_h2hi[BB * HD], g_h2lo[BB * HD];
__device__ __nv_bfloat16 g_hp0hi[BB * HD], g_hp0lo[BB * HD];   // initial h_prev
__device__ __nv_bfloat16 g_athi[BB * HE], g_atlo[BB * HE];
__device__ __nv_bfloat16 g_caphi[TT * BB * EE], g_caplo[TT * BB * EE];
__device__ __nv_bfloat16 g_enchi[BB * LL * HE], g_enclo[BB * LL * HE];

// bf16 hi/lo weight pool
#define WPOOL 20971520
__device__ __nv_bfloat16 g_whi[WPOOL];
__device__ __nv_bfloat16 g_wlo[WPOOL];

__device__ __forceinline__ float fast_tanh(float x) {
    float e = __expf(2.0f * x);
    return 1.0f - __fdividef(2.0f, e + 1.0f);
}
__device__ __forceinline__ float fast_sigm(float x) {
    return __fdividef(1.0f, 1.0f + __expf(-x));
}

// ---------------- init ----------------
__global__ void init_state(const float* __restrict__ h1_0, const float* __restrict__ c1_0,
                           const float* __restrict__ h2_0, const float* __restrict__ c2_0) {
    int i = blockIdx.x * blockDim.x + threadIdx.x;
    if (i < BB * HD) {
        float h1 = h1_0[i], h2 = h2_0[i];
        __nv_bfloat16 a = __float2bfloat16_rn(h1);
        g_h1hi[i] = a; g_h1lo[i] = __float2bfloat16_rn(h1 - __bfloat162float(a));
        __nv_bfloat16 b = __float2bfloat16_rn(h2);
        g_h2hi[i] = b; g_h2lo[i] = __float2bfloat16_rn(h2 - __bfloat162float(b));
        g_c1[i] = c1_0[i];
        g_c2[i] = c2_0[i];
        g_hp0hi[i] = __float2bfloat16_rn(1.0f / (float)HE);  // 2^-10 exact
        g_hp0lo[i] = __float2bfloat16_rn(0.0f);
    }
}

// ---------------- fp32 -> (bf16 hi, bf16 lo) split ----------------
__global__ void f32_split(const float* __restrict__ src,
                          __nv_bfloat16* __restrict__ hi,
                          __nv_bfloat16* __restrict__ lo, int n) {
    int i = blockIdx.x * 256 + threadIdx.x;
    if (i < n) {
        float x = src[i];
        __nv_bfloat16 h = __float2bfloat16_rn(x);
        hi[i] = h;
        lo[i] = __float2bfloat16_rn(x - __bfloat162float(h));
    }
}

// ---------------- split-bf16 tensor-core GEMM ----------------
// D[M,N] = sum_seg A_seg[M,K] @ B_seg[K,N] (+bias1+bias2, opt tanh)
// A,B bf16 hi/lo; 3 mma passes: Ah*Bh + Al*Bh + Ah*Bl, fp32 accum.
// 256 threads = 2 warp-sets of 4 warps. Set s handles k-tiles g where g%2==s,
// with a private 3-stage cp.async pipeline + named barrier. Partials merged
// through smem, epilogue by set 0.

struct Seg2 {
    const __nv_bfloat16* Ahi; const __nv_bfloat16* Alo; int lda;
    const __nv_bfloat16* Bhi; const __nv_bfloat16* Blo; int ldb;
    int K;
};
struct GemmArgs2 {
    Seg2 seg[3];
    int nseg;
    float* D; int ldd;
    const float* bias1; const float* bias2;
    int act_tanh;
};

#define PADA 40   // A smem row stride (halves) = 80B
#define PADB 72   // B smem row stride (halves) = 144B
#define STG 3     // pipeline stages per set

#define A_SET_H (STG * 64 * PADA)   // halves per (set, hi|lo)
#define B_SET_H (STG * 32 * PADB)
#define SET_H   (2 * A_SET_H + 2 * B_SET_H)
#define SMEM_BYTES (2 * SET_H * 2)

__device__ __forceinline__ uint32_t smem_u32(const void* p) {
    return (uint32_t)__cvta_generic_to_shared(p);
}
__device__ __forceinline__ void cp16(void* dst, const void* src) {
    asm volatile("cp.async.ca.shared.global [%0], [%1], 16;"
                 :: "r"(smem_u32(dst)), "l"(src));
}
__device__ __forceinline__ void ldsm_x4(uint32_t addr, uint32_t* r) {
    asm volatile("ldmatrix.sync.aligned.m8n8.x4.shared.b16 {%0,%1,%2,%3}, [%4];"
                 : "=r"(r[0]), "=r"(r[1]), "=r"(r[2]), "=r"(r[3]) : "r"(addr));
}
__device__ __forceinline__ void ldsm_x4_t(uint32_t addr, uint32_t& r0, uint32_t& r1,
                                          uint32_t& r2, uint32_t& r3) {
    asm volatile("ldmatrix.sync.aligned.m8n8.x4.trans.shared.b16 {%0,%1,%2,%3}, [%4];"
                 : "=r"(r0), "=r"(r1), "=r"(r2), "=r"(r3) : "r"(addr));
}
__device__ __forceinline__ void mma16816(float* c, const uint32_t* a, const uint32_t* b) {
    asm volatile(
        "mma.sync.aligned.m16n8k16.row.col.f32.bf16.bf16.f32 "
        "{%0,%1,%2,%3}, {%4,%5,%6,%7}, {%8,%9}, {%0,%1,%2,%3};"
        : "+f"(c[0]), "+f"(c[1]), "+f"(c[2]), "+f"(c[3])
        : "r"(a[0]), "r"(a[1]), "r"(a[2]), "r"(a[3]), "r"(b[0]), "r"(b[1]));
}
__device__ __forceinline__ void bar_set(int set) {
    asm volatile("bar.sync %0, 128;" :: "r"(set + 1) : "memory");
}

__device__ __forceinline__ void stage_tile(const GemmArgs2& a, int g, int bm, int bn, int stid,
                                           __nv_bfloat16* AsH, __nv_bfloat16* AsL,
                                           __nv_bfloat16* BsH, __nv_bfloat16* BsL) {
    int s = 0, rem = g;
    #pragma unroll
    for (int i = 0; i < 2; i++)
        if (s < a.nseg - 1 && rem >= (a.seg[s].K >> 5)) { rem -= a.seg[s].K >> 5; s++; }
    const Seg2 sg = a.seg[s];
    const int k0 = rem << 5;
    // A tile 64x32 (hi+lo): 256 16B-chunks each, 128 threads -> 2 per thread
    #pragma unroll
    for (int i = 0; i < 2; i++) {
        int ch = stid + i * 128;
        int row = ch >> 2, c = (ch & 3) * 8;
        size_t off = (size_t)(bm + row) * sg.lda + k0 + c;
        cp16(AsH + row * PADA + c, sg.Ahi + off);
        cp16(AsL + row * PADA + c, sg.Alo + off);
    }
    // B tile 32x64 (hi+lo)
    #pragma unroll
    for (int i = 0; i < 2; i++) {
        int ch = stid + i * 128;
        int row = ch >> 3, c = (ch & 7) * 8;
        size_t off = (size_t)(k0 + row) * sg.ldb + bn + c;
        cp16(BsH + row * PADB + c, sg.Bhi + off);
        cp16(BsL + row * PADB + c, sg.Blo + off);
    }
}

__global__ void __launch_bounds__(256)
gemm_bf16s(GemmArgs2 args) {
    extern __shared__ __align__(16) char smem_raw[];
    __nv_bfloat16* base = (__nv_bfloat16*)smem_raw;

    const int tid = threadIdx.x;
    const int lane = tid & 31;
    const int wid = tid >> 5;
    const int set = wid >> 2;        // 0/1
    const int swid = wid & 3;        // warp within set
    const int stid = tid & 127;      // thread within set
    const int wm = swid & 1;
    const int wn = swid >> 1;
    const int bm = blockIdx.y * 64;
    const int bn = blockIdx.x * 64;

    __nv_bfloat16* AsH = base + set * SET_H;
    __nv_bfloat16* AsL = AsH + A_SET_H;
    __nv_bfloat16* BsH = AsL + A_SET_H;
    __nv_bfloat16* BsL = BsH + B_SET_H;
    float* red = (float*)(base + SET_H);   // set-1 region, reused post-pipeline

    int ntile = 0;
    #pragma unroll
    for (int s = 0; s < 3; s++) if (s < args.nseg) ntile += args.seg[s].K >> 5;
    const int cnt = (ntile - set + 1) >> 1;      // tiles for this set (g = 2j+set)

    float acc[2][4][4];
    #pragma unroll
    for (int i = 0; i < 2; i++)
        #pragma unroll
        for (int j = 0; j < 4; j++)
            #pragma unroll
            for (int k = 0; k < 4; k++) acc[i][j][k] = 0.0f;

    const int a_r = lane & 15;
    const int a_c = (lane >> 4) << 3;
    const int b_r = (lane & 7) + ((lane >> 3) & 1) * 8;
    const int b_c = (lane >> 4) << 3;

    // prologue: stage tiles j=0, j=1 (always commit twice for uniform counting)
    if (cnt > 0)
        stage_tile(args, set, bm, bn, stid, AsH, AsL, BsH, BsL);
    asm volatile("cp.async.commit_group;");
    if (cnt > 1)
        stage_tile(args, 2 + set, bm, bn, stid,
                   AsH + 64 * PADA, AsL + 64 * PADA, BsH + 32 * PADB, BsL + 32 * PADB);
    asm volatile("cp.async.commit_group;");

    for (int j = 0; j < cnt; j++) {
        asm volatile("cp.async.wait_group 1;");
        bar_set(set);
        // stage j+2 into stage-slot (j+2)%3 (safe: consumed at iter j-1)
        {
            int p = (j + 2) % 3;
            if (j + 2 < cnt)
                stage_tile(args, 2 * (j + 2) + set, bm, bn, stid,
                           AsH + p * 64 * PADA, AsL + p * 64 * PADA,
                           BsH + p * 32 * PADB, BsL + p * 32 * PADB);
            asm volatile("cp.async.commit_group;");
        }
        // compute on stage-slot j%3
        const int q = j % 3;
        const __nv_bfloat16* cAH = AsH + q * 64 * PADA;
        const __nv_bfloat16* cAL = AsL + q * 64 * PADA;
        const __nv_bfloat16* cBH = BsH + q * 32 * PADB;
        const __nv_bfloat16* cBL = BsL + q * 32 * PADB;
        #pragma unroll
        for (int kk = 0; kk < 32; kk += 16) {
            uint32_t ah[2][4], al[2][4];
            #pragma unroll
            for (int mt = 0; mt < 2; mt++) {
                int rowoff = (wm * 32 + mt * 16 + a_r) * PADA + kk + a_c;
                ldsm_x4(smem_u32(&cAH[rowoff]), ah[mt]);
                ldsm_x4(smem_u32(&cAL[rowoff]), al[mt]);
            }
            uint32_t bh[4][2], bl[4][2];
            #pragma unroll
            for (int gi = 0; gi < 2; gi++) {
                int boff = (kk + b_r) * PADB + wn * 32 + gi * 16 + b_c;
                ldsm_x4_t(smem_u32(&cBH[boff]),
                          bh[gi * 2][0], bh[gi * 2][1], bh[gi * 2 + 1][0], bh[gi * 2 + 1][1]);
                ldsm_x4_t(smem_u32(&cBL[boff]),
                          bl[gi * 2][0], bl[gi * 2][1], bl[gi * 2 + 1][0], bl[gi * 2 + 1][1]);
            }
            #pragma unroll
            for (int mt = 0; mt < 2; mt++)
                #pragma unroll
                for (int nt = 0; nt < 4; nt++) {
                    mma16816(acc[mt][nt], ah[mt], bh[nt]);
                    mma16816(acc[mt][nt], al[mt], bh[nt]);
                    mma16816(acc[mt][nt], ah[mt], bl[nt]);
                }
        }
    }

    asm volatile("cp.async.wait_group 0;");
    __syncthreads();

    // merge set-1 partials into set-0 accumulators via smem
    if (set == 1) {
        float* r = red + swid * 1024 + lane * 32;
        #pragma unroll
        for (int mt = 0; mt < 2; mt++)
            #pragma unroll
            for (int nt = 0; nt < 4; nt++)
                #pragma unroll
                for (int k = 0; k < 4; k++)
                    r[mt * 16 + nt * 4 + k] = acc[mt][nt][k];
    }
    __syncthreads();
    if (set == 0) {
        const float* r = red + swid * 1024 + lane * 32;
        #pragma unroll
        for (int mt = 0; mt < 2; mt++)
            #pragma unroll
            for (int nt = 0; nt < 4; nt++)
                #pragma unroll
                for (int k = 0; k < 4; k++)
                    acc[mt][nt][k] += r[mt * 16 + nt * 4 + k];

        // epilogue (warps 0-3)
        #pragma unroll
        for (int mt = 0; mt < 2; mt++) {
            int r0 = bm + wm * 32 + mt * 16 + (lane >> 2);
            #pragma unroll
            for (int nt = 0; nt < 4; nt++) {
                int c0 = bn + wn * 32 + nt * 8 + (lane & 3) * 2;
                float bia0 = 0.0f, bia1 = 0.0f;
                if (args.bias1) { bia0 += args.bias1[c0]; bia1 += args.bias1[c0 + 1]; }
                if (args.bias2) { bia0 += args.bias2[c0]; bia1 += args.bias2[c0 + 1]; }
                float v00 = acc[mt][nt][0] + bia0;
                float v01 = acc[mt][nt][1] + bia1;
                float v10 = acc[mt][nt][2] + bia0;
                float v11 = acc[mt][nt][3] + bia1;
                if (args.act_tanh) {
                    v00 = fast_tanh(v00); v01 = fast_tanh(v01);
                    v10 = fast_tanh(v10); v11 = fast_tanh(v11);
                }
                args.D[(size_t)r0 * args.ldd + c0] = v00;
                args.D[(size_t)r0 * args.ldd + c0 + 1] = v01;
                args.D[(size_t)(r0 + 8) * args.ldd + c0] = v10;
                args.D[(size_t)(r0 + 8) * args.ldd + c0 + 1] = v11;
            }
        }
    }
}

// ---------------- fused attention: scores + softmax + context ----------------
__global__ void __launch_bounds__(512)
attn_fused(const float* __restrict__ enc,
           const float* __restrict__ corr_w,
           const float* __restrict__ corr_b,
           const int* __restrict__ mask) {
    const int b = blockIdx.x;
    const int tid = threadIdx.x;
    const int lane = tid & 31;
    const int warp = tid >> 5;      // 16 warps

    __shared__ float sm_e[LL];
    __shared__ float sm_a[LL];

    const float* qb = g_q + (size_t)b * AP;
    for (int l = warp; l < LL; l += 16) {
        const float* ep = g_enc_proj + ((size_t)b * LL + l) * AP;
        float s = 0.0f;
        #pragma unroll 4
        for (int ap = lane; ap < AP; ap += 32)
            s += fast_tanh(ep[ap] + qb[ap]) * corr_w[ap];
        #pragma unroll
        for (int o = 16; o; o >>= 1) s += __shfl_down_sync(0xffffffffu, s, o);
        if (lane == 0) {
            float v = s + corr_b[0];
            if (mask[b * LL + l] != 0) v = -INFINITY;
            sm_e[l] = v;
        }
    }
    __syncthreads();

    if (warp == 0) {
        float m = -INFINITY;
        #pragma unroll
        for (int i = lane; i < LL; i += 32) m = fmaxf(m, sm_e[i]);
        #pragma unroll
        for (int o = 16; o; o >>= 1) m = fmaxf(m, __shfl_xor_sync(0xffffffffu, m, o));
        float sum = 0.0f;
        #pragma unroll
        for (int i = lane; i < LL; i += 32) sum += __expf(sm_e[i] - m);
        #pragma unroll
        for (int o = 16; o; o >>= 1) sum += __shfl_xor_sync(0xffffffffu, sum, o);
        float inv = __fdividef(1.0f, sum);
        #pragma unroll
        for (int i = lane; i < LL; i += 32) sm_a[i] = __expf(sm_e[i] - m) * inv;
    }
    __syncthreads();

    #pragma unroll
    for (int rep = 0; rep < 2; rep++) {
        int h = tid + rep * 512;
        const float* eb = enc + (size_t)b * LL * HE + h;
        float acc = 0.0f;
        #pragma unroll 8
        for (int l = 0; l < LL; l++)
            acc = fmaf(sm_a[l], eb[(size_t)l * HE], acc);
        __nv_bfloat16 hi = __float2bfloat16_rn(acc);
        g_athi[b * HE + h] = hi;
        g_atlo[b * HE + h] = __float2bfloat16_rn(acc - __bfloat162float(hi));
    }
}

// ---------------- LSTM cell elementwise ----------------
__global__ void lstm_cell_k(const float* __restrict__ gates,
                            __nv_bfloat16* __restrict__ hhi,
                            __nv_bfloat16* __restrict__ hlo,
                            float* __restrict__ c) {
    int idx = blockIdx.x * 256 + threadIdx.x;
    if (idx >= BB * HD) return;
    int b = idx / HD, j = idx % HD;
    const float* gb = gates + (size_t)b * G4;
    float ig = gb[j];
    float fg = gb[HD + j];
    float gg = gb[2 * HD + j];
    float og = gb[3 * HD + j];
    float cn = fast_sigm(fg) * c[idx] + fast_sigm(ig) * fast_tanh(gg);
    float hn = fast_sigm(og) * fast_tanh(cn);
    c[idx] = cn;
    __nv_bfloat16 h = __float2bfloat16_rn(hn);
    hhi[idx] = h;
    hlo[idx] = __float2bfloat16_rn(hn - __bfloat162float(h));
}

// ---------------- launch ----------------
extern "C" void kernel_launch(void* const* d_in, const int* in_sizes, int n_in,
                              void* d_out, int out_size) {
    const float* enc      = (const float*)d_in[0];
    const int*   mask     = (const int*)  d_in[1];
    const float* h1_0     = (const float*)d_in[2];
    const float* c1_0     = (const float*)d_in[3];
    const float* h2_0     = (const float*)d_in[4];
    const float* c2_0     = (const float*)d_in[5];
    const float* captions = (const float*)d_in[6];
    const float* att_W    = (const float*)d_in[7];
    const float* att_b    = (const float*)d_in[8];
    const float* dhp_W    = (const float*)d_in[9];
    const float* dhp_b    = (const float*)d_in[10];
    const float* corr_w   = (const float*)d_in[11];
    const float* corr_b   = (const float*)d_in[12];
    const float* lt_W     = (const float*)d_in[13];
    const float* lt_b     = (const float*)d_in[14];
    const float* W_ih1    = (const float*)d_in[15];
    const float* W_hh1    = (const float*)d_in[16];
    const float* b_ih1    = (const float*)d_in[17];
    const float* b_hh1    = (const float*)d_in[18];
    const float* W_ih2    = (const float*)d_in[19];
    const float* W_hh2    = (const float*)d_in[20];
    const float* b_ih2    = (const float*)d_in[21];
    const float* b_hh2    = (const float*)d_in[22];
    float* out = (float*)d_out;

    cudaFuncSetAttribute(gemm_bf16s, cudaFuncAttributeMaxDynamicSharedMemorySize, SMEM_BYTES);

    float *p_encproj, *p_q, *p_gates, *p_c1, *p_c2;
    __nv_bfloat16 *p_whi, *p_wlo, *p_h1hi, *p_h1lo, *p_h2hi, *p_h2lo;
    __nv_bfloat16 *p_hp0hi, *p_hp0lo, *p_athi, *p_atlo, *p_caphi, *p_caplo, *p_enchi, *p_enclo;
    cudaGetSymbolAddress((void**)&p_encproj, g_enc_proj);
    cudaGetSymbolAddress((void**)&p_q,     g_q);
    cudaGetSymbolAddress((void**)&p_gates, g_gates);
    cudaGetSymbolAddress((void**)&p_c1,    g_c1);
    cudaGetSymbolAddress((void**)&p_c2,    g_c2);
    cudaGetSymbolAddress((void**)&p_whi,   g_whi);
    cudaGetSymbolAddress((void**)&p_wlo,   g_wlo);
    cudaGetSymbolAddress((void**)&p_h1hi,  g_h1hi);
    cudaGetSymbolAddress((void**)&p_h1lo,  g_h1lo);
    cudaGetSymbolAddress((void**)&p_h2hi,  g_h2hi);
    cudaGetSymbolAddress((void**)&p_h2lo,  g_h2lo);
    cudaGetSymbolAddress((void**)&p_hp0hi, g_hp0hi);
    cudaGetSymbolAddress((void**)&p_hp0lo, g_hp0lo);
    cudaGetSymbolAddress((void**)&p_athi,  g_athi);
    cudaGetSymbolAddress((void**)&p_atlo,  g_atlo);
    cudaGetSymbolAddress((void**)&p_caphi, g_caphi);
    cudaGetSymbolAddress((void**)&p_caplo, g_caplo);
    cudaGetSymbolAddress((void**)&p_enchi, g_enchi);
    cudaGetSymbolAddress((void**)&p_enclo, g_enclo);

    // weight pool offsets
    const size_t o_attW = 0;
    const size_t o_dhpW = o_attW + (size_t)HE * AP;
    const size_t o_ltW  = o_dhpW + (size_t)HD * AP;
    const size_t o_ih1  = o_ltW  + (size_t)HD * HD;
    const size_t o_hh1  = o_ih1  + (size_t)(EE + HE) * G4;
    const size_t o_ih2  = o_hh1  + (size_t)HD * G4;
    const size_t o_hh2  = o_ih2  + (size_t)HD * G4;

    // split weights + captions + enc to bf16 hi/lo
    {
        struct { const float* s; __nv_bfloat16* hi; __nv_bfloat16* lo; size_t n; } cv[9] = {
            {att_W, p_whi + o_attW, p_wlo + o_attW, (size_t)HE * AP},
            {dhp_W, p_whi + o_dhpW, p_wlo + o_dhpW, (size_t)HD * AP},
            {lt_W,  p_whi + o_ltW,  p_wlo + o_ltW,  (size_t)HD * HD},
            {W_ih1, p_whi + o_ih1,  p_wlo + o_ih1,  (size_t)(EE + HE) * G4},
            {W_hh1, p_whi + o_hh1,  p_wlo + o_hh1,  (size_t)HD * G4},
            {W_ih2, p_whi + o_ih2,  p_wlo + o_ih2,  (size_t)HD * G4},
            {W_hh2, p_whi + o_hh2,  p_wlo + o_hh2,  (size_t)HD * G4},
            {captions, p_caphi, p_caplo, (size_t)TT * BB * EE},
            {enc,      p_enchi, p_enclo, (size_t)BB * LL * HE}};
        for (int i = 0; i < 9; i++)
            f32_split<<<(int)((cv[i].n + 255) / 256), 256>>>(cv[i].s, cv[i].hi, cv[i].lo,
                                                             (int)cv[i].n);
    }

    init_state<<<(BB * HD + 255) / 256, 256>>>(h1_0, c1_0, h2_0, c2_0);

    // enc_proj = enc @ att_W + att_b  [(B*L) x AP]
    {
        GemmArgs2 a = {};
        a.seg[0] = {p_enchi, p_enclo, HE, p_whi + o_attW, p_wlo + o_attW, AP, HE};
        a.nseg = 1; a.D = p_encproj; a.ldd = AP; a.bias1 = att_b; a.bias2 = nullptr; a.act_tanh = 0;
        gemm_bf16s<<<dim3(AP / 64, (BB * LL) / 64), 256, SMEM_BYTES>>>(a);
    }

    for (int t = 0; t < TT; t++) {
        const __nv_bfloat16* hp_hi = (t == 0) ? p_hp0hi : p_h2hi;
        const __nv_bfloat16* hp_lo = (t == 0) ? p_hp0lo : p_h2lo;

        // q = h_prev @ dhp_W + dhp_b
        {
            GemmArgs2 a = {};
            a.seg[0] = {hp_hi, hp_lo, HD, p_whi + o_dhpW, p_wlo + o_dhpW, AP, HD};
            a.nseg = 1; a.D = p_q; a.ldd = AP; a.bias1 = dhp_b; a.bias2 = nullptr; a.act_tanh = 0;
            gemm_bf16s<<<dim3(AP / 64, BB / 64), 256, SMEM_BYTES>>>(a);
        }

        attn_fused<<<BB, 512>>>(enc, corr_w, corr_b, mask);

        // gates1 = x_t@Wih1[:E] + a_t@Wih1[E:] + h1@Whh1 + b_ih1 + b_hh1
        {
            GemmArgs2 a = {};
            a.seg[0] = {p_caphi + (size_t)t * BB * EE, p_caplo + (size_t)t * BB * EE, EE,
                        p_whi + o_ih1, p_wlo + o_ih1, G4, EE};
            a.seg[1] = {p_athi, p_atlo, HE,
                        p_whi + o_ih1 + (size_t)EE * G4, p_wlo + o_ih1 + (size_t)EE * G4, G4, HE};
            a.seg[2] = {p_h1hi, p_h1lo, HD, p_whi + o_hh1, p_wlo + o_hh1, G4, HD};
            a.nseg = 3; a.D = p_gates; a.ldd = G4; a.bias1 = b_ih1; a.bias2 = b_hh1; a.act_tanh = 0;
            gemm_bf16s<<<dim3(G4 / 64, BB / 64), 256, SMEM_BYTES>>>(a);
        }
        lstm_cell_k<<<(BB * HD) / 256, 256>>>(p_gates, p_h1hi, p_h1lo, p_c1);

        // out_t = tanh(h1n @ lt_W + lt_b)
        {
            GemmArgs2 a = {};
            a.seg[0] = {p_h1hi, p_h1lo, HD, p_whi + o_ltW, p_wlo + o_ltW, HD, HD};
            a.nseg = 1; a.D = out + (size_t)t * BB * HD; a.ldd = HD;
            a.bias1 = lt_b; a.bias2 = nullptr; a.act_tanh = 1;
            gemm_bf16s<<<dim3(HD / 64, BB / 64), 256, SMEM_BYTES>>>(a);
        }

        // gates2 = h1n@Wih2 + h2@Whh2 + b_ih2 + b_hh2
        {
            GemmArgs2 a = {};
            a.seg[0] = {p_h1hi, p_h1lo, HD, p_whi + o_ih2, p_wlo + o_ih2, G4, HD};
            a.seg[1] = {p_h2hi, p_h2lo, HD, p_whi + o_hh2, p_wlo + o_hh2, G4, HD};
            a.nseg = 2; a.D = p_gates; a.ldd = G4; a.bias1 = b_ih2; a.bias2 = b_hh2; a.act_tanh = 0;
            gemm_bf16s<<<dim3(G4 / 64, BB / 64), 256, SMEM_BYTES>>>(a);
        }
        lstm_cell_k<<<(BB * HD) / 256, 256>>>(p_gates, p_h2hi, p_h2lo, p_c2);
    }

    (void)in_sizes; (void)n_in; (void)out_size;
}

// round 5
// speedup vs baseline: 3.7654x; 1.0698x over previous
#include <cuda_runtime.h>
#include <cuda_bf16.h>
#include <math.h>
#include <stdint.h>

// Problem constants
#define BB 128   // batch
#define LL 128   // enc length
#define HE 1024  // enc hidden
#define HD 1024  // dec hidden
#define EE 512   // embed
#define AP 512   // attn proj
#define TT 64    // timesteps
#define G4 (4*HD)
#define NMEGA (G4 + HD)   // 5120: gates2 cols + out cols
#define QSPLIT 8

// ---------------- device scratch ----------------
__device__ float g_enc_proj[BB * LL * AP];   // 33.5 MB fp32
__device__ float g_qpart[QSPLIT * BB * AP];  // split-K q partials
__device__ float g_c1[BB * HD];
__device__ float g_c2[BB * HD];
__device__ float g_b1p[G4];                  // permuted b_ih1+b_hh1
__device__ float g_bmega[NMEGA];             // permuted b_ih2+b_hh2 | lt_b

// bf16 hi/lo activation buffers
__device__ __nv_bfloat16 g_h1hi[BB * HD], g_h1lo[BB * HD];
__device__ __nv_bfloat16 g_h2hi[BB * HD], g_h2lo[BB * HD];
__device__ __nv_bfloat16 g_hp0hi[BB * HD], g_hp0lo[BB * HD];
__device__ __nv_bfloat16 g_athi[BB * HE], g_atlo[BB * HE];
__device__ __nv_bfloat16 g_caphi[TT * BB * EE], g_caplo[TT * BB * EE];
__device__ __nv_bfloat16 g_enchi[BB * LL * HE], g_enclo[BB * LL * HE];

// bf16 hi/lo weight pool: attW + dhpW + Wih1p + Whh1p + mega
#define WPOOL 22020096
__device__ __nv_bfloat16 g_whi[WPOOL];
__device__ __nv_bfloat16 g_wlo[WPOOL];

__device__ __forceinline__ float fast_tanh(float x) {
    float e = __expf(2.0f * x);
    return 1.0f - __fdividef(2.0f, e + 1.0f);
}
__device__ __forceinline__ float fast_sigm(float x) {
    return __fdividef(1.0f, 1.0f + __expf(-x));
}

// ---------------- prep kernels ----------------
__global__ void init_state(const float* __restrict__ h1_0, const float* __restrict__ c1_0,
                           const float* __restrict__ h2_0, const float* __restrict__ c2_0) {
    int i = blockIdx.x * blockDim.x + threadIdx.x;
    if (i < BB * HD) {
        float h1 = h1_0[i], h2 = h2_0[i];
        __nv_bfloat16 a = __float2bfloat16_rn(h1);
        g_h1hi[i] = a; g_h1lo[i] = __float2bfloat16_rn(h1 - __bfloat162float(a));
        __nv_bfloat16 b = __float2bfloat16_rn(h2);
        g_h2hi[i] = b; g_h2lo[i] = __float2bfloat16_rn(h2 - __bfloat162float(b));
        g_c1[i] = c1_0[i];
        g_c2[i] = c2_0[i];
        g_hp0hi[i] = __float2bfloat16_rn(1.0f / (float)HE);
        g_hp0lo[i] = __float2bfloat16_rn(0.0f);
    }
}

__global__ void f32_split(const float* __restrict__ src,
                          __nv_bfloat16* __restrict__ hi,
                          __nv_bfloat16* __restrict__ lo, int n) {
    int i = blockIdx.x * 256 + threadIdx.x;
    if (i < n) {
        float x = src[i];
        __nv_bfloat16 h = __float2bfloat16_rn(x);
        hi[i] = h;
        lo[i] = __float2bfloat16_rn(x - __bfloat162float(h));
    }
}

// gate-permuting split: src [K x 4096] (gate-major cols), dst col' = 4*j+gate
__global__ void f32_split_perm(const float* __restrict__ src,
                               __nv_bfloat16* __restrict__ hi,
                               __nv_bfloat16* __restrict__ lo,
                               int K, int lddst) {
    int i = blockIdx.x * 256 + threadIdx.x;
    if (i < K * G4) {
        int row = i / G4, cd = i % G4;
        int j = cd >> 2, gate = cd & 3;
        float x = src[(size_t)row * G4 + gate * HD + j];
        __nv_bfloat16 h = __float2bfloat16_rn(x);
        size_t o = (size_t)row * lddst + cd;
        hi[o] = h;
        lo[o] = __float2bfloat16_rn(x - __bfloat162float(h));
    }
}

// plain split with dst leading dim
__global__ void f32_split_ld(const float* __restrict__ src,
                             __nv_bfloat16* __restrict__ hi,
                             __nv_bfloat16* __restrict__ lo,
                             int K, int N, int ldsrc, int lddst) {
    int i = blockIdx.x * 256 + threadIdx.x;
    if (i < K * N) {
        int row = i / N, c = i % N;
        float x = src[(size_t)row * ldsrc + c];
        __nv_bfloat16 h = __float2bfloat16_rn(x);
        size_t o = (size_t)row * lddst + c;
        hi[o] = h;
        lo[o] = __float2bfloat16_rn(x - __bfloat162float(h));
    }
}

__global__ void zero_block(__nv_bfloat16* __restrict__ hi,
                           __nv_bfloat16* __restrict__ lo,
                           int K, int N, int lddst) {
    int i = blockIdx.x * 256 + threadIdx.x;
    if (i < K * N) {
        int row = i / N, c = i % N;
        size_t o = (size_t)row * lddst + c;
        hi[o] = __float2bfloat16_rn(0.0f);
        lo[o] = __float2bfloat16_rn(0.0f);
    }
}

__global__ void bias_prep(const float* __restrict__ bi1, const float* __restrict__ bh1,
                          const float* __restrict__ bi2, const float* __restrict__ bh2,
                          const float* __restrict__ ltb) {
    int i = blockIdx.x * 256 + threadIdx.x;
    if (i < G4) {
        int j = i >> 2, gate = i & 3;
        g_b1p[i]   = bi1[gate * HD + j] + bh1[gate * HD + j];
        g_bmega[i] = bi2[gate * HD + j] + bh2[gate * HD + j];
    }
    if (i < HD) g_bmega[G4 + i] = ltb[i];
}

// ---------------- split-bf16 tensor-core GEMM with fused epilogues ----------------
struct Seg2 {
    const __nv_bfloat16* Ahi; const __nv_bfloat16* Alo; int lda;
    const __nv_bfloat16* Bhi; const __nv_bfloat16* Blo; int ldb;
    int K;
};
struct GemmArgs3 {
    Seg2 seg[3];
    int nseg;
    float* D; int ldd;            // mode 0/1 output
    const float* bias;            // indexed by global col (may be null)
    int mode;                     // 0 plain, 1 tanh, 2 cell, 3 mega (cell cols<ncell, tanh->D2 else)
    float* cellC; __nv_bfloat16* cellHhi; __nv_bfloat16* cellHlo;
    int ncell;
    float* D2; int ldd2;
    int zchunk;                   // >0: split-K via blockIdx.z (nseg==1)
};

#define PADA 40
#define PADB 72
#define STG 3
#define A_SET_H (STG * 64 * PADA)
#define B_SET_H (STG * 32 * PADB)
#define SET_H   (2 * A_SET_H + 2 * B_SET_H)
#define SMEM_BYTES (2 * SET_H * 2)

__device__ __forceinline__ uint32_t smem_u32(const void* p) {
    return (uint32_t)__cvta_generic_to_shared(p);
}
__device__ __forceinline__ void cp16(void* dst, const void* src) {
    asm volatile("cp.async.ca.shared.global [%0], [%1], 16;"
                 :: "r"(smem_u32(dst)), "l"(src));
}
__device__ __forceinline__ void ldsm_x4(uint32_t addr, uint32_t* r) {
    asm volatile("ldmatrix.sync.aligned.m8n8.x4.shared.b16 {%0,%1,%2,%3}, [%4];"
                 : "=r"(r[0]), "=r"(r[1]), "=r"(r[2]), "=r"(r[3]) : "r"(addr));
}
__device__ __forceinline__ void ldsm_x4_t(uint32_t addr, uint32_t& r0, uint32_t& r1,
                                          uint32_t& r2, uint32_t& r3) {
    asm volatile("ldmatrix.sync.aligned.m8n8.x4.trans.shared.b16 {%0,%1,%2,%3}, [%4];"
                 : "=r"(r0), "=r"(r1), "=r"(r2), "=r"(r3) : "r"(addr));
}
__device__ __forceinline__ void mma16816(float* c, const uint32_t* a, const uint32_t* b) {
    asm volatile(
        "mma.sync.aligned.m16n8k16.row.col.f32.bf16.bf16.f32 "
        "{%0,%1,%2,%3}, {%4,%5,%6,%7}, {%8,%9}, {%0,%1,%2,%3};"
        : "+f"(c[0]), "+f"(c[1]), "+f"(c[2]), "+f"(c[3])
        : "r"(a[0]), "r"(a[1]), "r"(a[2]), "r"(a[3]), "r"(b[0]), "r"(b[1]));
}
__device__ __forceinline__ void bar_set(int set) {
    asm volatile("bar.sync %0, 128;" :: "r"(set + 1) : "memory");
}

__device__ __forceinline__ void stage_tile(const GemmArgs3& a, int g, int bm, int bn, int stid,
                                           __nv_bfloat16* AsH, __nv_bfloat16* AsL,
                                           __nv_bfloat16* BsH, __nv_bfloat16* BsL) {
    int s = 0, rem = g;
    #pragma unroll
    for (int i = 0; i < 2; i++)
        if (s < a.nseg - 1 && rem >= (a.seg[s].K >> 5)) { rem -= a.seg[s].K >> 5; s++; }
    const Seg2 sg = a.seg[s];
    const int k0 = rem << 5;
    #pragma unroll
    for (int i = 0; i < 2; i++) {
        int ch = stid + i * 128;
        int row = ch >> 2, c = (ch & 3) * 8;
        size_t off = (size_t)(bm + row) * sg.lda + k0 + c;
        cp16(AsH + row * PADA + c, sg.Ahi + off);
        cp16(AsL + row * PADA + c, sg.Alo + off);
    }
    #pragma unroll
    for (int i = 0; i < 2; i++) {
        int ch = stid + i * 128;
        int row = ch >> 3, c = (ch & 7) * 8;
        size_t off = (size_t)(k0 + row) * sg.ldb + bn + c;
        cp16(BsH + row * PADB + c, sg.Bhi + off);
        cp16(BsL + row * PADB + c, sg.Blo + off);
    }
}

__global__ void __launch_bounds__(256)
gemm_bf16s(GemmArgs3 args_in) {
    extern __shared__ __align__(16) char smem_raw[];
    __nv_bfloat16* base = (__nv_bfloat16*)smem_raw;

    GemmArgs3 args = args_in;
    if (args.zchunk > 0) {
        int z = blockIdx.z;
        args.seg[0].Ahi += (size_t)z * args.zchunk;
        args.seg[0].Alo += (size_t)z * args.zchunk;
        args.seg[0].Bhi += (size_t)z * args.zchunk * args.seg[0].ldb;
        args.seg[0].Blo += (size_t)z * args.zchunk * args.seg[0].ldb;
        args.seg[0].K = args.zchunk;
        args.D += (size_t)z * BB * args.ldd;
    }

    const int tid = threadIdx.x;
    const int lane = tid & 31;
    const int wid = tid >> 5;
    const int set = wid >> 2;
    const int swid = wid & 3;
    const int stid = tid & 127;
    const int wm = swid & 1;
    const int wn = swid >> 1;
    const int bm = blockIdx.y * 64;
    const int bn = blockIdx.x * 64;

    __nv_bfloat16* AsH = base + set * SET_H;
    __nv_bfloat16* AsL = AsH + A_SET_H;
    __nv_bfloat16* BsH = AsL + A_SET_H;
    __nv_bfloat16* BsL = BsH + B_SET_H;
    float* red = (float*)(base + SET_H);
    float* gsm = (float*)base;      // gate staging (cell epilogue), 64x64 f32

    int ntile = 0;
    #pragma unroll
    for (int s = 0; s < 3; s++) if (s < args.nseg) ntile += args.seg[s].K >> 5;
    const int cnt = (ntile - set + 1) >> 1;

    float acc[2][4][4];
    #pragma unroll
    for (int i = 0; i < 2; i++)
        #pragma unroll
        for (int j = 0; j < 4; j++)
            #pragma unroll
            for (int k = 0; k < 4; k++) acc[i][j][k] = 0.0f;

    const int a_r = lane & 15;
    const int a_c = (lane >> 4) << 3;
    const int b_r = (lane & 7) + ((lane >> 3) & 1) * 8;
    const int b_c = (lane >> 4) << 3;

    if (cnt > 0)
        stage_tile(args, set, bm, bn, stid, AsH, AsL, BsH, BsL);
    asm volatile("cp.async.commit_group;");
    if (cnt > 1)
        stage_tile(args, 2 + set, bm, bn, stid,
                   AsH + 64 * PADA, AsL + 64 * PADA, BsH + 32 * PADB, BsL + 32 * PADB);
    asm volatile("cp.async.commit_group;");

    for (int j = 0; j < cnt; j++) {
        asm volatile("cp.async.wait_group 1;");
        bar_set(set);
        {
            int p = (j + 2) % 3;
            if (j + 2 < cnt)
                stage_tile(args, 2 * (j + 2) + set, bm, bn, stid,
                           AsH + p * 64 * PADA, AsL + p * 64 * PADA,
                           BsH + p * 32 * PADB, BsL + p * 32 * PADB);
            asm volatile("cp.async.commit_group;");
        }
        const int q = j % 3;
        const __nv_bfloat16* cAH = AsH + q * 64 * PADA;
        const __nv_bfloat16* cAL = AsL + q * 64 * PADA;
        const __nv_bfloat16* cBH = BsH + q * 32 * PADB;
        const __nv_bfloat16* cBL = BsL + q * 32 * PADB;
        #pragma unroll
        for (int kk = 0; kk < 32; kk += 16) {
            uint32_t ah[2][4], al[2][4];
            #pragma unroll
            for (int mt = 0; mt < 2; mt++) {
                int rowoff = (wm * 32 + mt * 16 + a_r) * PADA + kk + a_c;
                ldsm_x4(smem_u32(&cAH[rowoff]), ah[mt]);
                ldsm_x4(smem_u32(&cAL[rowoff]), al[mt]);
            }
            uint32_t bh[4][2], bl[4][2];
            #pragma unroll
            for (int gi = 0; gi < 2; gi++) {
                int boff = (kk + b_r) * PADB + wn * 32 + gi * 16 + b_c;
                ldsm_x4_t(smem_u32(&cBH[boff]),
                          bh[gi * 2][0], bh[gi * 2][1], bh[gi * 2 + 1][0], bh[gi * 2 + 1][1]);
                ldsm_x4_t(smem_u32(&cBL[boff]),
                          bl[gi * 2][0], bl[gi * 2][1], bl[gi * 2 + 1][0], bl[gi * 2 + 1][1]);
            }
            #pragma unroll
            for (int mt = 0; mt < 2; mt++)
                #pragma unroll
                for (int nt = 0; nt < 4; nt++) {
                    mma16816(acc[mt][nt], ah[mt], bh[nt]);
                    mma16816(acc[mt][nt], al[mt], bh[nt]);
                    mma16816(acc[mt][nt], ah[mt], bl[nt]);
                }
        }
    }

    asm volatile("cp.async.wait_group 0;");
    __syncthreads();

    // merge set-1 partials
    if (set == 1) {
        float* r = red + swid * 1024 + lane * 32;
        #pragma unroll
        for (int mt = 0; mt < 2; mt++)
            #pragma unroll
            for (int nt = 0; nt < 4; nt++)
                #pragma unroll
                for (int k = 0; k < 4; k++)
                    r[mt * 16 + nt * 4 + k] = acc[mt][nt][k];
    }
    __syncthreads();

    const bool is_cell = (args.mode == 2) || (args.mode == 3 && bn < args.ncell);

    if (!is_cell) {
        if (set == 0) {
            const float* r = red + swid * 1024 + lane * 32;
            const int do_tanh = (args.mode == 1) || (args.mode == 3);
            float* D = (args.mode == 3) ? args.D2 : args.D;
            const int ldd = (args.mode == 3) ? args.ldd2 : args.ldd;
            const int csub = (args.mode == 3) ? args.ncell : 0;
            #pragma unroll
            for (int mt = 0; mt < 2; mt++) {
                int r0 = bm + wm * 32 + mt * 16 + (lane >> 2);
                #pragma unroll
                for (int nt = 0; nt < 4; nt++) {
                    int c0 = bn + wn * 32 + nt * 8 + (lane & 3) * 2;
                    float bia0 = 0.0f, bia1 = 0.0f;
                    if (args.bias) { bia0 = args.bias[c0]; bia1 = args.bias[c0 + 1]; }
                    float v00 = acc[mt][nt][0] + r[mt * 16 + nt * 4 + 0] + bia0;
                    float v01 = acc[mt][nt][1] + r[mt * 16 + nt * 4 + 1] + bia1;
                    float v10 = acc[mt][nt][2] + r[mt * 16 + nt * 4 + 2] + bia0;
                    float v11 = acc[mt][nt][3] + r[mt * 16 + nt * 4 + 3] + bia1;
                    if (do_tanh) {
                        v00 = fast_tanh(v00); v01 = fast_tanh(v01);
                        v10 = fast_tanh(v10); v11 = fast_tanh(v11);
                    }
                    int cc = c0 - csub;
                    D[(size_t)r0 * ldd + cc] = v00;
                    D[(size_t)r0 * ldd + cc + 1] = v01;
                    D[(size_t)(r0 + 8) * ldd + cc] = v10;
                    D[(size_t)(r0 + 8) * ldd + cc + 1] = v11;
                }
            }
        }
    } else {
        // cell epilogue: stage gates (acc+bias) to smem, then all threads do LSTM cell
        if (set == 0) {
            const float* r = red + swid * 1024 + lane * 32;
            #pragma unroll
            for (int mt = 0; mt < 2; mt++) {
                int lr = wm * 32 + mt * 16 + (lane >> 2);
                #pragma unroll
                for (int nt = 0; nt < 4; nt++) {
                    int lc = wn * 32 + nt * 8 + (lane & 3) * 2;
                    float bia0 = args.bias[bn + lc];
                    float bia1 = args.bias[bn + lc + 1];
                    gsm[lr * 64 + lc]            = acc[mt][nt][0] + r[mt * 16 + nt * 4 + 0] + bia0;
                    gsm[lr * 64 + lc + 1]        = acc[mt][nt][1] + r[mt * 16 + nt * 4 + 1] + bia1;
                    gsm[(lr + 8) * 64 + lc]      = acc[mt][nt][2] + r[mt * 16 + nt * 4 + 2] + bia0;
                    gsm[(lr + 8) * 64 + lc + 1]  = acc[mt][nt][3] + r[mt * 16 + nt * 4 + 3] + bia1;
                }
            }
        }
        __syncthreads();
        #pragma unroll
        for (int it = 0; it < 4; it++) {
            int idx = tid + it * 256;       // 0..1023
            int row = idx >> 4;             // 0..63
            int u = idx & 15;               // 0..15
            float4 gq = *reinterpret_cast<float4*>(&gsm[row * 64 + u * 4]);  // i,f,g,o
            int gr = bm + row;
            int ju = (bn >> 2) + u;
            size_t hix = (size_t)gr * HD + ju;
            float cn = fast_sigm(gq.y) * args.cellC[hix] + fast_sigm(gq.x) * fast_tanh(gq.z);
            float hn = fast_sigm(gq.w) * fast_tanh(cn);
            args.cellC[hix] = cn;
            __nv_bfloat16 hh = __float2bfloat16_rn(hn);
            args.cellHhi[hix] = hh;
            args.cellHlo[hix] = __float2bfloat16_rn(hn - __bfloat162float(hh));
        }
    }
}

// ---------------- fused attention: q-reduce + scores + softmax + context ----------------
__global__ void __launch_bounds__(512)
attn_fused(const float* __restrict__ enc,
           const float* __restrict__ corr_w,
           const float* __restrict__ corr_b,
           const int* __restrict__ mask,
           const float* __restrict__ dhp_b) {
    const int b = blockIdx.x;
    const int tid = threadIdx.x;
    const int lane = tid & 31;
    const int warp = tid >> 5;

    __shared__ float sm_q[AP];
    __shared__ float sm_e[LL];
    __shared__ float sm_a[LL];

    // reduce split-K q partials + bias
    for (int i = tid; i < AP; i += 512) {
        float s = dhp_b[i];
        #pragma unroll
        for (int z = 0; z < QSPLIT; z++)
            s += g_qpart[(size_t)z * BB * AP + b * AP + i];
        sm_q[i] = s;
    }
    __syncthreads();

    for (int l = warp; l < LL; l += 16) {
        const float* ep = g_enc_proj + ((size_t)b * LL + l) * AP;
        float s = 0.0f;
        #pragma unroll 4
        for (int ap = lane; ap < AP; ap += 32)
            s += fast_tanh(ep[ap] + sm_q[ap]) * corr_w[ap];
        #pragma unroll
        for (int o = 16; o; o >>= 1) s += __shfl_down_sync(0xffffffffu, s, o);
        if (lane == 0) {
            float v = s + corr_b[0];
            if (mask[b * LL + l] != 0) v = -INFINITY;
            sm_e[l] = v;
        }
    }
    __syncthreads();

    if (warp == 0) {
        float m = -INFINITY;
        #pragma unroll
        for (int i = lane; i < LL; i += 32) m = fmaxf(m, sm_e[i]);
        #pragma unroll
        for (int o = 16; o; o >>= 1) m = fmaxf(m, __shfl_xor_sync(0xffffffffu, m, o));
        float sum = 0.0f;
        #pragma unroll
        for (int i = lane; i < LL; i += 32) sum += __expf(sm_e[i] - m);
        #pragma unroll
        for (int o = 16; o; o >>= 1) sum += __shfl_xor_sync(0xffffffffu, sum, o);
        float inv = __fdividef(1.0f, sum);
        #pragma unroll
        for (int i = lane; i < LL; i += 32) sm_a[i] = __expf(sm_e[i] - m) * inv;
    }
    __syncthreads();

    #pragma unroll
    for (int rep = 0; rep < 2; rep++) {
        int h = tid + rep * 512;
        const float* eb = enc + (size_t)b * LL * HE + h;
        float acc = 0.0f;
        #pragma unroll 8
        for (int l = 0; l < LL; l++)
            acc = fmaf(sm_a[l], eb[(size_t)l * HE], acc);
        __nv_bfloat16 hi = __float2bfloat16_rn(acc);
        g_athi[b * HE + h] = hi;
        g_atlo[b * HE + h] = __float2bfloat16_rn(acc - __bfloat162float(hi));
    }
}

// ---------------- launch ----------------
extern "C" void kernel_launch(void* const* d_in, const int* in_sizes, int n_in,
                              void* d_out, int out_size) {
    const float* enc      = (const float*)d_in[0];
    const int*   mask     = (const int*)  d_in[1];
    const float* h1_0     = (const float*)d_in[2];
    const float* c1_0     = (const float*)d_in[3];
    const float* h2_0     = (const float*)d_in[4];
    const float* c2_0     = (const float*)d_in[5];
    const float* captions = (const float*)d_in[6];
    const float* att_W    = (const float*)d_in[7];
    const float* att_b    = (const float*)d_in[8];
    const float* dhp_W    = (const float*)d_in[9];
    const float* dhp_b    = (const float*)d_in[10];
    const float* corr_w   = (const float*)d_in[11];
    const float* corr_b   = (const float*)d_in[12];
    const float* lt_W     = (const float*)d_in[13];
    const float* lt_b     = (const float*)d_in[14];
    const float* W_ih1    = (const float*)d_in[15];
    const float* W_hh1    = (const float*)d_in[16];
    const float* b_ih1    = (const float*)d_in[17];
    const float* b_hh1    = (const float*)d_in[18];
    const float* W_ih2    = (const float*)d_in[19];
    const float* W_hh2    = (const float*)d_in[20];
    const float* b_ih2    = (const float*)d_in[21];
    const float* b_hh2    = (const float*)d_in[22];
    float* out = (float*)d_out;

    cudaFuncSetAttribute(gemm_bf16s, cudaFuncAttributeMaxDynamicSharedMemorySize, SMEM_BYTES);

    float *p_encproj, *p_qpart, *p_c1, *p_c2, *p_b1p, *p_bmega;
    __nv_bfloat16 *p_whi, *p_wlo, *p_h1hi, *p_h1lo, *p_h2hi, *p_h2lo;
    __nv_bfloat16 *p_hp0hi, *p_hp0lo, *p_athi, *p_atlo, *p_caphi, *p_caplo, *p_enchi, *p_enclo;
    cudaGetSymbolAddress((void**)&p_encproj, g_enc_proj);
    cudaGetSymbolAddress((void**)&p_qpart, g_qpart);
    cudaGetSymbolAddress((void**)&p_c1,    g_c1);
    cudaGetSymbolAddress((void**)&p_c2,    g_c2);
    cudaGetSymbolAddress((void**)&p_b1p,   g_b1p);
    cudaGetSymbolAddress((void**)&p_bmega, g_bmega);
    cudaGetSymbolAddress((void**)&p_whi,   g_whi);
    cudaGetSymbolAddress((void**)&p_wlo,   g_wlo);
    cudaGetSymbolAddress((void**)&p_h1hi,  g_h1hi);
    cudaGetSymbolAddress((void**)&p_h1lo,  g_h1lo);
    cudaGetSymbolAddress((void**)&p_h2hi,  g_h2hi);
    cudaGetSymbolAddress((void**)&p_h2lo,  g_h2lo);
    cudaGetSymbolAddress((void**)&p_hp0hi, g_hp0hi);
    cudaGetSymbolAddress((void**)&p_hp0lo, g_hp0lo);
    cudaGetSymbolAddress((void**)&p_athi,  g_athi);
    cudaGetSymbolAddress((void**)&p_atlo,  g_atlo);
    cudaGetSymbolAddress((void**)&p_caphi, g_caphi);
    cudaGetSymbolAddress((void**)&p_caplo, g_caplo);
    cudaGetSymbolAddress((void**)&p_enchi, g_enchi);
    cudaGetSymbolAddress((void**)&p_enclo, g_enclo);

    // weight pool offsets
    const size_t o_attW = 0;
    const size_t o_dhpW = o_attW + (size_t)HE * AP;
    const size_t o_ih1  = o_dhpW + (size_t)HD * AP;                  // 1536 x 4096 permuted
    const size_t o_hh1  = o_ih1  + (size_t)(EE + HE) * G4;           // 1024 x 4096 permuted
    const size_t o_mega = o_hh1  + (size_t)HD * G4;                  // 2048 x 5120

    // ---- prep ----
    f32_split<<<(HE * AP + 255) / 256, 256>>>(att_W, p_whi + o_attW, p_wlo + o_attW, HE * AP);
    f32_split<<<(HD * AP + 255) / 256, 256>>>(dhp_W, p_whi + o_dhpW, p_wlo + o_dhpW, HD * AP);
    f32_split<<<(TT * BB * EE + 255) / 256, 256>>>(captions, p_caphi, p_caplo, TT * BB * EE);
    f32_split<<<(BB * LL * HE + 255) / 256, 256>>>(enc, p_enchi, p_enclo, BB * LL * HE);
    f32_split_perm<<<((EE + HE) * G4 + 255) / 256, 256>>>(W_ih1, p_whi + o_ih1, p_wlo + o_ih1,
                                                          EE + HE, G4);
    f32_split_perm<<<(HD * G4 + 255) / 256, 256>>>(W_hh1, p_whi + o_hh1, p_wlo + o_hh1, HD, G4);
    f32_split_perm<<<(HD * G4 + 255) / 256, 256>>>(W_ih2, p_whi + o_mega, p_wlo + o_mega,
                                                   HD, NMEGA);
    f32_split_perm<<<(HD * G4 + 255) / 256, 256>>>(W_hh2, p_whi + o_mega + (size_t)HD * NMEGA,
                                                   p_wlo + o_mega + (size_t)HD * NMEGA, HD, NMEGA);
    f32_split_ld<<<(HD * HD + 255) / 256, 256>>>(lt_W, p_whi + o_mega + G4,
                                                 p_wlo + o_mega + G4, HD, HD, HD, NMEGA);
    zero_block<<<(HD * HD + 255) / 256, 256>>>(p_whi + o_mega + (size_t)HD * NMEGA + G4,
                                               p_wlo + o_mega + (size_t)HD * NMEGA + G4,
                                               HD, HD, NMEGA);
    bias_prep<<<(G4 + 255) / 256, 256>>>(b_ih1, b_hh1, b_ih2, b_hh2, lt_b);
    init_state<<<(BB * HD + 255) / 256, 256>>>(h1_0, c1_0, h2_0, c2_0);

    // enc_proj = enc @ att_W + att_b
    {
        GemmArgs3 a = {};
        a.seg[0] = {p_enchi, p_enclo, HE, p_whi + o_attW, p_wlo + o_attW, AP, HE};
        a.nseg = 1; a.D = p_encproj; a.ldd = AP; a.bias = att_b; a.mode = 0; a.zchunk = 0;
        gemm_bf16s<<<dim3(AP / 64, (BB * LL) / 64), 256, SMEM_BYTES>>>(a);
    }

    for (int t = 0; t < TT; t++) {
        const __nv_bfloat16* hp_hi = (t == 0) ? p_hp0hi : p_h2hi;
        const __nv_bfloat16* hp_lo = (t == 0) ? p_hp0lo : p_h2lo;

        // q partials = h_prev @ dhp_W (split-K=8)
        {
            GemmArgs3 a = {};
            a.seg[0] = {hp_hi, hp_lo, HD, p_whi + o_dhpW, p_wlo + o_dhpW, AP, HD};
            a.nseg = 1; a.D = p_qpart; a.ldd = AP; a.bias = nullptr; a.mode = 0;
            a.zchunk = HD / QSPLIT;
            gemm_bf16s<<<dim3(AP / 64, BB / 64, QSPLIT), 256, SMEM_BYTES>>>(a);
        }

        attn_fused<<<BB, 512>>>(enc, corr_w, corr_b, mask, dhp_b);

        // gates1 + cell1 fused
        {
            GemmArgs3 a = {};
            a.seg[0] = {p_caphi + (size_t)t * BB * EE, p_caplo + (size_t)t * BB * EE, EE,
                        p_whi + o_ih1, p_wlo + o_ih1, G4, EE};
            a.seg[1] = {p_athi, p_atlo, HE,
                        p_whi + o_ih1 + (size_t)EE * G4, p_wlo + o_ih1 + (size_t)EE * G4, G4, HE};
            a.seg[2] = {p_h1hi, p_h1lo, HD, p_whi + o_hh1, p_wlo + o_hh1, G4, HD};
            a.nseg = 3; a.bias = p_b1p; a.mode = 2; a.zchunk = 0;
            a.cellC = p_c1; a.cellHhi = p_h1hi; a.cellHlo = p_h1lo;
            gemm_bf16s<<<dim3(G4 / 64, BB / 64), 256, SMEM_BYTES>>>(a);
        }

        // mega: gates2 + cell2 (cols < 4096) and out = tanh(h1@ltW+ltb) (cols >= 4096)
        {
            GemmArgs3 a = {};
            a.seg[0] = {p_h1hi, p_h1lo, HD, p_whi + o_mega, p_wlo + o_mega, NMEGA, HD};
            a.seg[1] = {p_h2hi, p_h2lo, HD,
                        p_whi + o_mega + (size_t)HD * NMEGA, p_wlo + o_mega + (size_t)HD * NMEGA,
                        NMEGA, HD};
            a.nseg = 2; a.bias = p_bmega; a.mode = 3; a.ncell = G4; a.zchunk = 0;
            a.cellC = p_c2; a.cellHhi = p_h2hi; a.cellHlo = p_h2lo;
            a.D2 = out + (size_t)t * BB * HD; a.ldd2 = HD;
            gemm_bf16s<<<dim3(NMEGA / 64, BB / 64), 256, SMEM_BYTES>>>(a);
        }
    }

    (void)in_sizes; (void)n_in; (void)out_size;
}

// round 7
// speedup vs baseline: 4.1384x; 1.0990x over previous
#include <cuda_runtime.h>
#include <cuda_bf16.h>
#include <math.h>
#include <stdint.h>

// Problem constants
#define BB 128   // batch
#define LL 128   // enc length
#define HE 1024  // enc hidden
#define HD 1024  // dec hidden
#define EE 512   // embed
#define AP 512   // attn proj
#define TT 64    // timesteps
#define G4 (4*HD)
#define NMEGA (G4 + HD)   // 5120
#define QSPLIT 4

// ---------------- device scratch ----------------
__device__ __nv_bfloat16 g_enc_projb[BB * LL * AP];   // bf16 enc_proj
__device__ float g_qpart[QSPLIT * BB * AP];
__device__ float g_c1[BB * HD];
__device__ float g_c2[BB * HD];
__device__ float g_b1p[G4];
__device__ float g_bmega[NMEGA];

__device__ __nv_bfloat16 g_h1hi[BB * HD], g_h1lo[BB * HD];
__device__ __nv_bfloat16 g_h2hi[BB * HD], g_h2lo[BB * HD];
__device__ __nv_bfloat16 g_hp0hi[BB * HD], g_hp0lo[BB * HD];
__device__ __nv_bfloat16 g_athi[BB * HE], g_atlo[BB * HE];
__device__ __nv_bfloat16 g_caphi[TT * BB * EE], g_caplo[TT * BB * EE];
__device__ __nv_bfloat16 g_enchi[BB * LL * HE], g_enclo[BB * LL * HE];

#define WPOOL 22020096
__device__ __nv_bfloat16 g_whi[WPOOL];
__device__ __nv_bfloat16 g_wlo[WPOOL];

__device__ __forceinline__ float fast_tanh(float x) {
    float e = __expf(2.0f * x);
    return 1.0f - __fdividef(2.0f, e + 1.0f);
}
__device__ __forceinline__ float fast_sigm(float x) {
    return __fdividef(1.0f, 1.0f + __expf(-x));
}

// ---------------- prep kernels ----------------
__global__ void init_state(const float* __restrict__ h1_0, const float* __restrict__ c1_0,
                           const float* __restrict__ h2_0, const float* __restrict__ c2_0) {
    int i = blockIdx.x * blockDim.x + threadIdx.x;
    if (i < BB * HD) {
        float h1 = h1_0[i], h2 = h2_0[i];
        __nv_bfloat16 a = __float2bfloat16_rn(h1);
        g_h1hi[i] = a; g_h1lo[i] = __float2bfloat16_rn(h1 - __bfloat162float(a));
        __nv_bfloat16 b = __float2bfloat16_rn(h2);
        g_h2hi[i] = b; g_h2lo[i] = __float2bfloat16_rn(h2 - __bfloat162float(b));
        g_c1[i] = c1_0[i];
        g_c2[i] = c2_0[i];
        g_hp0hi[i] = __float2bfloat16_rn(1.0f / (float)HE);
        g_hp0lo[i] = __float2bfloat16_rn(0.0f);
    }
}

// vectorized fp32 -> bf16 hi/lo split (n % 4 == 0)
__global__ void f32_split4(const float4* __restrict__ src,
                           __nv_bfloat162* __restrict__ hi,
                           __nv_bfloat162* __restrict__ lo, int n4) {
    int i = blockIdx.x * 256 + threadIdx.x;
    if (i < n4) {
        float4 v = src[i];
        __nv_bfloat16 h0 = __float2bfloat16_rn(v.x);
        __nv_bfloat16 h1 = __float2bfloat16_rn(v.y);
        __nv_bfloat16 h2 = __float2bfloat16_rn(v.z);
        __nv_bfloat16 h3 = __float2bfloat16_rn(v.w);
        hi[2 * i]     = __halves2bfloat162(h0, h1);
        hi[2 * i + 1] = __halves2bfloat162(h2, h3);
        lo[2 * i]     = __halves2bfloat162(
            __float2bfloat16_rn(v.x - __bfloat162float(h0)),
            __float2bfloat16_rn(v.y - __bfloat162float(h1)));
        lo[2 * i + 1] = __halves2bfloat162(
            __float2bfloat16_rn(v.z - __bfloat162float(h2)),
            __float2bfloat16_rn(v.w - __bfloat162float(h3)));
    }
}

// gate-permuting split: src [K x 4096] (gate-major cols), dst col' = 4*j+gate
__global__ void f32_split_perm(const float* __restrict__ src,
                               __nv_bfloat16* __restrict__ hi,
                               __nv_bfloat16* __restrict__ lo,
                               int K, int lddst) {
    int i = blockIdx.x * 256 + threadIdx.x;
    if (i < K * G4) {
        int row = i / G4, cd = i % G4;
        int j = cd >> 2, gate = cd & 3;
        float x = src[(size_t)row * G4 + gate * HD + j];
        __nv_bfloat16 h = __float2bfloat16_rn(x);
        size_t o = (size_t)row * lddst + cd;
        hi[o] = h;
        lo[o] = __float2bfloat16_rn(x - __bfloat162float(h));
    }
}

__global__ void f32_split_ld(const float* __restrict__ src,
                             __nv_bfloat16* __restrict__ hi,
                             __nv_bfloat16* __restrict__ lo,
                             int K, int N, int ldsrc, int lddst) {
    int i = blockIdx.x * 256 + threadIdx.x;
    if (i < K * N) {
        int row = i / N, c = i % N;
        float x = src[(size_t)row * ldsrc + c];
        __nv_bfloat16 h = __float2bfloat16_rn(x);
        size_t o = (size_t)row * lddst + c;
        hi[o] = h;
        lo[o] = __float2bfloat16_rn(x - __bfloat162float(h));
    }
}

__global__ void zero_block(__nv_bfloat16* __restrict__ hi,
                           __nv_bfloat16* __restrict__ lo,
                           int K, int N, int lddst) {
    int i = blockIdx.x * 256 + threadIdx.x;
    if (i < K * N) {
        int row = i / N, c = i % N;
        size_t o = (size_t)row * lddst + c;
        hi[o] = __float2bfloat16_rn(0.0f);
        lo[o] = __float2bfloat16_rn(0.0f);
    }
}

__global__ void bias_prep(const float* __restrict__ bi1, const float* __restrict__ bh1,
                          const float* __restrict__ bi2, const float* __restrict__ bh2,
                          const float* __restrict__ ltb) {
    int i = blockIdx.x * 256 + threadIdx.x;
    if (i < G4) {
        int j = i >> 2, gate = i & 3;
        g_b1p[i]   = bi1[gate * HD + j] + bh1[gate * HD + j];
        g_bmega[i] = bi2[gate * HD + j] + bh2[gate * HD + j];
    }
    if (i < HD) g_bmega[G4 + i] = ltb[i];
}

// ---------------- split-bf16 tensor-core GEMM with fused epilogues ----------------
struct Seg2 {
    const __nv_bfloat16* Ahi; const __nv_bfloat16* Alo; int lda;
    const __nv_bfloat16* Bhi; const __nv_bfloat16* Blo; int ldb;
    int K;
};
struct GemmArgs3 {
    Seg2 seg[3];
    int nseg;
    float* D; int ldd;
    const float* bias;
    int mode;                 // 0 plain f32, 2 cell, 3 mega, 4 plain bf16 (-> Db)
    float* cellC; __nv_bfloat16* cellHhi; __nv_bfloat16* cellHlo;
    int ncell;
    float* D2; int ldd2;
    __nv_bfloat16* Db;
    int zchunk;
};

#define PADA 40
#define PADB 72
#define STG 3
#define A_SET_H (STG * 64 * PADA)
#define B_SET_H (STG * 32 * PADB)
#define SET_H   (2 * A_SET_H + 2 * B_SET_H)
#define SMEM_BYTES (2 * SET_H * 2)

__device__ __forceinline__ uint32_t smem_u32(const void* p) {
    return (uint32_t)__cvta_generic_to_shared(p);
}
__device__ __forceinline__ void cp16(void* dst, const void* src) {
    asm volatile("cp.async.ca.shared.global [%0], [%1], 16;"
                 :: "r"(smem_u32(dst)), "l"(src));
}
__device__ __forceinline__ void ldsm_x4(uint32_t addr, uint32_t* r) {
    asm volatile("ldmatrix.sync.aligned.m8n8.x4.shared.b16 {%0,%1,%2,%3}, [%4];"
                 : "=r"(r[0]), "=r"(r[1]), "=r"(r[2]), "=r"(r[3]) : "r"(addr));
}
__device__ __forceinline__ void ldsm_x4_t(uint32_t addr, uint32_t& r0, uint32_t& r1,
                                          uint32_t& r2, uint32_t& r3) {
    asm volatile("ldmatrix.sync.aligned.m8n8.x4.trans.shared.b16 {%0,%1,%2,%3}, [%4];"
                 : "=r"(r0), "=r"(r1), "=r"(r2), "=r"(r3) : "r"(addr));
}
__device__ __forceinline__ void mma16816(float* c, const uint32_t* a, const uint32_t* b) {
    asm volatile(
        "mma.sync.aligned.m16n8k16.row.col.f32.bf16.bf16.f32 "
        "{%0,%1,%2,%3}, {%4,%5,%6,%7}, {%8,%9}, {%0,%1,%2,%3};"
        : "+f"(c[0]), "+f"(c[1]), "+f"(c[2]), "+f"(c[3])
        : "r"(a[0]), "r"(a[1]), "r"(a[2]), "r"(a[3]), "r"(b[0]), "r"(b[1]));
}
__device__ __forceinline__ void bar_set(int set) {
    asm volatile("bar.sync %0, 128;" :: "r"(set + 1) : "memory");
}

__device__ __forceinline__ void stage_tile(const GemmArgs3& a, int g, int bm, int bn, int stid,
                                           __nv_bfloat16* AsH, __nv_bfloat16* AsL,
                                           __nv_bfloat16* BsH, __nv_bfloat16* BsL) {
    int s = 0, rem = g;
    #pragma unroll
    for (int i = 0; i < 2; i++)
        if (s < a.nseg - 1 && rem >= (a.seg[s].K >> 5)) { rem -= a.seg[s].K >> 5; s++; }
    const Seg2 sg = a.seg[s];
    const int k0 = rem << 5;
    #pragma unroll
    for (int i = 0; i < 2; i++) {
        int ch = stid + i * 128;
        int row = ch >> 2, c = (ch & 3) * 8;
        size_t off = (size_t)(bm + row) * sg.lda + k0 + c;
        cp16(AsH + row * PADA + c, sg.Ahi + off);
        cp16(AsL + row * PADA + c, sg.Alo + off);
    }
    #pragma unroll
    for (int i = 0; i < 2; i++) {
        int ch = stid + i * 128;
        int row = ch >> 3, c = (ch & 7) * 8;
        size_t off = (size_t)(k0 + row) * sg.ldb + bn + c;
        cp16(BsH + row * PADB + c, sg.Bhi + off);
        cp16(BsL + row * PADB + c, sg.Blo + off);
    }
}

__global__ void __launch_bounds__(256)
gemm_bf16s(GemmArgs3 args_in) {
    extern __shared__ __align__(16) char smem_raw[];
    __nv_bfloat16* base = (__nv_bfloat16*)smem_raw;

    GemmArgs3 args = args_in;
    if (args.zchunk > 0) {
        int z = blockIdx.z;
        args.seg[0].Ahi += (size_t)z * args.zchunk;
        args.seg[0].Alo += (size_t)z * args.zchunk;
        args.seg[0].Bhi += (size_t)z * args.zchunk * args.seg[0].ldb;
        args.seg[0].Blo += (size_t)z * args.zchunk * args.seg[0].ldb;
        args.seg[0].K = args.zchunk;
        args.D += (size_t)z * BB * args.ldd;
    }

    const int tid = threadIdx.x;
    const int lane = tid & 31;
    const int wid = tid >> 5;
    const int set = wid >> 2;
    const int swid = wid & 3;
    const int stid = tid & 127;
    const int wm = swid & 1;
    const int wn = swid >> 1;
    const int bm = blockIdx.y * 64;
    const int bn = blockIdx.x * 64;

    __nv_bfloat16* AsH = base + set * SET_H;
    __nv_bfloat16* AsL = AsH + A_SET_H;
    __nv_bfloat16* BsH = AsL + A_SET_H;
    __nv_bfloat16* BsL = BsH + B_SET_H;
    float* red = (float*)(base + SET_H);
    float* gsm = (float*)base;

    int ntile = 0;
    #pragma unroll
    for (int s = 0; s < 3; s++) if (s < args.nseg) ntile += args.seg[s].K >> 5;
    const int cnt = (ntile - set + 1) >> 1;

    float acc[2][4][4];
    #pragma unroll
    for (int i = 0; i < 2; i++)
        #pragma unroll
        for (int j = 0; j < 4; j++)
            #pragma unroll
            for (int k = 0; k < 4; k++) acc[i][j][k] = 0.0f;

    const int a_r = lane & 15;
    const int a_c = (lane >> 4) << 3;
    const int b_r = (lane & 7) + ((lane >> 3) & 1) * 8;
    const int b_c = (lane >> 4) << 3;

    if (cnt > 0)
        stage_tile(args, set, bm, bn, stid, AsH, AsL, BsH, BsL);
    asm volatile("cp.async.commit_group;");
    if (cnt > 1)
        stage_tile(args, 2 + set, bm, bn, stid,
                   AsH + 64 * PADA, AsL + 64 * PADA, BsH + 32 * PADB, BsL + 32 * PADB);
    asm volatile("cp.async.commit_group;");

    for (int j = 0; j < cnt; j++) {
        asm volatile("cp.async.wait_group 1;");
        bar_set(set);
        {
            int p = (j + 2) % 3;
            if (j + 2 < cnt)
                stage_tile(args, 2 * (j + 2) + set, bm, bn, stid,
                           AsH + p * 64 * PADA, AsL + p * 64 * PADA,
                           BsH + p * 32 * PADB, BsL + p * 32 * PADB);
            asm volatile("cp.async.commit_group;");
        }
        const int q = j % 3;
        const __nv_bfloat16* cAH = AsH + q * 64 * PADA;
        const __nv_bfloat16* cAL = AsL + q * 64 * PADA;
        const __nv_bfloat16* cBH = BsH + q * 32 * PADB;
        const __nv_bfloat16* cBL = BsL + q * 32 * PADB;
        #pragma unroll
        for (int kk = 0; kk < 32; kk += 16) {
            uint32_t ah[2][4], al[2][4];
            #pragma unroll
            for (int mt = 0; mt < 2; mt++) {
                int rowoff = (wm * 32 + mt * 16 + a_r) * PADA + kk + a_c;
                ldsm_x4(smem_u32(&cAH[rowoff]), ah[mt]);
                ldsm_x4(smem_u32(&cAL[rowoff]), al[mt]);
            }
            uint32_t bh[4][2], bl[4][2];
            #pragma unroll
            for (int gi = 0; gi < 2; gi++) {
                int boff = (kk + b_r) * PADB + wn * 32 + gi * 16 + b_c;
                ldsm_x4_t(smem_u32(&cBH[boff]),
                          bh[gi * 2][0], bh[gi * 2][1], bh[gi * 2 + 1][0], bh[gi * 2 + 1][1]);
                ldsm_x4_t(smem_u32(&cBL[boff]),
                          bl[gi * 2][0], bl[gi * 2][1], bl[gi * 2 + 1][0], bl[gi * 2 + 1][1]);
            }
            #pragma unroll
            for (int mt = 0; mt < 2; mt++)
                #pragma unroll
                for (int nt = 0; nt < 4; nt++) {
                    mma16816(acc[mt][nt], ah[mt], bh[nt]);
                    mma16816(acc[mt][nt], al[mt], bh[nt]);
                    mma16816(acc[mt][nt], ah[mt], bl[nt]);
                }
        }
    }

    asm volatile("cp.async.wait_group 0;");
    __syncthreads();

    if (set == 1) {
        float* r = red + swid * 1024 + lane * 32;
        #pragma unroll
        for (int mt = 0; mt < 2; mt++)
            #pragma unroll
            for (int nt = 0; nt < 4; nt++)
                #pragma unroll
                for (int k = 0; k < 4; k++)
                    r[mt * 16 + nt * 4 + k] = acc[mt][nt][k];
    }
    __syncthreads();

    const bool is_cell = (args.mode == 2) || (args.mode == 3 && bn < args.ncell);

    if (!is_cell) {
        if (set == 0) {
            const float* r = red + swid * 1024 + lane * 32;
            const int do_tanh = (args.mode == 3);
            float* D = (args.mode == 3) ? args.D2 : args.D;
            const int ldd = (args.mode == 3) ? args.ldd2 : args.ldd;
            const int csub = (args.mode == 3) ? args.ncell : 0;
            #pragma unroll
            for (int mt = 0; mt < 2; mt++) {
                int r0 = bm + wm * 32 + mt * 16 + (lane >> 2);
                #pragma unroll
                for (int nt = 0; nt < 4; nt++) {
                    int c0 = bn + wn * 32 + nt * 8 + (lane & 3) * 2;
                    float bia0 = 0.0f, bia1 = 0.0f;
                    if (args.bias) { bia0 = args.bias[c0]; bia1 = args.bias[c0 + 1]; }
                    float v00 = acc[mt][nt][0] + r[mt * 16 + nt * 4 + 0] + bia0;
                    float v01 = acc[mt][nt][1] + r[mt * 16 + nt * 4 + 1] + bia1;
                    float v10 = acc[mt][nt][2] + r[mt * 16 + nt * 4 + 2] + bia0;
                    float v11 = acc[mt][nt][3] + r[mt * 16 + nt * 4 + 3] + bia1;
                    if (do_tanh) {
                        v00 = fast_tanh(v00); v01 = fast_tanh(v01);
                        v10 = fast_tanh(v10); v11 = fast_tanh(v11);
                    }
                    if (args.mode == 4) {
                        *reinterpret_cast<__nv_bfloat162*>(
                            args.Db + (size_t)r0 * args.ldd + c0) =
                            __halves2bfloat162(__float2bfloat16_rn(v00), __float2bfloat16_rn(v01));
                        *reinterpret_cast<__nv_bfloat162*>(
                            args.Db + (size_t)(r0 + 8) * args.ldd + c0) =
                            __halves2bfloat162(__float2bfloat16_rn(v10), __float2bfloat16_rn(v11));
                    } else {
                        int cc = c0 - csub;
                        D[(size_t)r0 * ldd + cc] = v00;
                        D[(size_t)r0 * ldd + cc + 1] = v01;
                        D[(size_t)(r0 + 8) * ldd + cc] = v10;
                        D[(size_t)(r0 + 8) * ldd + cc + 1] = v11;
                    }
                }
            }
        }
    } else {
        if (set == 0) {
            const float* r = red + swid * 1024 + lane * 32;
            #pragma unroll
            for (int mt = 0; mt < 2; mt++) {
                int lr = wm * 32 + mt * 16 + (lane >> 2);
                #pragma unroll
                for (int nt = 0; nt < 4; nt++) {
                    int lc = wn * 32 + nt * 8 + (lane & 3) * 2;
                    float bia0 = args.bias[bn + lc];
                    float bia1 = args.bias[bn + lc + 1];
                    gsm[lr * 64 + lc]            = acc[mt][nt][0] + r[mt * 16 + nt * 4 + 0] + bia0;
                    gsm[lr * 64 + lc + 1]        = acc[mt][nt][1] + r[mt * 16 + nt * 4 + 1] + bia1;
                    gsm[(lr + 8) * 64 + lc]      = acc[mt][nt][2] + r[mt * 16 + nt * 4 + 2] + bia0;
                    gsm[(lr + 8) * 64 + lc + 1]  = acc[mt][nt][3] + r[mt * 16 + nt * 4 + 3] + bia1;
                }
            }
        }
        __syncthreads();
        #pragma unroll
        for (int it = 0; it < 4; it++) {
            int idx = tid + it * 256;
            int row = idx >> 4;
            int u = idx & 15;
            float4 gq = *reinterpret_cast<float4*>(&gsm[row * 64 + u * 4]);  // i,f,g,o
            int gr = bm + row;
            int ju = (bn >> 2) + u;
            size_t hix = (size_t)gr * HD + ju;
            float cn = fast_sigm(gq.y) * args.cellC[hix] + fast_sigm(gq.x) * fast_tanh(gq.z);
            float hn = fast_sigm(gq.w) * fast_tanh(cn);
            args.cellC[hix] = cn;
            __nv_bfloat16 hh = __float2bfloat16_rn(hn);
            args.cellHhi[hix] = hh;
            args.cellHlo[hix] = __float2bfloat16_rn(hn - __bfloat162float(hh));
        }
    }
}

// ---------------- fused attention: q-reduce + scores + softmax + context ----------------
__global__ void __launch_bounds__(512)
attn_fused(const float* __restrict__ corr_w,
           const float* __restrict__ corr_b,
           const int* __restrict__ mask,
           const float* __restrict__ dhp_b) {
    const int b = blockIdx.x;
    const int tid = threadIdx.x;
    const int lane = tid & 31;
    const int warp = tid >> 5;

    __shared__ float sm_q[AP];
    __shared__ float sm_e[LL];
    __shared__ float sm_a[LL];

    for (int i = tid; i < AP; i += 512) {
        float s = dhp_b[i];
        #pragma unroll
        for (int z = 0; z < QSPLIT; z++)
            s += g_qpart[(size_t)z * BB * AP + b * AP + i];
        sm_q[i] = s;
    }
    __syncthreads();

    for (int l = warp; l < LL; l += 16) {
        const __nv_bfloat16* ep = g_enc_projb + ((size_t)b * LL + l) * AP;
        float s = 0.0f;
        #pragma unroll
        for (int k = 0; k < 8; k++) {
            int ap = lane * 2 + k * 64;
            __nv_bfloat162 v = *reinterpret_cast<const __nv_bfloat162*>(ep + ap);
            s += fast_tanh(__low2float(v) + sm_q[ap]) * corr_w[ap];
            s += fast_tanh(__high2float(v) + sm_q[ap + 1]) * corr_w[ap + 1];
        }
        #pragma unroll
        for (int o = 16; o; o >>= 1) s += __shfl_down_sync(0xffffffffu, s, o);
        if (lane == 0) {
            float v = s + corr_b[0];
            if (mask[b * LL + l] != 0) v = -INFINITY;
            sm_e[l] = v;
        }
    }
    __syncthreads();

    if (warp == 0) {
        float m = -INFINITY;
        #pragma unroll
        for (int i = lane; i < LL; i += 32) m = fmaxf(m, sm_e[i]);
        #pragma unroll
        for (int o = 16; o; o >>= 1) m = fmaxf(m, __shfl_xor_sync(0xffffffffu, m, o));
        float sum = 0.0f;
        #pragma unroll
        for (int i = lane; i < LL; i += 32) sum += __expf(sm_e[i] - m);
        #pragma unroll
        for (int o = 16; o; o >>= 1) sum += __shfl_xor_sync(0xffffffffu, sum, o);
        float inv = __fdividef(1.0f, sum);
        #pragma unroll
        for (int i = lane; i < LL; i += 32) sm_a[i] = __expf(sm_e[i] - m) * inv;
    }
    __syncthreads();

    // context from bf16 enc: thread handles columns h0, h0+1
    {
        int h0 = tid * 2;
        const __nv_bfloat16* eb = g_enchi + (size_t)b * LL * HE + h0;
        float a0 = 0.0f, a1 = 0.0f;
        #pragma unroll 8
        for (int l = 0; l < LL; l++) {
            __nv_bfloat162 v = *reinterpret_cast<const __nv_bfloat162*>(eb + (size_t)l * HE);
            float al = sm_a[l];
            a0 = fmaf(al, __low2float(v), a0);
            a1 = fmaf(al, __high2float(v), a1);
        }
        __nv_bfloat16 hb0 = __float2bfloat16_rn(a0);
        __nv_bfloat16 hb1 = __float2bfloat16_rn(a1);
        *reinterpret_cast<__nv_bfloat162*>(g_athi + (size_t)b * HE + h0) =
            __halves2bfloat162(hb0, hb1);
        *reinterpret_cast<__nv_bfloat162*>(g_atlo + (size_t)b * HE + h0) =
            __halves2bfloat162(__float2bfloat16_rn(a0 - __bfloat162float(hb0)),
                               __float2bfloat16_rn(a1 - __bfloat162float(hb1)));
    }
}

// ---------------- launch ----------------
extern "C" void kernel_launch(void* const* d_in, const int* in_sizes, int n_in,
                              void* d_out, int out_size) {
    const float* enc      = (const float*)d_in[0];
    const int*   mask     = (const int*)  d_in[1];
    const float* h1_0     = (const float*)d_in[2];
    const float* c1_0     = (const float*)d_in[3];
    const float* h2_0     = (const float*)d_in[4];
    const float* c2_0     = (const float*)d_in[5];
    const float* captions = (const float*)d_in[6];
    const float* att_W    = (const float*)d_in[7];
    const float* att_b    = (const float*)d_in[8];
    const float* dhp_W    = (const float*)d_in[9];
    const float* dhp_b    = (const float*)d_in[10];
    const float* corr_w   = (const float*)d_in[11];
    const float* corr_b   = (const float*)d_in[12];
    const float* lt_W     = (const float*)d_in[13];
    const float* lt_b     = (const float*)d_in[14];
    const float* W_ih1    = (const float*)d_in[15];
    const float* W_hh1    = (const float*)d_in[16];
    const float* b_ih1    = (const float*)d_in[17];
    const float* b_hh1    = (const float*)d_in[18];
    const float* W_ih2    = (const float*)d_in[19];
    const float* W_hh2    = (const float*)d_in[20];
    const float* b_ih2    = (const float*)d_in[21];
    const float* b_hh2    = (const float*)d_in[22];
    float* out = (float*)d_out;

    cudaFuncSetAttribute(gemm_bf16s, cudaFuncAttributeMaxDynamicSharedMemorySize, SMEM_BYTES);

    float *p_qpart, *p_c1, *p_c2, *p_b1p, *p_bmega;
    __nv_bfloat16 *p_encprojb, *p_whi, *p_wlo, *p_h1hi, *p_h1lo, *p_h2hi, *p_h2lo;
    __nv_bfloat16 *p_hp0hi, *p_hp0lo, *p_athi, *p_atlo, *p_caphi, *p_caplo, *p_enchi, *p_enclo;
    cudaGetSymbolAddress((void**)&p_encprojb, g_enc_projb);
    cudaGetSymbolAddress((void**)&p_qpart, g_qpart);
    cudaGetSymbolAddress((void**)&p_c1,    g_c1);
    cudaGetSymbolAddress((void**)&p_c2,    g_c2);
    cudaGetSymbolAddress((void**)&p_b1p,   g_b1p);
    cudaGetSymbolAddress((void**)&p_bmega, g_bmega);
    cudaGetSymbolAddress((void**)&p_whi,   g_whi);
    cudaGetSymbolAddress((void**)&p_wlo,   g_wlo);
    cudaGetSymbolAddress((void**)&p_h1hi,  g_h1hi);
    cudaGetSymbolAddress((void**)&p_h1lo,  g_h1lo);
    cudaGetSymbolAddress((void**)&p_h2hi,  g_h2hi);
    cudaGetSymbolAddress((void**)&p_h2lo,  g_h2lo);
    cudaGetSymbolAddress((void**)&p_hp0hi, g_hp0hi);
    cudaGetSymbolAddress((void**)&p_hp0lo, g_hp0lo);
    cudaGetSymbolAddress((void**)&p_athi,  g_athi);
    cudaGetSymbolAddress((void**)&p_atlo,  g_atlo);
    cudaGetSymbolAddress((void**)&p_caphi, g_caphi);
    cudaGetSymbolAddress((void**)&p_caplo, g_caplo);
    cudaGetSymbolAddress((void**)&p_enchi, g_enchi);
    cudaGetSymbolAddress((void**)&p_enclo, g_enclo);

    const size_t o_attW = 0;
    const size_t o_dhpW = o_attW + (size_t)HE * AP;
    const size_t o_ih1  = o_dhpW + (size_t)HD * AP;
    const size_t o_hh1  = o_ih1  + (size_t)(EE + HE) * G4;
    const size_t o_mega = o_hh1  + (size_t)HD * G4;

    // ---- prep ----
    f32_split4<<<(HE * AP / 4 + 255) / 256, 256>>>(
        (const float4*)att_W, (__nv_bfloat162*)(p_whi + o_attW),
        (__nv_bfloat162*)(p_wlo + o_attW), HE * AP / 4);
    f32_split4<<<(HD * AP / 4 + 255) / 256, 256>>>(
        (const float4*)dhp_W, (__nv_bfloat162*)(p_whi + o_dhpW),
        (__nv_bfloat162*)(p_wlo + o_dhpW), HD * AP / 4);
    f32_split4<<<(TT * BB * EE / 4 + 255) / 256, 256>>>(
        (const float4*)captions, (__nv_bfloat162*)p_caphi,
        (__nv_bfloat162*)p_caplo, TT * BB * EE / 4);
    f32_split4<<<(BB * LL * HE / 4 + 255) / 256, 256>>>(
        (const float4*)enc, (__nv_bfloat162*)p_enchi,
        (__nv_bfloat162*)p_enclo, BB * LL * HE / 4);
    f32_split_perm<<<((EE + HE) * G4 + 255) / 256, 256>>>(W_ih1, p_whi + o_ih1, p_wlo + o_ih1,
                                                          EE + HE, G4);
    f32_split_perm<<<(HD * G4 + 255) / 256, 256>>>(W_hh1, p_whi + o_hh1, p_wlo + o_hh1, HD, G4);
    f32_split_perm<<<(HD * G4 + 255) / 256, 256>>>(W_ih2, p_whi + o_mega, p_wlo + o_mega,
                                                   HD, NMEGA);
    f32_split_perm<<<(HD * G4 + 255) / 256, 256>>>(W_hh2, p_whi + o_mega + (size_t)HD * NMEGA,
                                                   p_wlo + o_mega + (size_t)HD * NMEGA, HD, NMEGA);
    f32_split_ld<<<(HD * HD + 255) / 256, 256>>>(lt_W, p_whi + o_mega + G4,
                                                 p_wlo + o_mega + G4, HD, HD, HD, NMEGA);
    zero_block<<<(HD * HD + 255) / 256, 256>>>(p_whi + o_mega + (size_t)HD * NMEGA + G4,
                                               p_wlo + o_mega + (size_t)HD * NMEGA + G4,
                                               HD, HD, NMEGA);
    bias_prep<<<(G4 + 255) / 256, 256>>>(b_ih1, b_hh1, b_ih2, b_hh2, lt_b);
    init_state<<<(BB * HD + 255) / 256, 256>>>(h1_0, c1_0, h2_0, c2_0);

    // enc_proj = enc @ att_W + att_b (stored bf16)
    {
        GemmArgs3 a = {};
        a.seg[0] = {p_enchi, p_enclo, HE, p_whi + o_attW, p_wlo + o_attW, AP, HE};
        a.nseg = 1; a.ldd = AP; a.bias = att_b; a.mode = 4; a.Db = p_encprojb; a.zchunk = 0;
        gemm_bf16s<<<dim3(AP / 64, (BB * LL) / 64), 256, SMEM_BYTES>>>(a);
    }

    for (int t = 0; t < TT; t++) {
        const __nv_bfloat16* hp_hi = (t == 0) ? p_hp0hi : p_h2hi;
        const __nv_bfloat16* hp_lo = (t == 0) ? p_hp0lo : p_h2lo;

        // q partials = h_prev @ dhp_W (split-K=4)
        {
            GemmArgs3 a = {};
            a.seg[0] = {hp_hi, hp_lo, HD, p_whi + o_dhpW, p_wlo + o_dhpW, AP, HD};
            a.nseg = 1; a.D = p_qpart; a.ldd = AP; a.bias = nullptr; a.mode = 0;
            a.zchunk = HD / QSPLIT;
            gemm_bf16s<<<dim3(AP / 64, BB / 64, QSPLIT), 256, SMEM_BYTES>>>(a);
        }

        attn_fused<<<BB, 512>>>(corr_w, corr_b, mask, dhp_b);

        // gates1 + cell1 fused
        {
            GemmArgs3 a = {};
            a.seg[0] = {p_caphi + (size_t)t * BB * EE, p_caplo + (size_t)t * BB * EE, EE,
                        p_whi + o_ih1, p_wlo + o_ih1, G4, EE};
            a.seg[1] = {p_athi, p_atlo, HE,
                        p_whi + o_ih1 + (size_t)EE * G4, p_wlo + o_ih1 + (size_t)EE * G4, G4, HE};
            a.seg[2] = {p_h1hi, p_h1lo, HD, p_whi + o_hh1, p_wlo + o_hh1, G4, HD};
            a.nseg = 3; a.bias = p_b1p; a.mode = 2; a.zchunk = 0;
            a.cellC = p_c1; a.cellHhi = p_h1hi; a.cellHlo = p_h1lo;
            gemm_bf16s<<<dim3(G4 / 64, BB / 64), 256, SMEM_BYTES>>>(a);
        }

        // mega: gates2+cell2 (cols<4096) | out tanh (cols>=4096)
        {
            GemmArgs3 a = {};
            a.seg[0] = {p_h1hi, p_h1lo, HD, p_whi + o_mega, p_wlo + o_mega, NMEGA, HD};
            a.seg[1] = {p_h2hi, p_h2lo, HD,
                        p_whi + o_mega + (size_t)HD * NMEGA, p_wlo + o_mega + (size_t)HD * NMEGA,
                        NMEGA, HD};
            a.nseg = 2; a.bias = p_bmega; a.mode = 3; a.ncell = G4; a.zchunk = 0;
            a.cellC = p_c2; a.cellHhi = p_h2hi; a.cellHlo = p_h2lo;
            a.D2 = out + (size_t)t * BB * HD; a.ldd2 = HD;
            gemm_bf16s<<<dim3(NMEGA / 64, BB / 64), 256, SMEM_BYTES>>>(a);
        }
    }

    (void)in_sizes; (void)n_in; (void)out_size;
}

// round 9
// speedup vs baseline: 5.1180x; 1.2367x over previous
#include <cuda_runtime.h>
#include <cuda_bf16.h>
#include <math.h>
#include <stdint.h>

// Problem constants
#define BB 128   // batch
#define LL 128   // enc length
#define HE 1024  // enc hidden
#define HD 1024  // dec hidden
#define EE 512   // embed
#define AP 512   // attn proj
#define TT 64    // timesteps
#define G4 (4*HD)
#define QSPLIT 4

// ---------------- device scratch ----------------
__device__ __nv_bfloat16 g_enc_projb[BB * LL * AP];   // bf16 enc_proj
__device__ float g_qpart[QSPLIT * BB * AP];
__device__ float g_c1[BB * HD];
__device__ float g_c2[BB * HD];
__device__ float g_b1p[G4];
__device__ float g_b2p[G4];

// h1 archive: one slot per timestep (gates1 of step t writes slot t;
// gates1/gates2 of step t read slot t-1 / t). Removes races, enables final batched out-GEMM.
__device__ __nv_bfloat16 g_h1ahi[TT * BB * HD], g_h1alo[TT * BB * HD];
__device__ __nv_bfloat16 g_h1inithi[BB * HD], g_h1initlo[BB * HD];
// h2 ping-pong
__device__ __nv_bfloat16 g_h2hi[2][BB * HD], g_h2lo[2][BB * HD];
__device__ __nv_bfloat16 g_hp0hi[BB * HD], g_hp0lo[BB * HD];
__device__ __nv_bfloat16 g_athi[BB * HE], g_atlo[BB * HE];
__device__ __nv_bfloat16 g_caphi[TT * BB * EE], g_caplo[TT * BB * EE];
__device__ __nv_bfloat16 g_enchi[BB * LL * HE], g_enclo[BB * LL * HE];

#define WPOOL 20971520
__device__ __nv_bfloat16 g_whi[WPOOL];
__device__ __nv_bfloat16 g_wlo[WPOOL];

__device__ __forceinline__ float fast_tanh(float x) {
    float e = __expf(2.0f * x);
    return 1.0f - __fdividef(2.0f, e + 1.0f);
}
__device__ __forceinline__ float fast_sigm(float x) {
    return __fdividef(1.0f, 1.0f + __expf(-x));
}
__device__ __forceinline__ float tanh_mufu(float x) {
    float y;
    asm("tanh.approx.f32 %0, %1;" : "=f"(y) : "f"(x));
    return y;
}

// ---------------- prep kernels ----------------
__global__ void init_state(const float* __restrict__ h1_0, const float* __restrict__ c1_0,
                           const float* __restrict__ h2_0, const float* __restrict__ c2_0) {
    int i = blockIdx.x * blockDim.x + threadIdx.x;
    if (i < BB * HD) {
        float h1 = h1_0[i], h2 = h2_0[i];
        __nv_bfloat16 a = __float2bfloat16_rn(h1);
        g_h1inithi[i] = a; g_h1initlo[i] = __float2bfloat16_rn(h1 - __bfloat162float(a));
        __nv_bfloat16 b = __float2bfloat16_rn(h2);
        g_h2hi[0][i] = b; g_h2lo[0][i] = __float2bfloat16_rn(h2 - __bfloat162float(b));
        g_c1[i] = c1_0[i];
        g_c2[i] = c2_0[i];
        g_hp0hi[i] = __float2bfloat16_rn(1.0f / (float)HE);
        g_hp0lo[i] = __float2bfloat16_rn(0.0f);
    }
}

// vectorized fp32 -> bf16 hi/lo split
__global__ void f32_split4(const float4* __restrict__ src,
                           __nv_bfloat162* __restrict__ hi,
                           __nv_bfloat162* __restrict__ lo, int n4) {
    int i = blockIdx.x * 256 + threadIdx.x;
    if (i < n4) {
        float4 v = src[i];
        __nv_bfloat16 h0 = __float2bfloat16_rn(v.x);
        __nv_bfloat16 h1 = __float2bfloat16_rn(v.y);
        __nv_bfloat16 h2 = __float2bfloat16_rn(v.z);
        __nv_bfloat16 h3 = __float2bfloat16_rn(v.w);
        hi[2 * i]     = __halves2bfloat162(h0, h1);
        hi[2 * i + 1] = __halves2bfloat162(h2, h3);
        lo[2 * i]     = __halves2bfloat162(
            __float2bfloat16_rn(v.x - __bfloat162float(h0)),
            __float2bfloat16_rn(v.y - __bfloat162float(h1)));
        lo[2 * i + 1] = __halves2bfloat162(
            __float2bfloat16_rn(v.z - __bfloat162float(h2)),
            __float2bfloat16_rn(v.w - __bfloat162float(h3)));
    }
}

// gate-permuting split: src [K x 4096] (gate-major cols), dst col' = 4*j+gate
__global__ void f32_split_perm(const float* __restrict__ src,
                               __nv_bfloat16* __restrict__ hi,
                               __nv_bfloat16* __restrict__ lo,
                               int K) {
    int i = blockIdx.x * 256 + threadIdx.x;
    if (i < K * G4) {
        int row = i / G4, cd = i % G4;
        int j = cd >> 2, gate = cd & 3;
        float x = src[(size_t)row * G4 + gate * HD + j];
        __nv_bfloat16 h = __float2bfloat16_rn(x);
        hi[i] = h;
        lo[i] = __float2bfloat16_rn(x - __bfloat162float(h));
    }
}

__global__ void bias_prep(const float* __restrict__ bi1, const float* __restrict__ bh1,
                          const float* __restrict__ bi2, const float* __restrict__ bh2) {
    int i = blockIdx.x * 256 + threadIdx.x;
    if (i < G4) {
        int j = i >> 2, gate = i & 3;
        g_b1p[i] = bi1[gate * HD + j] + bh1[gate * HD + j];
        g_b2p[i] = bi2[gate * HD + j] + bh2[gate * HD + j];
    }
}

// ---------------- split-bf16 tensor-core GEMM with fused epilogues ----------------
struct Seg2 {
    const __nv_bfloat16* Ahi; const __nv_bfloat16* Alo; int lda;
    const __nv_bfloat16* Bhi; const __nv_bfloat16* Blo; int ldb;
    int K;
};
struct GemmArgs3 {
    Seg2 seg[3];
    int nseg;
    float* D; int ldd;
    const float* bias;
    int mode;                 // 0 plain f32, 1 tanh f32, 2 cell, 4 bf16 out
    float* cellC; __nv_bfloat16* cellHhi; __nv_bfloat16* cellHlo;
    __nv_bfloat16* Db;
    int zchunk;
};

#define PADA 40
#define PADB 72
#define STG 3
#define A_SET_H (STG * 64 * PADA)
#define B_SET_H (STG * 32 * PADB)
#define SET_H   (2 * A_SET_H + 2 * B_SET_H)
#define SMEM_BYTES (2 * SET_H * 2)

__device__ __forceinline__ uint32_t smem_u32(const void* p) {
    return (uint32_t)__cvta_generic_to_shared(p);
}
__device__ __forceinline__ void cp16(void* dst, const void* src) {
    asm volatile("cp.async.ca.shared.global [%0], [%1], 16;"
                 :: "r"(smem_u32(dst)), "l"(src));
}
__device__ __forceinline__ void ldsm_x4(uint32_t addr, uint32_t* r) {
    asm volatile("ldmatrix.sync.aligned.m8n8.x4.shared.b16 {%0,%1,%2,%3}, [%4];"
                 : "=r"(r[0]), "=r"(r[1]), "=r"(r[2]), "=r"(r[3]) : "r"(addr));
}
__device__ __forceinline__ void ldsm_x4_t(uint32_t addr, uint32_t& r0, uint32_t& r1,
                                          uint32_t& r2, uint32_t& r3) {
    asm volatile("ldmatrix.sync.aligned.m8n8.x4.trans.shared.b16 {%0,%1,%2,%3}, [%4];"
                 : "=r"(r0), "=r"(r1), "=r"(r2), "=r"(r3) : "r"(addr));
}
__device__ __forceinline__ void mma16816(float* c, const uint32_t* a, const uint32_t* b) {
    asm volatile(
        "mma.sync.aligned.m16n8k16.row.col.f32.bf16.bf16.f32 "
        "{%0,%1,%2,%3}, {%4,%5,%6,%7}, {%8,%9}, {%0,%1,%2,%3};"
        : "+f"(c[0]), "+f"(c[1]), "+f"(c[2]), "+f"(c[3])
        : "r"(a[0]), "r"(a[1]), "r"(a[2]), "r"(a[3]), "r"(b[0]), "r"(b[1]));
}
__device__ __forceinline__ void bar_set(int set) {
    asm volatile("bar.sync %0, 128;" :: "r"(set + 1) : "memory");
}

__device__ __forceinline__ void stage_tile(const GemmArgs3& a, int g, int bm, int bn, int stid,
                                           __nv_bfloat16* AsH, __nv_bfloat16* AsL,
                                           __nv_bfloat16* BsH, __nv_bfloat16* BsL) {
    int s = 0, rem = g;
    #pragma unroll
    for (int i = 0; i < 2; i++)
        if (s < a.nseg - 1 && rem >= (a.seg[s].K >> 5)) { rem -= a.seg[s].K >> 5; s++; }
    const Seg2 sg = a.seg[s];
    const int k0 = rem << 5;
    #pragma unroll
    for (int i = 0; i < 2; i++) {
        int ch = stid + i * 128;
        int row = ch >> 2, c = (ch & 3) * 8;
        size_t off = (size_t)(bm + row) * sg.lda + k0 + c;
        cp16(AsH + row * PADA + c, sg.Ahi + off);
        cp16(AsL + row * PADA + c, sg.Alo + off);
    }
    #pragma unroll
    for (int i = 0; i < 2; i++) {
        int ch = stid + i * 128;
        int row = ch >> 3, c = (ch & 7) * 8;
        size_t off = (size_t)(k0 + row) * sg.ldb + bn + c;
        cp16(BsH + row * PADB + c, sg.Bhi + off);
        cp16(BsL + row * PADB + c, sg.Blo + off);
    }
}

__global__ void __launch_bounds__(256)
gemm_bf16s(GemmArgs3 args_in) {
    extern __shared__ __align__(16) char smem_raw[];
    __nv_bfloat16* base = (__nv_bfloat16*)smem_raw;

    GemmArgs3 args = args_in;
    if (args.zchunk > 0) {
        int z = blockIdx.z;
        args.seg[0].Ahi += (size_t)z * args.zchunk;
        args.seg[0].Alo += (size_t)z * args.zchunk;
        args.seg[0].Bhi += (size_t)z * args.zchunk * args.seg[0].ldb;
        args.seg[0].Blo += (size_t)z * args.zchunk * args.seg[0].ldb;
        args.seg[0].K = args.zchunk;
        args.D += (size_t)z * BB * args.ldd;
    }

    const int tid = threadIdx.x;
    const int lane = tid & 31;
    const int wid = tid >> 5;
    const int set = wid >> 2;
    const int swid = wid & 3;
    const int stid = tid & 127;
    const int wm = swid & 1;
    const int wn = swid >> 1;
    const int bm = blockIdx.y * 64;
    const int bn = blockIdx.x * 64;

    __nv_bfloat16* AsH = base + set * SET_H;
    __nv_bfloat16* AsL = AsH + A_SET_H;
    __nv_bfloat16* BsH = AsL + A_SET_H;
    __nv_bfloat16* BsL = BsH + B_SET_H;
    float* red = (float*)(base + SET_H);
    float* gsm = (float*)base;

    int ntile = 0;
    #pragma unroll
    for (int s = 0; s < 3; s++) if (s < args.nseg) ntile += args.seg[s].K >> 5;
    const int cnt = (ntile - set + 1) >> 1;

    float acc[2][4][4];
    #pragma unroll
    for (int i = 0; i < 2; i++)
        #pragma unroll
        for (int j = 0; j < 4; j++)
            #pragma unroll
            for (int k = 0; k < 4; k++) acc[i][j][k] = 0.0f;

    const int a_r = lane & 15;
    const int a_c = (lane >> 4) << 3;
    const int b_r = (lane & 7) + ((lane >> 3) & 1) * 8;
    const int b_c = (lane >> 4) << 3;

    if (cnt > 0)
        stage_tile(args, set, bm, bn, stid, AsH, AsL, BsH, BsL);
    asm volatile("cp.async.commit_group;");
    if (cnt > 1)
        stage_tile(args, 2 + set, bm, bn, stid,
                   AsH + 64 * PADA, AsL + 64 * PADA, BsH + 32 * PADB, BsL + 32 * PADB);
    asm volatile("cp.async.commit_group;");

    for (int j = 0; j < cnt; j++) {
        asm volatile("cp.async.wait_group 1;");
        bar_set(set);
        {
            int p = (j + 2) % 3;
            if (j + 2 < cnt)
                stage_tile(args, 2 * (j + 2) + set, bm, bn, stid,
                           AsH + p * 64 * PADA, AsL + p * 64 * PADA,
                           BsH + p * 32 * PADB, BsL + p * 32 * PADB);
            asm volatile("cp.async.commit_group;");
        }
        const int q = j % 3;
        const __nv_bfloat16* cAH = AsH + q * 64 * PADA;
        const __nv_bfloat16* cAL = AsL + q * 64 * PADA;
        const __nv_bfloat16* cBH = BsH + q * 32 * PADB;
        const __nv_bfloat16* cBL = BsL + q * 32 * PADB;
        #pragma unroll
        for (int kk = 0; kk < 32; kk += 16) {
            uint32_t ah[2][4], al[2][4];
            #pragma unroll
            for (int mt = 0; mt < 2; mt++) {
                int rowoff = (wm * 32 + mt * 16 + a_r) * PADA + kk + a_c;
                ldsm_x4(smem_u32(&cAH[rowoff]), ah[mt]);
                ldsm_x4(smem_u32(&cAL[rowoff]), al[mt]);
            }
            uint32_t bh[4][2], bl[4][2];
            #pragma unroll
            for (int gi = 0; gi < 2; gi++) {
                int boff = (kk + b_r) * PADB + wn * 32 + gi * 16 + b_c;
                ldsm_x4_t(smem_u32(&cBH[boff]),
                          bh[gi * 2][0], bh[gi * 2][1], bh[gi * 2 + 1][0], bh[gi * 2 + 1][1]);
                ldsm_x4_t(smem_u32(&cBL[boff]),
                          bl[gi * 2][0], bl[gi * 2][1], bl[gi * 2 + 1][0], bl[gi * 2 + 1][1]);
            }
            #pragma unroll
            for (int mt = 0; mt < 2; mt++)
                #pragma unroll
                for (int nt = 0; nt < 4; nt++) {
                    mma16816(acc[mt][nt], ah[mt], bh[nt]);
                    mma16816(acc[mt][nt], al[mt], bh[nt]);
                    mma16816(acc[mt][nt], ah[mt], bl[nt]);
                }
        }
    }

    asm volatile("cp.async.wait_group 0;");
    __syncthreads();

    if (set == 1) {
        float* r = red + swid * 1024 + lane * 32;
        #pragma unroll
        for (int mt = 0; mt < 2; mt++)
            #pragma unroll
            for (int nt = 0; nt < 4; nt++)
                #pragma unroll
                for (int k = 0; k < 4; k++)
                    r[mt * 16 + nt * 4 + k] = acc[mt][nt][k];
    }
    __syncthreads();

    if (args.mode != 2) {
        if (set == 0) {
            const float* r = red + swid * 1024 + lane * 32;
            const int do_tanh = (args.mode == 1);
            #pragma unroll
            for (int mt = 0; mt < 2; mt++) {
                int r0 = bm + wm * 32 + mt * 16 + (lane >> 2);
                #pragma unroll
                for (int nt = 0; nt < 4; nt++) {
                    int c0 = bn + wn * 32 + nt * 8 + (lane & 3) * 2;
                    float bia0 = 0.0f, bia1 = 0.0f;
                    if (args.bias) { bia0 = args.bias[c0]; bia1 = args.bias[c0 + 1]; }
                    float v00 = acc[mt][nt][0] + r[mt * 16 + nt * 4 + 0] + bia0;
                    float v01 = acc[mt][nt][1] + r[mt * 16 + nt * 4 + 1] + bia1;
                    float v10 = acc[mt][nt][2] + r[mt * 16 + nt * 4 + 2] + bia0;
                    float v11 = acc[mt][nt][3] + r[mt * 16 + nt * 4 + 3] + bia1;
                    if (do_tanh) {
                        v00 = fast_tanh(v00); v01 = fast_tanh(v01);
                        v10 = fast_tanh(v10); v11 = fast_tanh(v11);
                    }
                    if (args.mode == 4) {
                        *reinterpret_cast<__nv_bfloat162*>(
                            args.Db + (size_t)r0 * args.ldd + c0) =
                            __halves2bfloat162(__float2bfloat16_rn(v00), __float2bfloat16_rn(v01));
                        *reinterpret_cast<__nv_bfloat162*>(
                            args.Db + (size_t)(r0 + 8) * args.ldd + c0) =
                            __halves2bfloat162(__float2bfloat16_rn(v10), __float2bfloat16_rn(v11));
                    } else {
                        args.D[(size_t)r0 * args.ldd + c0] = v00;
                        args.D[(size_t)r0 * args.ldd + c0 + 1] = v01;
                        args.D[(size_t)(r0 + 8) * args.ldd + c0] = v10;
                        args.D[(size_t)(r0 + 8) * args.ldd + c0 + 1] = v11;
                    }
                }
            }
        }
    } else {
        if (set == 0) {
            const float* r = red + swid * 1024 + lane * 32;
            #pragma unroll
            for (int mt = 0; mt < 2; mt++) {
                int lr = wm * 32 + mt * 16 + (lane >> 2);
                #pragma unroll
                for (int nt = 0; nt < 4; nt++) {
                    int lc = wn * 32 + nt * 8 + (lane & 3) * 2;
                    float bia0 = args.bias[bn + lc];
                    float bia1 = args.bias[bn + lc + 1];
                    gsm[lr * 64 + lc]            = acc[mt][nt][0] + r[mt * 16 + nt * 4 + 0] + bia0;
                    gsm[lr * 64 + lc + 1]        = acc[mt][nt][1] + r[mt * 16 + nt * 4 + 1] + bia1;
                    gsm[(lr + 8) * 64 + lc]      = acc[mt][nt][2] + r[mt * 16 + nt * 4 + 2] + bia0;
                    gsm[(lr + 8) * 64 + lc + 1]  = acc[mt][nt][3] + r[mt * 16 + nt * 4 + 3] + bia1;
                }
            }
        }
        __syncthreads();
        #pragma unroll
        for (int it = 0; it < 4; it++) {
            int idx = tid + it * 256;
            int row = idx >> 4;
            int u = idx & 15;
            float4 gq = *reinterpret_cast<float4*>(&gsm[row * 64 + u * 4]);  // i,f,g,o
            int gr = bm + row;
            int ju = (bn >> 2) + u;
            size_t hix = (size_t)gr * HD + ju;
            float cn = fast_sigm(gq.y) * args.cellC[hix] + fast_sigm(gq.x) * fast_tanh(gq.z);
            float hn = fast_sigm(gq.w) * fast_tanh(cn);
            args.cellC[hix] = cn;
            __nv_bfloat16 hh = __float2bfloat16_rn(hn);
            args.cellHhi[hix] = hh;
            args.cellHlo[hix] = __float2bfloat16_rn(hn - __bfloat162float(hh));
        }
    }
}

// ---------------- fused attention: q-reduce + scores + softmax + context ----------------
__global__ void __launch_bounds__(512)
attn_fused(const float* __restrict__ corr_w,
           const float* __restrict__ corr_b,
           const int* __restrict__ mask,
           const float* __restrict__ dhp_b) {
    const int b = blockIdx.x;
    const int tid = threadIdx.x;
    const int lane = tid & 31;
    const int warp = tid >> 5;

    __shared__ float sm_q[AP];
    __shared__ float sm_e[LL];
    __shared__ float sm_a[LL];

    for (int i = tid; i < AP; i += 512) {
        float s = dhp_b[i];
        #pragma unroll
        for (int z = 0; z < QSPLIT; z++)
            s += g_qpart[(size_t)z * BB * AP + b * AP + i];
        sm_q[i] = s;
    }
    __syncthreads();

    for (int l = warp; l < LL; l += 16) {
        const __nv_bfloat16* ep = g_enc_projb + ((size_t)b * LL + l) * AP;
        float s = 0.0f;
        #pragma unroll
        for (int k = 0; k < 8; k++) {
            int ap = lane * 2 + k * 64;
            __nv_bfloat162 v = *reinterpret_cast<const __nv_bfloat162*>(ep + ap);
            s += tanh_mufu(__low2float(v) + sm_q[ap]) * corr_w[ap];
            s += tanh_mufu(__high2float(v) + sm_q[ap + 1]) * corr_w[ap + 1];
        }
        #pragma unroll
        for (int o = 16; o; o >>= 1) s += __shfl_down_sync(0xffffffffu, s, o);
        if (lane == 0) {
            float v = s + corr_b[0];
            if (mask[b * LL + l] != 0) v = -INFINITY;
            sm_e[l] = v;
        }
    }
    __syncthreads();

    if (warp == 0) {
        float m = -INFINITY;
        #pragma unroll
        for (int i = lane; i < LL; i += 32) m = fmaxf(m, sm_e[i]);
        #pragma unroll
        for (int o = 16; o; o >>= 1) m = fmaxf(m, __shfl_xor_sync(0xffffffffu, m, o));
        float sum = 0.0f;
        #pragma unroll
        for (int i = lane; i < LL; i += 32) sum += __expf(sm_e[i] - m);
        #pragma unroll
        for (int o = 16; o; o >>= 1) sum += __shfl_xor_sync(0xffffffffu, sum, o);
        float inv = __fdividef(1.0f, sum);
        #pragma unroll
        for (int i = lane; i < LL; i += 32) sm_a[i] = __expf(sm_e[i] - m) * inv;
    }
    __syncthreads();

    {
        int h0 = tid * 2;
        const __nv_bfloat16* eb = g_enchi + (size_t)b * LL * HE + h0;
        float a0 = 0.0f, a1 = 0.0f;
        #pragma unroll 8
        for (int l = 0; l < LL; l++) {
            __nv_bfloat162 v = *reinterpret_cast<const __nv_bfloat162*>(eb + (size_t)l * HE);
            float al = sm_a[l];
            a0 = fmaf(al, __low2float(v), a0);
            a1 = fmaf(al, __high2float(v), a1);
        }
        __nv_bfloat16 hb0 = __float2bfloat16_rn(a0);
        __nv_bfloat16 hb1 = __float2bfloat16_rn(a1);
        *reinterpret_cast<__nv_bfloat162*>(g_athi + (size_t)b * HE + h0) =
            __halves2bfloat162(hb0, hb1);
        *reinterpret_cast<__nv_bfloat162*>(g_atlo + (size_t)b * HE + h0) =
            __halves2bfloat162(__float2bfloat16_rn(a0 - __bfloat162float(hb0)),
                               __float2bfloat16_rn(a1 - __bfloat162float(hb1)));
    }
}

// ---------------- launch ----------------
extern "C" void kernel_launch(void* const* d_in, const int* in_sizes, int n_in,
                              void* d_out, int out_size) {
    const float* enc      = (const float*)d_in[0];
    const int*   mask     = (const int*)  d_in[1];
    const float* h1_0     = (const float*)d_in[2];
    const float* c1_0     = (const float*)d_in[3];
    const float* h2_0     = (const float*)d_in[4];
    const float* c2_0     = (const float*)d_in[5];
    const float* captions = (const float*)d_in[6];
    const float* att_W    = (const float*)d_in[7];
    const float* att_b    = (const float*)d_in[8];
    const float* dhp_W    = (const float*)d_in[9];
    const float* dhp_b    = (const float*)d_in[10];
    const float* corr_w   = (const float*)d_in[11];
    const float* corr_b   = (const float*)d_in[12];
    const float* lt_W     = (const float*)d_in[13];
    const float* lt_b     = (const float*)d_in[14];
    const float* W_ih1    = (const float*)d_in[15];
    const float* W_hh1    = (const float*)d_in[16];
    const float* b_ih1    = (const float*)d_in[17];
    const float* b_hh1    = (const float*)d_in[18];
    const float* W_ih2    = (const float*)d_in[19];
    const float* W_hh2    = (const float*)d_in[20];
    const float* b_ih2    = (const float*)d_in[21];
    const float* b_hh2    = (const float*)d_in[22];
    float* out = (float*)d_out;

    cudaFuncSetAttribute(gemm_bf16s, cudaFuncAttributeMaxDynamicSharedMemorySize, SMEM_BYTES);

    float *p_qpart, *p_c1, *p_c2, *p_b1p, *p_b2p;
    __nv_bfloat16 *p_encprojb, *p_whi, *p_wlo;
    __nv_bfloat16 *p_h1ahi, *p_h1alo, *p_h1inithi, *p_h1initlo, *p_h2hi, *p_h2lo;
    __nv_bfloat16 *p_hp0hi, *p_hp0lo, *p_athi, *p_atlo, *p_caphi, *p_caplo, *p_enchi, *p_enclo;
    cudaGetSymbolAddress((void**)&p_encprojb, g_enc_projb);
    cudaGetSymbolAddress((void**)&p_qpart, g_qpart);
    cudaGetSymbolAddress((void**)&p_c1,    g_c1);
    cudaGetSymbolAddress((void**)&p_c2,    g_c2);
    cudaGetSymbolAddress((void**)&p_b1p,   g_b1p);
    cudaGetSymbolAddress((void**)&p_b2p,   g_b2p);
    cudaGetSymbolAddress((void**)&p_whi,   g_whi);
    cudaGetSymbolAddress((void**)&p_wlo,   g_wlo);
    cudaGetSymbolAddress((void**)&p_h1ahi, g_h1ahi);
    cudaGetSymbolAddress((void**)&p_h1alo, g_h1alo);
    cudaGetSymbolAddress((void**)&p_h1inithi, g_h1inithi);
    cudaGetSymbolAddress((void**)&p_h1initlo, g_h1initlo);
    cudaGetSymbolAddress((void**)&p_h2hi,  g_h2hi);
    cudaGetSymbolAddress((void**)&p_h2lo,  g_h2lo);
    cudaGetSymbolAddress((void**)&p_hp0hi, g_hp0hi);
    cudaGetSymbolAddress((void**)&p_hp0lo, g_hp0lo);
    cudaGetSymbolAddress((void**)&p_athi,  g_athi);
    cudaGetSymbolAddress((void**)&p_atlo,  g_atlo);
    cudaGetSymbolAddress((void**)&p_caphi, g_caphi);
    cudaGetSymbolAddress((void**)&p_caplo, g_caplo);
    cudaGetSymbolAddress((void**)&p_enchi, g_enchi);
    cudaGetSymbolAddress((void**)&p_enclo, g_enclo);

    const size_t o_attW = 0;
    const size_t o_dhpW = o_attW + (size_t)HE * AP;
    const size_t o_ih1  = o_dhpW + (size_t)HD * AP;
    const size_t o_hh1  = o_ih1  + (size_t)(EE + HE) * G4;
    const size_t o_ih2  = o_hh1  + (size_t)HD * G4;
    const size_t o_hh2  = o_ih2  + (size_t)HD * G4;
    const size_t o_ltW  = o_hh2  + (size_t)HD * G4;

    // ---- prep ----
    f32_split4<<<(HE * AP / 4 + 255) / 256, 256>>>(
        (const float4*)att_W, (__nv_bfloat162*)(p_whi + o_attW),
        (__nv_bfloat162*)(p_wlo + o_attW), HE * AP / 4);
    f32_split4<<<(HD * AP / 4 + 255) / 256, 256>>>(
        (const float4*)dhp_W, (__nv_bfloat162*)(p_whi + o_dhpW),
        (__nv_bfloat162*)(p_wlo + o_dhpW), HD * AP / 4);
    f32_split4<<<(HD * HD / 4 + 255) / 256, 256>>>(
        (const float4*)lt_W, (__nv_bfloat162*)(p_whi + o_ltW),
        (__nv_bfloat162*)(p_wlo + o_ltW), HD * HD / 4);
    f32_split4<<<(TT * BB * EE / 4 + 255) / 256, 256>>>(
        (const float4*)captions, (__nv_bfloat162*)p_caphi,
        (__nv_bfloat162*)p_caplo, TT * BB * EE / 4);
    f32_split4<<<(BB * LL * HE / 4 + 255) / 256, 256>>>(
        (const float4*)enc, (__nv_bfloat162*)p_enchi,
        (__nv_bfloat162*)p_enclo, BB * LL * HE / 4);
    f32_split_perm<<<((EE + HE) * G4 + 255) / 256, 256>>>(W_ih1, p_whi + o_ih1, p_wlo + o_ih1,
                                                          EE + HE);
    f32_split_perm<<<(HD * G4 + 255) / 256, 256>>>(W_hh1, p_whi + o_hh1, p_wlo + o_hh1, HD);
    f32_split_perm<<<(HD * G4 + 255) / 256, 256>>>(W_ih2, p_whi + o_ih2, p_wlo + o_ih2, HD);
    f32_split_perm<<<(HD * G4 + 255) / 256, 256>>>(W_hh2, p_whi + o_hh2, p_wlo + o_hh2, HD);
    bias_prep<<<(G4 + 255) / 256, 256>>>(b_ih1, b_hh1, b_ih2, b_hh2);
    init_state<<<(BB * HD + 255) / 256, 256>>>(h1_0, c1_0, h2_0, c2_0);

    // enc_proj = enc @ att_W + att_b (stored bf16)
    {
        GemmArgs3 a = {};
        a.seg[0] = {p_enchi, p_enclo, HE, p_whi + o_attW, p_wlo + o_attW, AP, HE};
        a.nseg = 1; a.ldd = AP; a.bias = att_b; a.mode = 4; a.Db = p_encprojb; a.zchunk = 0;
        gemm_bf16s<<<dim3(AP / 64, (BB * LL) / 64), 256, SMEM_BYTES>>>(a);
    }

    for (int t = 0; t < TT; t++) {
        const int cur = t & 1, nxt = cur ^ 1;
        const size_t curo = (size_t)cur * BB * HD, nxto = (size_t)nxt * BB * HD;
        const __nv_bfloat16* hp_hi = (t == 0) ? p_hp0hi : p_h2hi + curo;
        const __nv_bfloat16* hp_lo = (t == 0) ? p_hp0lo : p_h2lo + curo;
        const __nv_bfloat16* h1p_hi = (t == 0) ? p_h1inithi : p_h1ahi + (size_t)(t - 1) * BB * HD;
        const __nv_bfloat16* h1p_lo = (t == 0) ? p_h1initlo : p_h1alo + (size_t)(t - 1) * BB * HD;
        __nv_bfloat16* h1c_hi = p_h1ahi + (size_t)t * BB * HD;
        __nv_bfloat16* h1c_lo = p_h1alo + (size_t)t * BB * HD;

        // q partials = h_prev @ dhp_W (split-K=4)
        {
            GemmArgs3 a = {};
            a.seg[0] = {hp_hi, hp_lo, HD, p_whi + o_dhpW, p_wlo + o_dhpW, AP, HD};
            a.nseg = 1; a.D = p_qpart; a.ldd = AP; a.bias = nullptr; a.mode = 0;
            a.zchunk = HD / QSPLIT;
            gemm_bf16s<<<dim3(AP / 64, BB / 64, QSPLIT), 256, SMEM_BYTES>>>(a);
        }

        attn_fused<<<BB, 512>>>(corr_w, corr_b, mask, dhp_b);

        // gates1 + cell1: reads h1[t-1] (archive), writes h1 archive slot t + c1
        {
            GemmArgs3 a = {};
            a.seg[0] = {p_caphi + (size_t)t * BB * EE, p_caplo + (size_t)t * BB * EE, EE,
                        p_whi + o_ih1, p_wlo + o_ih1, G4, EE};
            a.seg[1] = {p_athi, p_atlo, HE,
                        p_whi + o_ih1 + (size_t)EE * G4, p_wlo + o_ih1 + (size_t)EE * G4, G4, HE};
            a.seg[2] = {h1p_hi, h1p_lo, HD, p_whi + o_hh1, p_wlo + o_hh1, G4, HD};
            a.nseg = 3; a.bias = p_b1p; a.mode = 2; a.zchunk = 0;
            a.cellC = p_c1; a.cellHhi = h1c_hi; a.cellHlo = h1c_lo;
            gemm_bf16s<<<dim3(G4 / 64, BB / 64), 256, SMEM_BYTES>>>(a);
        }

        // gates2 + cell2: reads h1[t], h2[cur]; writes h2[nxt], c2
        {
            GemmArgs3 a = {};
            a.seg[0] = {h1c_hi, h1c_lo, HD, p_whi + o_ih2, p_wlo + o_ih2, G4, HD};
            a.seg[1] = {p_h2hi + curo, p_h2lo + curo, HD, p_whi + o_hh2, p_wlo + o_hh2, G4, HD};
            a.nseg = 2; a.bias = p_b2p; a.mode = 2; a.zchunk = 0;
            a.cellC = p_c2; a.cellHhi = p_h2hi + nxto; a.cellHlo = p_h2lo + nxto;
            gemm_bf16s<<<dim3(G4 / 64, BB / 64), 256, SMEM_BYTES>>>(a);
        }
    }

    // final batched out-projection: out[t,b,:] = tanh(h1[t,b,:] @ lt_W + lt_b)
    // M = TT*BB = 8192 rows (archive is t-major, matching out layout exactly)
    {
        GemmArgs3 a = {};
        a.seg[0] = {p_h1ahi, p_h1alo, HD, p_whi + o_ltW, p_wlo + o_ltW, HD, HD};
        a.nseg = 1; a.D = out; a.ldd = HD; a.bias = lt_b; a.mode = 1; a.zchunk = 0;
        gemm_bf16s<<<dim3(HD / 64, (TT * BB) / 64), 256, SMEM_BYTES>>>(a);
    }

    (void)in_sizes; (void)n_in; (void)out_size;
}

// round 10
// speedup vs baseline: 5.3511x; 1.0455x over previous
#include <cuda_runtime.h>
#include <cuda_fp16.h>
#include <math.h>
#include <stdint.h>

// Problem constants
#define BB 128   // batch
#define LL 128   // enc length
#define HE 1024  // enc hidden
#define HD 1024  // dec hidden
#define EE 512   // embed
#define AP 512   // attn proj
#define TT 64    // timesteps
#define G4 (4*HD)
#define QSPLIT 4

// ---------------- device scratch ----------------
__device__ __half g_enc_projh[BB * LL * AP];   // fp16 enc_proj
__device__ float g_qpart[QSPLIT * BB * AP];
__device__ float g_c1[BB * HD];
__device__ float g_c2[BB * HD];
__device__ float g_b1p[G4];
__device__ float g_b2p[G4];

// h1 archive (one slot per timestep) + init slot; h2 ping-pong
__device__ __half g_h1ahi[TT * BB * HD], g_h1alo[TT * BB * HD];
__device__ __half g_h1inithi[BB * HD], g_h1initlo[BB * HD];
__device__ __half g_h2hi[2][BB * HD], g_h2lo[2][BB * HD];
__device__ __half g_hp0hi[BB * HD], g_hp0lo[BB * HD];
__device__ __half g_athi[BB * HE], g_atlo[BB * HE];
__device__ __half g_caphi[TT * BB * EE], g_caplo[TT * BB * EE];
__device__ __half g_ench[BB * LL * HE];        // enc, single fp16

// fp16 single-precision weight pool
#define WPOOL 20971520
__device__ __half g_wh[WPOOL];

__device__ __forceinline__ float fast_tanh(float x) {
    float e = __expf(2.0f * x);
    return 1.0f - __fdividef(2.0f, e + 1.0f);
}
__device__ __forceinline__ float fast_sigm(float x) {
    return __fdividef(1.0f, 1.0f + __expf(-x));
}
__device__ __forceinline__ float tanh_mufu(float x) {
    float y;
    asm("tanh.approx.f32 %0, %1;" : "=f"(y) : "f"(x));
    return y;
}

// ---------------- prep kernels ----------------
__global__ void init_state(const float* __restrict__ h1_0, const float* __restrict__ c1_0,
                           const float* __restrict__ h2_0, const float* __restrict__ c2_0) {
    int i = blockIdx.x * blockDim.x + threadIdx.x;
    if (i < BB * HD) {
        float h1 = h1_0[i], h2 = h2_0[i];
        __half a = __float2half_rn(h1);
        g_h1inithi[i] = a; g_h1initlo[i] = __float2half_rn(h1 - __half2float(a));
        __half b = __float2half_rn(h2);
        g_h2hi[0][i] = b; g_h2lo[0][i] = __float2half_rn(h2 - __half2float(b));
        g_c1[i] = c1_0[i];
        g_c2[i] = c2_0[i];
        g_hp0hi[i] = __float2half_rn(1.0f / (float)HE);
        g_hp0lo[i] = __float2half_rn(0.0f);
    }
}

// fp32 -> fp16 hi/lo split (vectorized)
__global__ void f32_split4(const float4* __restrict__ src,
                           __half2* __restrict__ hi,
                           __half2* __restrict__ lo, int n4) {
    int i = blockIdx.x * 256 + threadIdx.x;
    if (i < n4) {
        float4 v = src[i];
        __half h0 = __float2half_rn(v.x);
        __half h1 = __float2half_rn(v.y);
        __half h2 = __float2half_rn(v.z);
        __half h3 = __float2half_rn(v.w);
        hi[2 * i]     = __halves2half2(h0, h1);
        hi[2 * i + 1] = __halves2half2(h2, h3);
        lo[2 * i]     = __halves2half2(
            __float2half_rn(v.x - __half2float(h0)),
            __float2half_rn(v.y - __half2float(h1)));
        lo[2 * i + 1] = __halves2half2(
            __float2half_rn(v.z - __half2float(h2)),
            __float2half_rn(v.w - __half2float(h3)));
    }
}

// fp32 -> fp16 single convert (vectorized)
__global__ void f32_cvt4(const float4* __restrict__ src, __half2* __restrict__ dst, int n4) {
    int i = blockIdx.x * 256 + threadIdx.x;
    if (i < n4) {
        float4 v = src[i];
        dst[2 * i]     = __halves2half2(__float2half_rn(v.x), __float2half_rn(v.y));
        dst[2 * i + 1] = __halves2half2(__float2half_rn(v.z), __float2half_rn(v.w));
    }
}

// gate-permuting convert: src [K x 4096] gate-major, dst col' = 4*j+gate (single fp16)
__global__ void f32_cvt_perm(const float* __restrict__ src, __half* __restrict__ dst, int K) {
    int i = blockIdx.x * 256 + threadIdx.x;
    if (i < K * G4) {
        int row = i / G4, cd = i % G4;
        int j = cd >> 2, gate = cd & 3;
        dst[i] = __float2half_rn(src[(size_t)row * G4 + gate * HD + j]);
    }
}

__global__ void bias_prep(const float* __restrict__ bi1, const float* __restrict__ bh1,
                          const float* __restrict__ bi2, const float* __restrict__ bh2) {
    int i = blockIdx.x * 256 + threadIdx.x;
    if (i < G4) {
        int j = i >> 2, gate = i & 3;
        g_b1p[i] = bi1[gate * HD + j] + bh1[gate * HD + j];
        g_b2p[i] = bi2[gate * HD + j] + bh2[gate * HD + j];
    }
}

// ---------------- fp16 split-A tensor-core GEMM with fused epilogues ----------------
// D = sum_seg A_seg @ B_seg, A fp16 hi(+lo), B fp16 single.
// passes: Ah*B (+ Al*B if apass==2). fp32 accum.
struct Seg2 {
    const __half* Ahi; const __half* Alo; int lda;
    const __half* B; int ldb;
    int K;
};
struct GemmArgs3 {
    Seg2 seg[3];
    int nseg;
    int apass;                // 1 or 2 A-passes
    float* D; int ldd;
    const float* bias;
    int mode;                 // 0 plain f32, 1 tanh f32, 2 cell, 4 fp16 out
    float* cellC; __half* cellHhi; __half* cellHlo;
    __half* Dh;
    int zchunk;
};

#define PADA 40
#define PADB 72
#define STG 3
#define A_SET_H (STG * 64 * PADA)   // 7680 halves per (A hi|lo)
#define B_SET_H (STG * 32 * PADB)   // 6912 halves
#define SET_H   (2 * A_SET_H + B_SET_H)   // 22272 halves
#define SMEM_BYTES (2 * SET_H * 2)        // 89088 B

__device__ __forceinline__ uint32_t smem_u32(const void* p) {
    return (uint32_t)__cvta_generic_to_shared(p);
}
__device__ __forceinline__ void cp16(void* dst, const void* src) {
    asm volatile("cp.async.ca.shared.global [%0], [%1], 16;"
                 :: "r"(smem_u32(dst)), "l"(src));
}
__device__ __forceinline__ void ldsm_x4(uint32_t addr, uint32_t* r) {
    asm volatile("ldmatrix.sync.aligned.m8n8.x4.shared.b16 {%0,%1,%2,%3}, [%4];"
                 : "=r"(r[0]), "=r"(r[1]), "=r"(r[2]), "=r"(r[3]) : "r"(addr));
}
__device__ __forceinline__ void ldsm_x4_t(uint32_t addr, uint32_t& r0, uint32_t& r1,
                                          uint32_t& r2, uint32_t& r3) {
    asm volatile("ldmatrix.sync.aligned.m8n8.x4.trans.shared.b16 {%0,%1,%2,%3}, [%4];"
                 : "=r"(r0), "=r"(r1), "=r"(r2), "=r"(r3) : "r"(addr));
}
__device__ __forceinline__ void mma16816(float* c, const uint32_t* a, const uint32_t* b) {
    asm volatile(
        "mma.sync.aligned.m16n8k16.row.col.f32.f16.f16.f32 "
        "{%0,%1,%2,%3}, {%4,%5,%6,%7}, {%8,%9}, {%0,%1,%2,%3};"
        : "+f"(c[0]), "+f"(c[1]), "+f"(c[2]), "+f"(c[3])
        : "r"(a[0]), "r"(a[1]), "r"(a[2]), "r"(a[3]), "r"(b[0]), "r"(b[1]));
}
__device__ __forceinline__ void bar_set(int set) {
    asm volatile("bar.sync %0, 128;" :: "r"(set + 1) : "memory");
}

__device__ __forceinline__ void stage_tile(const GemmArgs3& a, int g, int bm, int bn, int stid,
                                           __half* AsH, __half* AsL, __half* Bs) {
    int s = 0, rem = g;
    #pragma unroll
    for (int i = 0; i < 2; i++)
        if (s < a.nseg - 1 && rem >= (a.seg[s].K >> 5)) { rem -= a.seg[s].K >> 5; s++; }
    const Seg2 sg = a.seg[s];
    const int k0 = rem << 5;
    #pragma unroll
    for (int i = 0; i < 2; i++) {
        int ch = stid + i * 128;
        int row = ch >> 2, c = (ch & 3) * 8;
        size_t off = (size_t)(bm + row) * sg.lda + k0 + c;
        cp16(AsH + row * PADA + c, sg.Ahi + off);
        if (a.apass == 2) cp16(AsL + row * PADA + c, sg.Alo + off);
    }
    #pragma unroll
    for (int i = 0; i < 2; i++) {
        int ch = stid + i * 128;
        int row = ch >> 3, c = (ch & 7) * 8;
        size_t off = (size_t)(k0 + row) * sg.ldb + bn + c;
        cp16(Bs + row * PADB + c, sg.B + off);
    }
}

__global__ void __launch_bounds__(256)
gemm_f16s(GemmArgs3 args_in) {
    extern __shared__ __align__(16) char smem_raw[];
    __half* base = (__half*)smem_raw;

    GemmArgs3 args = args_in;
    if (args.zchunk > 0) {
        int z = blockIdx.z;
        args.seg[0].Ahi += (size_t)z * args.zchunk;
        args.seg[0].Alo += (size_t)z * args.zchunk;
        args.seg[0].B   += (size_t)z * args.zchunk * args.seg[0].ldb;
        args.seg[0].K = args.zchunk;
        args.D += (size_t)z * BB * args.ldd;
    }

    const int tid = threadIdx.x;
    const int lane = tid & 31;
    const int wid = tid >> 5;
    const int set = wid >> 2;
    const int swid = wid & 3;
    const int stid = tid & 127;
    const int wm = swid & 1;
    const int wn = swid >> 1;
    const int bm = blockIdx.y * 64;
    const int bn = blockIdx.x * 64;

    __half* AsH = base + set * SET_H;
    __half* AsL = AsH + A_SET_H;
    __half* Bs  = AsL + A_SET_H;
    float* red = (float*)(base + SET_H);   // set-1 region, reused post-pipeline
    float* gsm = (float*)base;

    int ntile = 0;
    #pragma unroll
    for (int s = 0; s < 3; s++) if (s < args.nseg) ntile += args.seg[s].K >> 5;
    const int cnt = (ntile - set + 1) >> 1;

    float acc[2][4][4];
    #pragma unroll
    for (int i = 0; i < 2; i++)
        #pragma unroll
        for (int j = 0; j < 4; j++)
            #pragma unroll
            for (int k = 0; k < 4; k++) acc[i][j][k] = 0.0f;

    const int a_r = lane & 15;
    const int a_c = (lane >> 4) << 3;
    const int b_r = (lane & 7) + ((lane >> 3) & 1) * 8;
    const int b_c = (lane >> 4) << 3;

    if (cnt > 0)
        stage_tile(args, set, bm, bn, stid, AsH, AsL, Bs);
    asm volatile("cp.async.commit_group;");
    if (cnt > 1)
        stage_tile(args, 2 + set, bm, bn, stid,
                   AsH + 64 * PADA, AsL + 64 * PADA, Bs + 32 * PADB);
    asm volatile("cp.async.commit_group;");

    for (int j = 0; j < cnt; j++) {
        asm volatile("cp.async.wait_group 1;");
        bar_set(set);
        {
            int p = (j + 2) % 3;
            if (j + 2 < cnt)
                stage_tile(args, 2 * (j + 2) + set, bm, bn, stid,
                           AsH + p * 64 * PADA, AsL + p * 64 * PADA, Bs + p * 32 * PADB);
            asm volatile("cp.async.commit_group;");
        }
        const int q = j % 3;
        const __half* cAH = AsH + q * 64 * PADA;
        const __half* cAL = AsL + q * 64 * PADA;
        const __half* cB  = Bs + q * 32 * PADB;
        #pragma unroll
        for (int kk = 0; kk < 32; kk += 16) {
            uint32_t ah[2][4], al[2][4];
            #pragma unroll
            for (int mt = 0; mt < 2; mt++) {
                int rowoff = (wm * 32 + mt * 16 + a_r) * PADA + kk + a_c;
                ldsm_x4(smem_u32(&cAH[rowoff]), ah[mt]);
                if (args.apass == 2) ldsm_x4(smem_u32(&cAL[rowoff]), al[mt]);
            }
            uint32_t bh[4][2];
            #pragma unroll
            for (int gi = 0; gi < 2; gi++) {
                int boff = (kk + b_r) * PADB + wn * 32 + gi * 16 + b_c;
                ldsm_x4_t(smem_u32(&cB[boff]),
                          bh[gi * 2][0], bh[gi * 2][1], bh[gi * 2 + 1][0], bh[gi * 2 + 1][1]);
            }
            #pragma unroll
            for (int mt = 0; mt < 2; mt++)
                #pragma unroll
                for (int nt = 0; nt < 4; nt++) {
                    mma16816(acc[mt][nt], ah[mt], bh[nt]);
                    if (args.apass == 2) mma16816(acc[mt][nt], al[mt], bh[nt]);
                }
        }
    }

    asm volatile("cp.async.wait_group 0;");
    __syncthreads();

    if (set == 1) {
        float* r = red + swid * 1024 + lane * 32;
        #pragma unroll
        for (int mt = 0; mt < 2; mt++)
            #pragma unroll
            for (int nt = 0; nt < 4; nt++)
                #pragma unroll
                for (int k = 0; k < 4; k++)
                    r[mt * 16 + nt * 4 + k] = acc[mt][nt][k];
    }
    __syncthreads();

    if (args.mode != 2) {
        if (set == 0) {
            const float* r = red + swid * 1024 + lane * 32;
            const int do_tanh = (args.mode == 1);
            #pragma unroll
            for (int mt = 0; mt < 2; mt++) {
                int r0 = bm + wm * 32 + mt * 16 + (lane >> 2);
                #pragma unroll
                for (int nt = 0; nt < 4; nt++) {
                    int c0 = bn + wn * 32 + nt * 8 + (lane & 3) * 2;
                    float bia0 = 0.0f, bia1 = 0.0f;
                    if (args.bias) { bia0 = args.bias[c0]; bia1 = args.bias[c0 + 1]; }
                    float v00 = acc[mt][nt][0] + r[mt * 16 + nt * 4 + 0] + bia0;
                    float v01 = acc[mt][nt][1] + r[mt * 16 + nt * 4 + 1] + bia1;
                    float v10 = acc[mt][nt][2] + r[mt * 16 + nt * 4 + 2] + bia0;
                    float v11 = acc[mt][nt][3] + r[mt * 16 + nt * 4 + 3] + bia1;
                    if (do_tanh) {
                        v00 = fast_tanh(v00); v01 = fast_tanh(v01);
                        v10 = fast_tanh(v10); v11 = fast_tanh(v11);
                    }
                    if (args.mode == 4) {
                        *reinterpret_cast<__half2*>(args.Dh + (size_t)r0 * args.ldd + c0) =
                            __halves2half2(__float2half_rn(v00), __float2half_rn(v01));
                        *reinterpret_cast<__half2*>(args.Dh + (size_t)(r0 + 8) * args.ldd + c0) =
                            __halves2half2(__float2half_rn(v10), __float2half_rn(v11));
                    } else {
                        args.D[(size_t)r0 * args.ldd + c0] = v00;
                        args.D[(size_t)r0 * args.ldd + c0 + 1] = v01;
                        args.D[(size_t)(r0 + 8) * args.ldd + c0] = v10;
                        args.D[(size_t)(r0 + 8) * args.ldd + c0 + 1] = v11;
                    }
                }
            }
        }
    } else {
        if (set == 0) {
            const float* r = red + swid * 1024 + lane * 32;
            #pragma unroll
            for (int mt = 0; mt < 2; mt++) {
                int lr = wm * 32 + mt * 16 + (lane >> 2);
                #pragma unroll
                for (int nt = 0; nt < 4; nt++) {
                    int lc = wn * 32 + nt * 8 + (lane & 3) * 2;
                    float bia0 = args.bias[bn + lc];
                    float bia1 = args.bias[bn + lc + 1];
                    gsm[lr * 64 + lc]            = acc[mt][nt][0] + r[mt * 16 + nt * 4 + 0] + bia0;
                    gsm[lr * 64 + lc + 1]        = acc[mt][nt][1] + r[mt * 16 + nt * 4 + 1] + bia1;
                    gsm[(lr + 8) * 64 + lc]      = acc[mt][nt][2] + r[mt * 16 + nt * 4 + 2] + bia0;
                    gsm[(lr + 8) * 64 + lc + 1]  = acc[mt][nt][3] + r[mt * 16 + nt * 4 + 3] + bia1;
                }
            }
        }
        __syncthreads();
        #pragma unroll
        for (int it = 0; it < 4; it++) {
            int idx = tid + it * 256;
            int row = idx >> 4;
            int u = idx & 15;
            float4 gq = *reinterpret_cast<float4*>(&gsm[row * 64 + u * 4]);  // i,f,g,o
            int gr = bm + row;
            int ju = (bn >> 2) + u;
            size_t hix = (size_t)gr * HD + ju;
            float cn = fast_sigm(gq.y) * args.cellC[hix] + fast_sigm(gq.x) * fast_tanh(gq.z);
            float hn = fast_sigm(gq.w) * fast_tanh(cn);
            args.cellC[hix] = cn;
            __half hh = __float2half_rn(hn);
            args.cellHhi[hix] = hh;
            args.cellHlo[hix] = __float2half_rn(hn - __half2float(hh));
        }
    }
}

// ---------------- fused attention: q-reduce + scores + softmax + context ----------------
__global__ void __launch_bounds__(512)
attn_fused(const float* __restrict__ corr_w,
           const float* __restrict__ corr_b,
           const int* __restrict__ mask,
           const float* __restrict__ dhp_b) {
    const int b = blockIdx.x;
    const int tid = threadIdx.x;
    const int lane = tid & 31;
    const int warp = tid >> 5;

    __shared__ float sm_q[AP];
    __shared__ float sm_e[LL];
    __shared__ float sm_a[LL];

    for (int i = tid; i < AP; i += 512) {
        float s = dhp_b[i];
        #pragma unroll
        for (int z = 0; z < QSPLIT; z++)
            s += g_qpart[(size_t)z * BB * AP + b * AP + i];
        sm_q[i] = s;
    }
    __syncthreads();

    for (int l = warp; l < LL; l += 16) {
        const __half* ep = g_enc_projh + ((size_t)b * LL + l) * AP;
        float s = 0.0f;
        #pragma unroll
        for (int k = 0; k < 8; k++) {
            int ap = lane * 2 + k * 64;
            __half2 v = *reinterpret_cast<const __half2*>(ep + ap);
            s += tanh_mufu(__low2float(v) + sm_q[ap]) * corr_w[ap];
            s += tanh_mufu(__high2float(v) + sm_q[ap + 1]) * corr_w[ap + 1];
        }
        #pragma unroll
        for (int o = 16; o; o >>= 1) s += __shfl_down_sync(0xffffffffu, s, o);
        if (lane == 0) {
            float v = s + corr_b[0];
            if (mask[b * LL + l] != 0) v = -INFINITY;
            sm_e[l] = v;
        }
    }
    __syncthreads();

    if (warp == 0) {
        float m = -INFINITY;
        #pragma unroll
        for (int i = lane; i < LL; i += 32) m = fmaxf(m, sm_e[i]);
        #pragma unroll
        for (int o = 16; o; o >>= 1) m = fmaxf(m, __shfl_xor_sync(0xffffffffu, m, o));
        float sum = 0.0f;
        #pragma unroll
        for (int i = lane; i < LL; i += 32) sum += __expf(sm_e[i] - m);
        #pragma unroll
        for (int o = 16; o; o >>= 1) sum += __shfl_xor_sync(0xffffffffu, sum, o);
        float inv = __fdividef(1.0f, sum);
        #pragma unroll
        for (int i = lane; i < LL; i += 32) sm_a[i] = __expf(sm_e[i] - m) * inv;
    }
    __syncthreads();

    {
        int h0 = tid * 2;
        const __half* eb = g_ench + (size_t)b * LL * HE + h0;
        float a0 = 0.0f, a1 = 0.0f;
        #pragma unroll 8
        for (int l = 0; l < LL; l++) {
            __half2 v = *reinterpret_cast<const __half2*>(eb + (size_t)l * HE);
            float al = sm_a[l];
            a0 = fmaf(al, __low2float(v), a0);
            a1 = fmaf(al, __high2float(v), a1);
        }
        __half hb0 = __float2half_rn(a0);
        __half hb1 = __float2half_rn(a1);
        *reinterpret_cast<__half2*>(g_athi + (size_t)b * HE + h0) = __halves2half2(hb0, hb1);
        *reinterpret_cast<__half2*>(g_atlo + (size_t)b * HE + h0) =
            __halves2half2(__float2half_rn(a0 - __half2float(hb0)),
                           __float2half_rn(a1 - __half2float(hb1)));
    }
}

// ---------------- launch ----------------
extern "C" void kernel_launch(void* const* d_in, const int* in_sizes, int n_in,
                              void* d_out, int out_size) {
    const float* enc      = (const float*)d_in[0];
    const int*   mask     = (const int*)  d_in[1];
    const float* h1_0     = (const float*)d_in[2];
    const float* c1_0     = (const float*)d_in[3];
    const float* h2_0     = (const float*)d_in[4];
    const float* c2_0     = (const float*)d_in[5];
    const float* captions = (const float*)d_in[6];
    const float* att_W    = (const float*)d_in[7];
    const float* att_b    = (const float*)d_in[8];
    const float* dhp_W    = (const float*)d_in[9];
    const float* dhp_b    = (const float*)d_in[10];
    const float* corr_w   = (const float*)d_in[11];
    const float* corr_b   = (const float*)d_in[12];
    const float* lt_W     = (const float*)d_in[13];
    const float* lt_b     = (const float*)d_in[14];
    const float* W_ih1    = (const float*)d_in[15];
    const float* W_hh1    = (const float*)d_in[16];
    const float* b_ih1    = (const float*)d_in[17];
    const float* b_hh1    = (const float*)d_in[18];
    const float* W_ih2    = (const float*)d_in[19];
    const float* W_hh2    = (const float*)d_in[20];
    const float* b_ih2    = (const float*)d_in[21];
    const float* b_hh2    = (const float*)d_in[22];
    float* out = (float*)d_out;

    cudaFuncSetAttribute(gemm_f16s, cudaFuncAttributeMaxDynamicSharedMemorySize, SMEM_BYTES);

    float *p_qpart, *p_c1, *p_c2, *p_b1p, *p_b2p;
    __half *p_encprojh, *p_wh;
    __half *p_h1ahi, *p_h1alo, *p_h1inithi, *p_h1initlo, *p_h2hi, *p_h2lo;
    __half *p_hp0hi, *p_hp0lo, *p_athi, *p_atlo, *p_caphi, *p_caplo, *p_ench;
    cudaGetSymbolAddress((void**)&p_encprojh, g_enc_projh);
    cudaGetSymbolAddress((void**)&p_qpart, g_qpart);
    cudaGetSymbolAddress((void**)&p_c1,    g_c1);
    cudaGetSymbolAddress((void**)&p_c2,    g_c2);
    cudaGetSymbolAddress((void**)&p_b1p,   g_b1p);
    cudaGetSymbolAddress((void**)&p_b2p,   g_b2p);
    cudaGetSymbolAddress((void**)&p_wh,    g_wh);
    cudaGetSymbolAddress((void**)&p_h1ahi, g_h1ahi);
    cudaGetSymbolAddress((void**)&p_h1alo, g_h1alo);
    cudaGetSymbolAddress((void**)&p_h1inithi, g_h1inithi);
    cudaGetSymbolAddress((void**)&p_h1initlo, g_h1initlo);
    cudaGetSymbolAddress((void**)&p_h2hi,  g_h2hi);
    cudaGetSymbolAddress((void**)&p_h2lo,  g_h2lo);
    cudaGetSymbolAddress((void**)&p_hp0hi, g_hp0hi);
    cudaGetSymbolAddress((void**)&p_hp0lo, g_hp0lo);
    cudaGetSymbolAddress((void**)&p_athi,  g_athi);
    cudaGetSymbolAddress((void**)&p_atlo,  g_atlo);
    cudaGetSymbolAddress((void**)&p_caphi, g_caphi);
    cudaGetSymbolAddress((void**)&p_caplo, g_caplo);
    cudaGetSymbolAddress((void**)&p_ench,  g_ench);

    const size_t o_attW = 0;
    const size_t o_dhpW = o_attW + (size_t)HE * AP;
    const size_t o_ih1  = o_dhpW + (size_t)HD * AP;
    const size_t o_hh1  = o_ih1  + (size_t)(EE + HE) * G4;
    const size_t o_ih2  = o_hh1  + (size_t)HD * G4;
    const size_t o_hh2  = o_ih2  + (size_t)HD * G4;
    const size_t o_ltW  = o_hh2  + (size_t)HD * G4;

    // ---- prep ----
    f32_cvt4<<<(HE * AP / 4 + 255) / 256, 256>>>(
        (const float4*)att_W, (__half2*)(p_wh + o_attW), HE * AP / 4);
    f32_cvt4<<<(HD * AP / 4 + 255) / 256, 256>>>(
        (const float4*)dhp_W, (__half2*)(p_wh + o_dhpW), HD * AP / 4);
    f32_cvt4<<<(HD * HD / 4 + 255) / 256, 256>>>(
        (const float4*)lt_W, (__half2*)(p_wh + o_ltW), HD * HD / 4);
    f32_cvt4<<<(BB * LL * HE / 4 + 255) / 256, 256>>>(
        (const float4*)enc, (__half2*)p_ench, BB * LL * HE / 4);
    f32_split4<<<(TT * BB * EE / 4 + 255) / 256, 256>>>(
        (const float4*)captions, (__half2*)p_caphi, (__half2*)p_caplo, TT * BB * EE / 4);
    f32_cvt_perm<<<((EE + HE) * G4 + 255) / 256, 256>>>(W_ih1, p_wh + o_ih1, EE + HE);
    f32_cvt_perm<<<(HD * G4 + 255) / 256, 256>>>(W_hh1, p_wh + o_hh1, HD);
    f32_cvt_perm<<<(HD * G4 + 255) / 256, 256>>>(W_ih2, p_wh + o_ih2, HD);
    f32_cvt_perm<<<(HD * G4 + 255) / 256, 256>>>(W_hh2, p_wh + o_hh2, HD);
    bias_prep<<<(G4 + 255) / 256, 256>>>(b_ih1, b_hh1, b_ih2, b_hh2);
    init_state<<<(BB * HD + 255) / 256, 256>>>(h1_0, c1_0, h2_0, c2_0);

    // enc_proj = enc @ att_W + att_b (fp16 out, 1 A-pass: enc single fp16)
    {
        GemmArgs3 a = {};
        a.seg[0] = {p_ench, p_ench, HE, p_wh + o_attW, AP, HE};
        a.nseg = 1; a.apass = 1; a.ldd = AP; a.bias = att_b; a.mode = 4;
        a.Dh = p_encprojh; a.zchunk = 0;
        gemm_f16s<<<dim3(AP / 64, (BB * LL) / 64), 256, SMEM_BYTES>>>(a);
    }

    for (int t = 0; t < TT; t++) {
        const int cur = t & 1, nxt = cur ^ 1;
        const size_t curo = (size_t)cur * BB * HD, nxto = (size_t)nxt * BB * HD;
        const __half* hp_hi = (t == 0) ? p_hp0hi : p_h2hi + curo;
        const __half* hp_lo = (t == 0) ? p_hp0lo : p_h2lo + curo;
        const __half* h1p_hi = (t == 0) ? p_h1inithi : p_h1ahi + (size_t)(t - 1) * BB * HD;
        const __half* h1p_lo = (t == 0) ? p_h1initlo : p_h1alo + (size_t)(t - 1) * BB * HD;
        __half* h1c_hi = p_h1ahi + (size_t)t * BB * HD;
        __half* h1c_lo = p_h1alo + (size_t)t * BB * HD;

        // q partials = h_prev @ dhp_W (split-K=4)
        {
            GemmArgs3 a = {};
            a.seg[0] = {hp_hi, hp_lo, HD, p_wh + o_dhpW, AP, HD};
            a.nseg = 1; a.apass = 2; a.D = p_qpart; a.ldd = AP; a.bias = nullptr; a.mode = 0;
            a.zchunk = HD / QSPLIT;
            gemm_f16s<<<dim3(AP / 64, BB / 64, QSPLIT), 256, SMEM_BYTES>>>(a);
        }

        attn_fused<<<BB, 512>>>(corr_w, corr_b, mask, dhp_b);

        // gates1 + cell1: reads h1[t-1] archive, writes slot t + c1
        {
            GemmArgs3 a = {};
            a.seg[0] = {p_caphi + (size_t)t * BB * EE, p_caplo + (size_t)t * BB * EE, EE,
                        p_wh + o_ih1, G4, EE};
            a.seg[1] = {p_athi, p_atlo, HE, p_wh + o_ih1 + (size_t)EE * G4, G4, HE};
            a.seg[2] = {h1p_hi, h1p_lo, HD, p_wh + o_hh1, G4, HD};
            a.nseg = 3; a.apass = 2; a.bias = p_b1p; a.mode = 2; a.zchunk = 0;
            a.cellC = p_c1; a.cellHhi = h1c_hi; a.cellHlo = h1c_lo;
            gemm_f16s<<<dim3(G4 / 64, BB / 64), 256, SMEM_BYTES>>>(a);
        }

        // gates2 + cell2: reads h1[t], h2[cur]; writes h2[nxt], c2
        {
            GemmArgs3 a = {};
            a.seg[0] = {h1c_hi, h1c_lo, HD, p_wh + o_ih2, G4, HD};
            a.seg[1] = {p_h2hi + curo, p_h2lo + curo, HD, p_wh + o_hh2, G4, HD};
            a.nseg = 2; a.apass = 2; a.bias = p_b2p; a.mode = 2; a.zchunk = 0;
            a.cellC = p_c2; a.cellHhi = p_h2hi + nxto; a.cellHlo = p_h2lo + nxto;
            gemm_f16s<<<dim3(G4 / 64, BB / 64), 256, SMEM_BYTES>>>(a);
        }
    }

    // final batched out-projection: out[t,b,:] = tanh(h1[t,b,:] @ lt_W + lt_b)
    {
        GemmArgs3 a = {};
        a.seg[0] = {p_h1ahi, p_h1alo, HD, p_wh + o_ltW, HD, HD};
        a.nseg = 1; a.apass = 2; a.D = out; a.ldd = HD; a.bias = lt_b; a.mode = 1; a.zchunk = 0;
        gemm_f16s<<<dim3(HD / 64, (TT * BB) / 64), 256, SMEM_BYTES>>>(a);
    }

    (void)in_sizes; (void)n_in; (void)out_size;
}

// round 11
// speedup vs baseline: 5.7023x; 1.0656x over previous
#include <cuda_runtime.h>
#include <cuda_fp16.h>
#include <math.h>
#include <stdint.h>

// Problem constants
#define BB 128   // batch
#define LL 128   // enc length
#define HE 1024  // enc hidden
#define HD 1024  // dec hidden
#define EE 512   // embed
#define AP 512   // attn proj
#define TT 64    // timesteps
#define G4 (4*HD)
#define QSPLIT 8
#define NCTA 128

// ---------------- device scratch ----------------
__device__ __half g_enc_projh[BB * LL * AP];   // fp16 enc_proj (read-only in loop)
__device__ float g_qpart[QSPLIT * BB * AP];
__device__ float g_c1[BB * HD];
__device__ float g_c2[BB * HD];
__device__ float g_b1p[G4];
__device__ float g_b2p[G4];

__device__ __half g_h1ahi[TT * BB * HD], g_h1alo[TT * BB * HD];   // h1 archive
__device__ __half g_h1inithi[BB * HD], g_h1initlo[BB * HD];
__device__ __half g_h2hi[2][BB * HD], g_h2lo[2][BB * HD];
__device__ __half g_hp0hi[BB * HD], g_hp0lo[BB * HD];
__device__ __half g_athi[BB * HE], g_atlo[BB * HE];
__device__ __half g_caphi[TT * BB * EE], g_caplo[TT * BB * EE];
__device__ __half g_ench[BB * LL * HE];

#define WPOOL 20971520
__device__ __half g_wh[WPOOL];

// weight pool offsets (compile-time)
#define O_ATTW ((size_t)0)
#define O_DHPW (O_ATTW + (size_t)HE * AP)
#define O_IH1  (O_DHPW + (size_t)HD * AP)
#define O_HH1  (O_IH1  + (size_t)(EE + HE) * G4)
#define O_IH2  (O_HH1  + (size_t)HD * G4)
#define O_HH2  (O_IH2  + (size_t)HD * G4)
#define O_LTW  (O_HH2  + (size_t)HD * G4)

// software grid barrier
__device__ unsigned g_bar_count = 0;
__device__ volatile unsigned g_bar_gen = 0;

__device__ __forceinline__ void grid_sync() {
    __threadfence();
    __syncthreads();
    if (threadIdx.x == 0) {
        unsigned gen = g_bar_gen;
        if (atomicAdd(&g_bar_count, 1u) == NCTA - 1u) {
            g_bar_count = 0;
            __threadfence();
            g_bar_gen = gen + 1;
        } else {
            while (g_bar_gen == gen) __nanosleep(32);
        }
    }
    __syncthreads();
}

__device__ __forceinline__ float fast_tanh(float x) {
    float e = __expf(2.0f * x);
    return 1.0f - __fdividef(2.0f, e + 1.0f);
}
__device__ __forceinline__ float fast_sigm(float x) {
    return __fdividef(1.0f, 1.0f + __expf(-x));
}
__device__ __forceinline__ float tanh_mufu(float x) {
    float y;
    asm("tanh.approx.f32 %0, %1;" : "=f"(y) : "f"(x));
    return y;
}

// ---------------- prep kernels ----------------
__global__ void init_state(const float* __restrict__ h1_0, const float* __restrict__ c1_0,
                           const float* __restrict__ h2_0, const float* __restrict__ c2_0) {
    int i = blockIdx.x * blockDim.x + threadIdx.x;
    if (i < BB * HD) {
        float h1 = h1_0[i], h2 = h2_0[i];
        __half a = __float2half_rn(h1);
        g_h1inithi[i] = a; g_h1initlo[i] = __float2half_rn(h1 - __half2float(a));
        __half b = __float2half_rn(h2);
        g_h2hi[0][i] = b; g_h2lo[0][i] = __float2half_rn(h2 - __half2float(b));
        g_c1[i] = c1_0[i];
        g_c2[i] = c2_0[i];
        g_hp0hi[i] = __float2half_rn(1.0f / (float)HE);
        g_hp0lo[i] = __float2half_rn(0.0f);
    }
}

__global__ void f32_split4(const float4* __restrict__ src,
                           __half2* __restrict__ hi,
                           __half2* __restrict__ lo, int n4) {
    int i = blockIdx.x * 256 + threadIdx.x;
    if (i < n4) {
        float4 v = src[i];
        __half h0 = __float2half_rn(v.x);
        __half h1 = __float2half_rn(v.y);
        __half h2 = __float2half_rn(v.z);
        __half h3 = __float2half_rn(v.w);
        hi[2 * i]     = __halves2half2(h0, h1);
        hi[2 * i + 1] = __halves2half2(h2, h3);
        lo[2 * i]     = __halves2half2(
            __float2half_rn(v.x - __half2float(h0)),
            __float2half_rn(v.y - __half2float(h1)));
        lo[2 * i + 1] = __halves2half2(
            __float2half_rn(v.z - __half2float(h2)),
            __float2half_rn(v.w - __half2float(h3)));
    }
}

__global__ void f32_cvt4(const float4* __restrict__ src, __half2* __restrict__ dst, int n4) {
    int i = blockIdx.x * 256 + threadIdx.x;
    if (i < n4) {
        float4 v = src[i];
        dst[2 * i]     = __halves2half2(__float2half_rn(v.x), __float2half_rn(v.y));
        dst[2 * i + 1] = __halves2half2(__float2half_rn(v.z), __float2half_rn(v.w));
    }
}

__global__ void f32_cvt_perm(const float* __restrict__ src, __half* __restrict__ dst, int K) {
    int i = blockIdx.x * 256 + threadIdx.x;
    if (i < K * G4) {
        int row = i / G4, cd = i % G4;
        int j = cd >> 2, gate = cd & 3;
        dst[i] = __float2half_rn(src[(size_t)row * G4 + gate * HD + j]);
    }
}

__global__ void bias_prep(const float* __restrict__ bi1, const float* __restrict__ bh1,
                          const float* __restrict__ bi2, const float* __restrict__ bh2) {
    int i = blockIdx.x * 256 + threadIdx.x;
    if (i < G4) {
        int j = i >> 2, gate = i & 3;
        g_b1p[i] = bi1[gate * HD + j] + bh1[gate * HD + j];
        g_b2p[i] = bi2[gate * HD + j] + bh2[gate * HD + j];
    }
}

// ---------------- fp16 split-A tensor-core GEMM tile (device fn) ----------------
struct Seg2 {
    const __half* Ahi; const __half* Alo; int lda;
    const __half* B; int ldb;
    int K;
};
struct GemmArgs3 {
    Seg2 seg[3];
    int nseg;
    int apass;                // 1 or 2 A-passes
    float* D; int ldd;
    const float* bias;
    int mode;                 // 0 plain f32, 1 tanh f32, 2 cell, 4 fp16 out
    float* cellC; __half* cellHhi; __half* cellHlo;
    __half* Dh;
    int zchunk;
};

#define PADA 40
#define PADB 72
#define STG 3
#define A_SET_H (STG * 64 * PADA)
#define B_SET_H (STG * 32 * PADB)
#define SET_H   (2 * A_SET_H + B_SET_H)
#define SMEM_BYTES (2 * SET_H * 2)

__device__ __forceinline__ uint32_t smem_u32(const void* p) {
    return (uint32_t)__cvta_generic_to_shared(p);
}
// cg variant: bypass L1 (persistent kernel; cross-CTA producer/consumer)
__device__ __forceinline__ void cp16(void* dst, const void* src) {
    asm volatile("cp.async.cg.shared.global [%0], [%1], 16;"
                 :: "r"(smem_u32(dst)), "l"(src));
}
__device__ __forceinline__ void ldsm_x4(uint32_t addr, uint32_t* r) {
    asm volatile("ldmatrix.sync.aligned.m8n8.x4.shared.b16 {%0,%1,%2,%3}, [%4];"
                 : "=r"(r[0]), "=r"(r[1]), "=r"(r[2]), "=r"(r[3]) : "r"(addr));
}
__device__ __forceinline__ void ldsm_x4_t(uint32_t addr, uint32_t& r0, uint32_t& r1,
                                          uint32_t& r2, uint32_t& r3) {
    asm volatile("ldmatrix.sync.aligned.m8n8.x4.trans.shared.b16 {%0,%1,%2,%3}, [%4];"
                 : "=r"(r0), "=r"(r1), "=r"(r2), "=r"(r3) : "r"(addr));
}
__device__ __forceinline__ void mma16816(float* c, const uint32_t* a, const uint32_t* b) {
    asm volatile(
        "mma.sync.aligned.m16n8k16.row.col.f32.f16.f16.f32 "
        "{%0,%1,%2,%3}, {%4,%5,%6,%7}, {%8,%9}, {%0,%1,%2,%3};"
        : "+f"(c[0]), "+f"(c[1]), "+f"(c[2]), "+f"(c[3])
        : "r"(a[0]), "r"(a[1]), "r"(a[2]), "r"(a[3]), "r"(b[0]), "r"(b[1]));
}
__device__ __forceinline__ void bar_set(int set) {
    asm volatile("bar.sync %0, 128;" :: "r"(set + 1) : "memory");
}

__device__ __forceinline__ void stage_tile(const GemmArgs3& a, int g, int bm, int bn, int stid,
                                           __half* AsH, __half* AsL, __half* Bs) {
    int s = 0, rem = g;
    #pragma unroll
    for (int i = 0; i < 2; i++)
        if (s < a.nseg - 1 && rem >= (a.seg[s].K >> 5)) { rem -= a.seg[s].K >> 5; s++; }
    const Seg2 sg = a.seg[s];
    const int k0 = rem << 5;
    #pragma unroll
    for (int i = 0; i < 2; i++) {
        int ch = stid + i * 128;
        int row = ch >> 2, c = (ch & 3) * 8;
        size_t off = (size_t)(bm + row) * sg.lda + k0 + c;
        cp16(AsH + row * PADA + c, sg.Ahi + off);
        if (a.apass == 2) cp16(AsL + row * PADA + c, sg.Alo + off);
    }
    #pragma unroll
    for (int i = 0; i < 2; i++) {
        int ch = stid + i * 128;
        int row = ch >> 3, c = (ch & 7) * 8;
        size_t off = (size_t)(k0 + row) * sg.ldb + bn + c;
        cp16(Bs + row * PADB + c, sg.B + off);
    }
}

__device__ void gemm_tile(GemmArgs3 args, int bx, int by, int bz, char* smem_raw) {
    __half* base = (__half*)smem_raw;

    if (args.zchunk > 0) {
        args.seg[0].Ahi += (size_t)bz * args.zchunk;
        args.seg[0].Alo += (size_t)bz * args.zchunk;
        args.seg[0].B   += (size_t)bz * args.zchunk * args.seg[0].ldb;
        args.seg[0].K = args.zchunk;
        args.D += (size_t)bz * BB * args.ldd;
    }

    const int tid = threadIdx.x;
    const int lane = tid & 31;
    const int wid = tid >> 5;
    const int set = wid >> 2;
    const int swid = wid & 3;
    const int stid = tid & 127;
    const int wm = swid & 1;
    const int wn = swid >> 1;
    const int bm = by * 64;
    const int bn = bx * 64;

    __half* AsH = base + set * SET_H;
    __half* AsL = AsH + A_SET_H;
    __half* Bs  = AsL + A_SET_H;
    float* red = (float*)(base + SET_H);
    float* gsm = (float*)base;

    int ntile = 0;
    #pragma unroll
    for (int s = 0; s < 3; s++) if (s < args.nseg) ntile += args.seg[s].K >> 5;
    const int cnt = (ntile - set + 1) >> 1;

    float acc[2][4][4];
    #pragma unroll
    for (int i = 0; i < 2; i++)
        #pragma unroll
        for (int j = 0; j < 4; j++)
            #pragma unroll
            for (int k = 0; k < 4; k++) acc[i][j][k] = 0.0f;

    const int a_r = lane & 15;
    const int a_c = (lane >> 4) << 3;
    const int b_r = (lane & 7) + ((lane >> 3) & 1) * 8;
    const int b_c = (lane >> 4) << 3;

    if (cnt > 0)
        stage_tile(args, set, bm, bn, stid, AsH, AsL, Bs);
    asm volatile("cp.async.commit_group;");
    if (cnt > 1)
        stage_tile(args, 2 + set, bm, bn, stid,
                   AsH + 64 * PADA, AsL + 64 * PADA, Bs + 32 * PADB);
    asm volatile("cp.async.commit_group;");

    for (int j = 0; j < cnt; j++) {
        asm volatile("cp.async.wait_group 1;");
        bar_set(set);
        {
            int p = (j + 2) % 3;
            if (j + 2 < cnt)
                stage_tile(args, 2 * (j + 2) + set, bm, bn, stid,
                           AsH + p * 64 * PADA, AsL + p * 64 * PADA, Bs + p * 32 * PADB);
            asm volatile("cp.async.commit_group;");
        }
        const int q = j % 3;
        const __half* cAH = AsH + q * 64 * PADA;
        const __half* cAL = AsL + q * 64 * PADA;
        const __half* cB  = Bs + q * 32 * PADB;
        #pragma unroll
        for (int kk = 0; kk < 32; kk += 16) {
            uint32_t ah[2][4], al[2][4];
            #pragma unroll
            for (int mt = 0; mt < 2; mt++) {
                int rowoff = (wm * 32 + mt * 16 + a_r) * PADA + kk + a_c;
                ldsm_x4(smem_u32(&cAH[rowoff]), ah[mt]);
                if (args.apass == 2) ldsm_x4(smem_u32(&cAL[rowoff]), al[mt]);
            }
            uint32_t bh[4][2];
            #pragma unroll
            for (int gi = 0; gi < 2; gi++) {
                int boff = (kk + b_r) * PADB + wn * 32 + gi * 16 + b_c;
                ldsm_x4_t(smem_u32(&cB[boff]),
                          bh[gi * 2][0], bh[gi * 2][1], bh[gi * 2 + 1][0], bh[gi * 2 + 1][1]);
            }
            #pragma unroll
            for (int mt = 0; mt < 2; mt++)
                #pragma unroll
                for (int nt = 0; nt < 4; nt++) {
                    mma16816(acc[mt][nt], ah[mt], bh[nt]);
                    if (args.apass == 2) mma16816(acc[mt][nt], al[mt], bh[nt]);
                }
        }
    }

    asm volatile("cp.async.wait_group 0;");
    __syncthreads();

    if (set == 1) {
        float* r = red + swid * 1024 + lane * 32;
        #pragma unroll
        for (int mt = 0; mt < 2; mt++)
            #pragma unroll
            for (int nt = 0; nt < 4; nt++)
                #pragma unroll
                for (int k = 0; k < 4; k++)
                    r[mt * 16 + nt * 4 + k] = acc[mt][nt][k];
    }
    __syncthreads();

    if (args.mode != 2) {
        if (set == 0) {
            const float* r = red + swid * 1024 + lane * 32;
            const int do_tanh = (args.mode == 1);
            #pragma unroll
            for (int mt = 0; mt < 2; mt++) {
                int r0 = bm + wm * 32 + mt * 16 + (lane >> 2);
                #pragma unroll
                for (int nt = 0; nt < 4; nt++) {
                    int c0 = bn + wn * 32 + nt * 8 + (lane & 3) * 2;
                    float bia0 = 0.0f, bia1 = 0.0f;
                    if (args.bias) { bia0 = args.bias[c0]; bia1 = args.bias[c0 + 1]; }
                    float v00 = acc[mt][nt][0] + r[mt * 16 + nt * 4 + 0] + bia0;
                    float v01 = acc[mt][nt][1] + r[mt * 16 + nt * 4 + 1] + bia1;
                    float v10 = acc[mt][nt][2] + r[mt * 16 + nt * 4 + 2] + bia0;
                    float v11 = acc[mt][nt][3] + r[mt * 16 + nt * 4 + 3] + bia1;
                    if (do_tanh) {
                        v00 = fast_tanh(v00); v01 = fast_tanh(v01);
                        v10 = fast_tanh(v10); v11 = fast_tanh(v11);
                    }
                    if (args.mode == 4) {
                        *reinterpret_cast<__half2*>(args.Dh + (size_t)r0 * args.ldd + c0) =
                            __halves2half2(__float2half_rn(v00), __float2half_rn(v01));
                        *reinterpret_cast<__half2*>(args.Dh + (size_t)(r0 + 8) * args.ldd + c0) =
                            __halves2half2(__float2half_rn(v10), __float2half_rn(v11));
                    } else {
                        args.D[(size_t)r0 * args.ldd + c0] = v00;
                        args.D[(size_t)r0 * args.ldd + c0 + 1] = v01;
                        args.D[(size_t)(r0 + 8) * args.ldd + c0] = v10;
                        args.D[(size_t)(r0 + 8) * args.ldd + c0 + 1] = v11;
                    }
                }
            }
        }
    } else {
        if (set == 0) {
            const float* r = red + swid * 1024 + lane * 32;
            #pragma unroll
            for (int mt = 0; mt < 2; mt++) {
                int lr = wm * 32 + mt * 16 + (lane >> 2);
                #pragma unroll
                for (int nt = 0; nt < 4; nt++) {
                    int lc = wn * 32 + nt * 8 + (lane & 3) * 2;
                    float bia0 = args.bias[bn + lc];
                    float bia1 = args.bias[bn + lc + 1];
                    gsm[lr * 64 + lc]            = acc[mt][nt][0] + r[mt * 16 + nt * 4 + 0] + bia0;
                    gsm[lr * 64 + lc + 1]        = acc[mt][nt][1] + r[mt * 16 + nt * 4 + 1] + bia1;
                    gsm[(lr + 8) * 64 + lc]      = acc[mt][nt][2] + r[mt * 16 + nt * 4 + 2] + bia0;
                    gsm[(lr + 8) * 64 + lc + 1]  = acc[mt][nt][3] + r[mt * 16 + nt * 4 + 3] + bia1;
                }
            }
        }
        __syncthreads();
        #pragma unroll
        for (int it = 0; it < 4; it++) {
            int idx = tid + it * 256;
            int row = idx >> 4;
            int u = idx & 15;
            float4 gq = *reinterpret_cast<float4*>(&gsm[row * 64 + u * 4]);  // i,f,g,o
            int gr = bm + row;
            int ju = (bn >> 2) + u;
            size_t hix = (size_t)gr * HD + ju;
            float cn = fast_sigm(gq.y) * args.cellC[hix] + fast_sigm(gq.x) * fast_tanh(gq.z);
            float hn = fast_sigm(gq.w) * fast_tanh(cn);
            args.cellC[hix] = cn;
            __half hh = __float2half_rn(hn);
            args.cellHhi[hix] = hh;
            args.cellHlo[hix] = __float2half_rn(hn - __half2float(hh));
        }
    }
    __syncthreads();
}

// standalone wrapper (enc_proj, out-GEMM)
__global__ void __launch_bounds__(256)
gemm_f16s(GemmArgs3 args) {
    extern __shared__ char smem_raw[];
    gemm_tile(args, blockIdx.x, blockIdx.y, blockIdx.z, smem_raw);
}

// ---------------- attention phase (device fn, 256 threads, CTA = batch row) ----------------
__device__ void attn_phase(char* smem_raw, int b,
                           const float* __restrict__ corr_w,
                           const float* __restrict__ corr_b,
                           const int* __restrict__ mask,
                           const float* __restrict__ dhp_b) {
    const int tid = threadIdx.x;
    const int lane = tid & 31;
    const int warp = tid >> 5;     // 8 warps

    float* sm_q = (float*)smem_raw;        // 512
    float* sm_e = sm_q + AP;               // 128
    float* sm_a = sm_e + LL;               // 128

    for (int i = tid; i < AP; i += 256) {
        float s = dhp_b[i];
        #pragma unroll
        for (int z = 0; z < QSPLIT; z++)
            s += __ldcg(&g_qpart[(size_t)z * BB * AP + b * AP + i]);
        sm_q[i] = s;
    }
    __syncthreads();

    for (int l = warp; l < LL; l += 8) {
        const __half* ep = g_enc_projh + ((size_t)b * LL + l) * AP;
        float s = 0.0f;
        #pragma unroll
        for (int k = 0; k < 8; k++) {
            int ap = lane * 2 + k * 64;
            __half2 v = *reinterpret_cast<const __half2*>(ep + ap);
            s += tanh_mufu(__low2float(v) + sm_q[ap]) * corr_w[ap];
            s += tanh_mufu(__high2float(v) + sm_q[ap + 1]) * corr_w[ap + 1];
        }
        #pragma unroll
        for (int o = 16; o; o >>= 1) s += __shfl_down_sync(0xffffffffu, s, o);
        if (lane == 0) {
            float v = s + corr_b[0];
            if (mask[b * LL + l] != 0) v = -INFINITY;
            sm_e[l] = v;
        }
    }
    __syncthreads();

    if (warp == 0) {
        float m = -INFINITY;
        #pragma unroll
        for (int i = lane; i < LL; i += 32) m = fmaxf(m, sm_e[i]);
        #pragma unroll
        for (int o = 16; o; o >>= 1) m = fmaxf(m, __shfl_xor_sync(0xffffffffu, m, o));
        float sum = 0.0f;
        #pragma unroll
        for (int i = lane; i < LL; i += 32) sum += __expf(sm_e[i] - m);
        #pragma unroll
        for (int o = 16; o; o >>= 1) sum += __shfl_xor_sync(0xffffffffu, sum, o);
        float inv = __fdividef(1.0f, sum);
        #pragma unroll
        for (int i = lane; i < LL; i += 32) sm_a[i] = __expf(sm_e[i] - m) * inv;
    }
    __syncthreads();

    // context: 4 columns per thread (1024 = 256*4)
    {
        int h0 = tid * 4;
        const __half* eb = g_ench + (size_t)b * LL * HE + h0;
        float a0 = 0.0f, a1 = 0.0f, a2 = 0.0f, a3 = 0.0f;
        #pragma unroll 4
        for (int l = 0; l < LL; l++) {
            const __half2* p = reinterpret_cast<const __half2*>(eb + (size_t)l * HE);
            __half2 v0 = p[0], v1 = p[1];
            float al = sm_a[l];
            a0 = fmaf(al, __low2float(v0), a0);
            a1 = fmaf(al, __high2float(v0), a1);
            a2 = fmaf(al, __low2float(v1), a2);
            a3 = fmaf(al, __high2float(v1), a3);
        }
        __half b0 = __float2half_rn(a0), b1 = __float2half_rn(a1);
        __half b2 = __float2half_rn(a2), b3 = __float2half_rn(a3);
        __half2* dh = reinterpret_cast<__half2*>(g_athi + (size_t)b * HE + h0);
        dh[0] = __halves2half2(b0, b1);
        dh[1] = __halves2half2(b2, b3);
        __half2* dl = reinterpret_cast<__half2*>(g_atlo + (size_t)b * HE + h0);
        dl[0] = __halves2half2(__float2half_rn(a0 - __half2float(b0)),
                               __float2half_rn(a1 - __half2float(b1)));
        dl[1] = __halves2half2(__float2half_rn(a2 - __half2float(b2)),
                               __float2half_rn(a3 - __half2float(b3)));
    }
    __syncthreads();
}

// ---------------- persistent decoder loop: 128 CTAs x 256 threads ----------------
__global__ void __launch_bounds__(256)
decoder_loop(const float* __restrict__ corr_w, const float* __restrict__ corr_b,
             const int* __restrict__ mask, const float* __restrict__ dhp_b) {
    extern __shared__ char smem[];
    const int cta = blockIdx.x;

    for (int t = 0; t < TT; t++) {
        const int cur = t & 1, nxt = cur ^ 1;
        const __half* hp_hi = (t == 0) ? g_hp0hi : g_h2hi[cur];
        const __half* hp_lo = (t == 0) ? g_hp0lo : g_h2lo[cur];
        const __half* h1p_hi = (t == 0) ? g_h1inithi : g_h1ahi + (size_t)(t - 1) * BB * HD;
        const __half* h1p_lo = (t == 0) ? g_h1initlo : g_h1alo + (size_t)(t - 1) * BB * HD;
        __half* h1c_hi = g_h1ahi + (size_t)t * BB * HD;
        __half* h1c_lo = g_h1alo + (size_t)t * BB * HD;

        // phase 1: q partials (16 tile positions x 8 split-K) = 128 CTAs
        {
            GemmArgs3 a = {};
            a.seg[0] = {hp_hi, hp_lo, HD, g_wh + O_DHPW, AP, HD};
            a.nseg = 1; a.apass = 2; a.D = g_qpart; a.ldd = AP; a.bias = nullptr; a.mode = 0;
            a.zchunk = HD / QSPLIT;
            int z = cta >> 4, rem = cta & 15;
            gemm_tile(a, rem & 7, rem >> 3, z, smem);
        }
        grid_sync();

        // phase 2: attention (CTA = batch row)
        attn_phase(smem, cta, corr_w, corr_b, mask, dhp_b);
        grid_sync();

        // phase 3: gates1 + cell1 (64 x 2 = 128 tiles)
        {
            GemmArgs3 a = {};
            a.seg[0] = {g_caphi + (size_t)t * BB * EE, g_caplo + (size_t)t * BB * EE, EE,
                        g_wh + O_IH1, G4, EE};
            a.seg[1] = {g_athi, g_atlo, HE, g_wh + O_IH1 + (size_t)EE * G4, G4, HE};
            a.seg[2] = {h1p_hi, h1p_lo, HD, g_wh + O_HH1, G4, HD};
            a.nseg = 3; a.apass = 2; a.bias = g_b1p; a.mode = 2; a.zchunk = 0;
            a.cellC = g_c1; a.cellHhi = h1c_hi; a.cellHlo = h1c_lo;
            gemm_tile(a, cta & 63, cta >> 6, 0, smem);
        }
        grid_sync();

        // phase 4: gates2 + cell2 (64 x 2 = 128 tiles)
        {
            GemmArgs3 a = {};
            a.seg[0] = {h1c_hi, h1c_lo, HD, g_wh + O_IH2, G4, HD};
            a.seg[1] = {g_h2hi[cur], g_h2lo[cur], HD, g_wh + O_HH2, G4, HD};
            a.nseg = 2; a.apass = 2; a.bias = g_b2p; a.mode = 2; a.zchunk = 0;
            a.cellC = g_c2; a.cellHhi = g_h2hi[nxt]; a.cellHlo = g_h2lo[nxt];
            gemm_tile(a, cta & 63, cta >> 6, 0, smem);
        }
        grid_sync();
    }
}

// ---------------- launch ----------------
extern "C" void kernel_launch(void* const* d_in, const int* in_sizes, int n_in,
                              void* d_out, int out_size) {
    const float* enc      = (const float*)d_in[0];
    const int*   mask     = (const int*)  d_in[1];
    const float* h1_0     = (const float*)d_in[2];
    const float* c1_0     = (const float*)d_in[3];
    const float* h2_0     = (const float*)d_in[4];
    const float* c2_0     = (const float*)d_in[5];
    const float* captions = (const float*)d_in[6];
    const float* att_W    = (const float*)d_in[7];
    const float* att_b    = (const float*)d_in[8];
    const float* dhp_W    = (const float*)d_in[9];
    const float* dhp_b    = (const float*)d_in[10];
    const float* corr_w   = (const float*)d_in[11];
    const float* corr_b   = (const float*)d_in[12];
    const float* lt_W     = (const float*)d_in[13];
    const float* lt_b     = (const float*)d_in[14];
    const float* W_ih1    = (const float*)d_in[15];
    const float* W_hh1    = (const float*)d_in[16];
    const float* b_ih1    = (const float*)d_in[17];
    const float* b_hh1    = (const float*)d_in[18];
    const float* W_ih2    = (const float*)d_in[19];
    const float* W_hh2    = (const float*)d_in[20];
    const float* b_ih2    = (const float*)d_in[21];
    const float* b_hh2    = (const float*)d_in[22];
    float* out = (float*)d_out;

    cudaFuncSetAttribute(gemm_f16s, cudaFuncAttributeMaxDynamicSharedMemorySize, SMEM_BYTES);
    cudaFuncSetAttribute(decoder_loop, cudaFuncAttributeMaxDynamicSharedMemorySize, SMEM_BYTES);

    __half *p_encprojh, *p_wh, *p_ench, *p_caphi, *p_caplo, *p_h1ahi, *p_h1alo;
    cudaGetSymbolAddress((void**)&p_encprojh, g_enc_projh);
    cudaGetSymbolAddress((void**)&p_wh,    g_wh);
    cudaGetSymbolAddress((void**)&p_ench,  g_ench);
    cudaGetSymbolAddress((void**)&p_caphi, g_caphi);
    cudaGetSymbolAddress((void**)&p_caplo, g_caplo);
    cudaGetSymbolAddress((void**)&p_h1ahi, g_h1ahi);
    cudaGetSymbolAddress((void**)&p_h1alo, g_h1alo);

    // ---- prep ----
    f32_cvt4<<<(HE * AP / 4 + 255) / 256, 256>>>(
        (const float4*)att_W, (__half2*)(p_wh + O_ATTW), HE * AP / 4);
    f32_cvt4<<<(HD * AP / 4 + 255) / 256, 256>>>(
        (const float4*)dhp_W, (__half2*)(p_wh + O_DHPW), HD * AP / 4);
    f32_cvt4<<<(HD * HD / 4 + 255) / 256, 256>>>(
        (const float4*)lt_W, (__half2*)(p_wh + O_LTW), HD * HD / 4);
    f32_cvt4<<<(BB * LL * HE / 4 + 255) / 256, 256>>>(
        (const float4*)enc, (__half2*)p_ench, BB * LL * HE / 4);
    f32_split4<<<(TT * BB * EE / 4 + 255) / 256, 256>>>(
        (const float4*)captions, (__half2*)p_caphi, (__half2*)p_caplo, TT * BB * EE / 4);
    f32_cvt_perm<<<((EE + HE) * G4 + 255) / 256, 256>>>(W_ih1, p_wh + O_IH1, EE + HE);
    f32_cvt_perm<<<(HD * G4 + 255) / 256, 256>>>(W_hh1, p_wh + O_HH1, HD);
    f32_cvt_perm<<<(HD * G4 + 255) / 256, 256>>>(W_ih2, p_wh + O_IH2, HD);
    f32_cvt_perm<<<(HD * G4 + 255) / 256, 256>>>(W_hh2, p_wh + O_HH2, HD);
    bias_prep<<<(G4 + 255) / 256, 256>>>(b_ih1, b_hh1, b_ih2, b_hh2);
    init_state<<<(BB * HD + 255) / 256, 256>>>(h1_0, c1_0, h2_0, c2_0);

    // enc_proj = enc @ att_W + att_b (fp16 out, 1 A-pass)
    {
        GemmArgs3 a = {};
        a.seg[0] = {p_ench, p_ench, HE, p_wh + O_ATTW, AP, HE};
        a.nseg = 1; a.apass = 1; a.ldd = AP; a.bias = att_b; a.mode = 4;
        a.Dh = p_encprojh; a.zchunk = 0;
        gemm_f16s<<<dim3(AP / 64, (BB * LL) / 64), 256, SMEM_BYTES>>>(a);
    }

    // full 64-step decoder loop: ONE persistent kernel
    decoder_loop<<<NCTA, 256, SMEM_BYTES>>>(corr_w, corr_b, mask, dhp_b);

    // final batched out-projection: out[t,b,:] = tanh(h1[t,b,:] @ lt_W + lt_b)
    {
        GemmArgs3 a = {};
        a.seg[0] = {p_h1ahi, p_h1alo, HD, p_wh + O_LTW, HD, HD};
        a.nseg = 1; a.apass = 2; a.D = out; a.ldd = HD; a.bias = lt_b; a.mode = 1; a.zchunk = 0;
        gemm_f16s<<<dim3(HD / 64, (TT * BB) / 64), 256, SMEM_BYTES>>>(a);
    }

    (void)in_sizes; (void)n_in; (void)out_size;
}